// round 10
// baseline (speedup 1.0000x reference)
#include <cuda_runtime.h>
#include <cuda_bf16.h>
#include <cstdint>

#define C_DIM 1024
#define NH 16
#define HD 64
#define MAX_T 8192
#define LMAX 1024
#define EPS_RMS 1.1920929e-07f

typedef __nv_bfloat16 bf16;

// ---------------- scratch (device globals; allocation-free rule) ----------
// linear layouts (attention operands)
__device__ bf16 g_qh[MAX_T * C_DIM];
__device__ bf16 g_ql[MAX_T * C_DIM];
__device__ bf16 g_kh2[MAX_T * C_DIM];
__device__ bf16 g_kl2[MAX_T * C_DIM];
__device__ bf16 g_vh2[MAX_T * C_DIM];
__device__ bf16 g_vl2[MAX_T * C_DIM];

// tiled layouts (GEMM operands): [blk128][kblk32][128 rows x 40 elems]
#define TROW 40
#define TBLK_ELEMS (128 * TROW)       // 5120 elems
#define TBLK_BYTES (TBLK_ELEMS * 2)   // 10240 B
#define NKB (C_DIM / 32)              // 32 k-blocks
__device__ bf16 g_xh[(MAX_T / 128) * NKB * TBLK_ELEMS];
__device__ bf16 g_xl[(MAX_T / 128) * NKB * TBLK_ELEMS];
__device__ bf16 g_ath[(MAX_T / 128) * NKB * TBLK_ELEMS];
__device__ bf16 g_atl[(MAX_T / 128) * NKB * TBLK_ELEMS];
__device__ bf16 g_wqh[8 * NKB * TBLK_ELEMS];
__device__ bf16 g_wql[8 * NKB * TBLK_ELEMS];
__device__ bf16 g_wkh[8 * NKB * TBLK_ELEMS];
__device__ bf16 g_wkl[8 * NKB * TBLK_ELEMS];
__device__ bf16 g_wvh[8 * NKB * TBLK_ELEMS];
__device__ bf16 g_wvl[8 * NKB * TBLK_ELEMS];
__device__ bf16 g_woh[8 * NKB * TBLK_ELEMS];
__device__ bf16 g_wol[8 * NKB * TBLK_ELEMS];

// ---------------- helpers ---------------------------------------------
__device__ __forceinline__ uint32_t smem_u32(const void* p) {
    uint32_t a;
    asm("{ .reg .u64 t; cvta.to.shared.u64 t, %1; cvt.u32.u64 %0, t; }"
        : "=r"(a) : "l"(p));
    return a;
}

__device__ __forceinline__ size_t tiled_off(int r, int c) {
    return ((size_t)((r >> 7) * NKB + (c >> 5))) * TBLK_ELEMS +
           (size_t)((r & 127) * TROW + (c & 31));
}

#define LDSM_X4(r0, r1, r2, r3, addr) \
    asm volatile("ldmatrix.sync.aligned.m8n8.x4.shared.b16 {%0,%1,%2,%3}, [%4];" \
                 : "=r"(r0), "=r"(r1), "=r"(r2), "=r"(r3) : "r"(addr))

#define LDSM_X4_T(r0, r1, r2, r3, addr) \
    asm volatile("ldmatrix.sync.aligned.m8n8.x4.trans.shared.b16 {%0,%1,%2,%3}, [%4];" \
                 : "=r"(r0), "=r"(r1), "=r"(r2), "=r"(r3) : "r"(addr))

#define MMA16816(d, a, b) \
    asm volatile("mma.sync.aligned.m16n8k16.row.col.f32.bf16.bf16.f32 " \
                 "{%0,%1,%2,%3}, {%4,%5,%6,%7}, {%8,%9}, {%0,%1,%2,%3};" \
                 : "+f"((d)[0]), "+f"((d)[1]), "+f"((d)[2]), "+f"((d)[3]) \
                 : "r"((a)[0]), "r"((a)[1]), "r"((a)[2]), "r"((a)[3]), \
                   "r"((b)[0]), "r"((b)[1]))

#define CP_ASYNC16(dst, src) \
    asm volatile("cp.async.cg.shared.global [%0], [%1], 16;" :: "r"(dst), "l"(src))
#define CP_COMMIT() asm volatile("cp.async.commit_group;" ::: "memory")
#define CP_WAIT(n)  asm volatile("cp.async.wait_group %0;" :: "n"(n) : "memory")

#define MBAR_INIT(a, cnt) \
    asm volatile("mbarrier.init.shared.b64 [%0], %1;" :: "r"(a), "r"(cnt) : "memory")
#define MBAR_EXPECT_TX(a, bytes) \
    asm volatile("mbarrier.arrive.expect_tx.shared.b64 _, [%0], %1;" \
                 :: "r"(a), "r"(bytes) : "memory")
#define BULK_G2S(dst, src, bytes, mbar) \
    asm volatile("cp.async.bulk.shared::cta.global.mbarrier::complete_tx::bytes " \
                 "[%0], [%1], %2, [%3];" \
                 :: "r"(dst), "l"(src), "r"(bytes), "r"(mbar) : "memory")

__device__ __forceinline__ void mbar_wait(uint32_t a, int phase) {
    asm volatile(
        "{ .reg .pred P;\n"
        "WL%=:\n"
        " mbarrier.try_wait.parity.acquire.cta.shared::cta.b64 P, [%0], %1, 0x989680;\n"
        " @P bra WD%=;\n"
        " bra WL%=;\n"
        "WD%=: }"
        :: "r"(a), "r"(phase) : "memory");
}

__device__ __forceinline__ void split2(float x, float y, uint32_t& h, uint32_t& l) {
    bf16 hx = __float2bfloat16(x);
    bf16 hy = __float2bfloat16(y);
    __nv_bfloat162 H; H.x = hx; H.y = hy;
    __nv_bfloat162 L;
    L.x = __float2bfloat16(x - __bfloat162float(hx));
    L.y = __float2bfloat16(y - __bfloat162float(hy));
    h = *(uint32_t*)&H;
    l = *(uint32_t*)&L;
}

// ---------------------------------------------------------------------------
// fused fp32 -> (hi,lo) split into TILED layout: x + 4 weight matrices
// region 0: x (xn4 float4), regions 1..4: weights (wn4 each)
// ---------------------------------------------------------------------------
__global__ __launch_bounds__(256) void split_all_tiled(
    const float4* __restrict__ x,
    const float4* __restrict__ w0, const float4* __restrict__ w1,
    const float4* __restrict__ w2, const float4* __restrict__ w3,
    bf16* __restrict__ xh, bf16* __restrict__ xl,
    bf16* __restrict__ h0p, bf16* __restrict__ l0p,
    bf16* __restrict__ h1p, bf16* __restrict__ l1p,
    bf16* __restrict__ h2p, bf16* __restrict__ l2p,
    bf16* __restrict__ h3p, bf16* __restrict__ l3p,
    int xn4, int wn4)
{
    int gid = blockIdx.x * blockDim.x + threadIdx.x;
    const float4* in; bf16 *hi, *lo; int i;
    if (gid < xn4) {
        in = x; hi = xh; lo = xl; i = gid;
    } else {
        int g = gid - xn4;
        int sel = g / wn4;
        if (sel >= 4) return;
        i = g - sel * wn4;
        if (sel == 0)      { in = w0; hi = h0p; lo = l0p; }
        else if (sel == 1) { in = w1; hi = h1p; lo = l1p; }
        else if (sel == 2) { in = w2; hi = h2p; lo = l2p; }
        else               { in = w3; hi = h3p; lo = l3p; }
    }
    float4 v = in[i];
    const int row = i >> 8;
    const int c = (i & 255) * 4;
    const size_t off = tiled_off(row, c);
    uint32_t a0, b0, a1, b1;
    split2(v.x, v.y, a0, b0);
    split2(v.z, v.w, a1, b1);
    *(uint2*)(hi + off) = make_uint2(a0, a1);
    *(uint2*)(lo + off) = make_uint2(b0, b1);
}

// ---------------------------------------------------------------------------
// bf16x3 GEMM: BM=128, BN=128, BK=32; 8 warps (4x2), warp tile 32x64;
// 2-stage bulk-copy double buffer; occupancy 2.
// EPI: 0 = fp32 C + bias; 1 = bias + split to linear hi/lo;
//      2 = bias + RMSNORM(warp's 64-col head span) + scale + split to hi/lo.
// ---------------------------------------------------------------------------
#define NKT NKB
#define SUBTILE_B TBLK_BYTES              // 10240
#define STAGE_BYTES (4 * SUBTILE_B)       // 40960 (Ah, Al, Bh, Bl)
#define GEMM_SMEM (128 + 2 * STAGE_BYTES) // 82048

template <int EPI>
__device__ __forceinline__ void gemm_core(
    const bf16* __restrict__ Ah, const bf16* __restrict__ Al,
    const bf16* __restrict__ Bh, const bf16* __restrict__ Bl,
    const float* __restrict__ bias, float* __restrict__ C,
    bf16* __restrict__ Oh, bf16* __restrict__ Ol,
    const float* __restrict__ nw, float nscale, int M,
    int mblk, int nblk, char* dsm)
{
    const uint32_t sbase = smem_u32(dsm);
    const uint32_t mb0 = sbase, mb1 = sbase + 8;
    const uint32_t tiles = sbase + 128;
    const int tid = threadIdx.x;
    const int wid = tid >> 5;
    const int lane = tid & 31;
    const int wm = wid & 3;
    const int wn = wid >> 2;

    float acc[2][8][4];
#pragma unroll
    for (int i = 0; i < 2; i++)
#pragma unroll
        for (int j = 0; j < 8; j++)
#pragma unroll
            for (int r = 0; r < 4; r++) acc[i][j][r] = 0.0f;

    if (tid == 0) { MBAR_INIT(mb0, 1); MBAR_INIT(mb1, 1); }
    __syncthreads();

    const size_t abase_blk = (size_t)mblk * NKB;
    const size_t bbase_blk = (size_t)nblk * NKB;

    auto issue = [&](int kt) {
        const int s = kt & 1;
        const uint32_t dst = tiles + s * STAGE_BYTES;
        const uint32_t m = s ? mb1 : mb0;
        MBAR_EXPECT_TX(m, (uint32_t)STAGE_BYTES);
        const size_t ao = (abase_blk + kt) * TBLK_ELEMS;
        const size_t bo = (bbase_blk + kt) * TBLK_ELEMS;
        BULK_G2S(dst,                  Ah + ao, (uint32_t)TBLK_BYTES, m);
        BULK_G2S(dst + SUBTILE_B,      Al + ao, (uint32_t)TBLK_BYTES, m);
        BULK_G2S(dst + 2 * SUBTILE_B,  Bh + bo, (uint32_t)TBLK_BYTES, m);
        BULK_G2S(dst + 3 * SUBTILE_B,  Bl + bo, (uint32_t)TBLK_BYTES, m);
    };
    if (tid == 0) { issue(0); issue(1); }

    const int a_row = (lane & 15);
    const int a_col = (lane >> 4) * 8;
    const int b_row = (lane & 7) + ((lane >> 4) & 1) * 8;
    const int b_col = ((lane >> 3) & 1) * 8;

    int ph0 = 0, ph1 = 0;
    for (int kt = 0; kt < NKT; kt++) {
        const int s = kt & 1;
        if (s == 0) { mbar_wait(mb0, ph0); ph0 ^= 1; }
        else        { mbar_wait(mb1, ph1); ph1 ^= 1; }
        const uint32_t st = tiles + s * STAGE_BYTES;

#pragma unroll
        for (int ph = 0; ph < 2; ph++) {
            const int koff = ph * 16;
            uint32_t af[2][2][4];
#pragma unroll
            for (int prod = 0; prod < 2; prod++) {
                const uint32_t abase = st + prod * SUBTILE_B;
#pragma unroll
                for (int mf = 0; mf < 2; mf++) {
                    const uint32_t addr = abase +
                        (uint32_t)((wm * 32 + mf * 16 + a_row) * (TROW * 2) +
                                   (koff + a_col) * 2);
                    LDSM_X4(af[prod][mf][0], af[prod][mf][1],
                            af[prod][mf][2], af[prod][mf][3], addr);
                }
            }
#pragma unroll
            for (int np = 0; np < 4; np++) {
                const uint32_t boff =
                    (uint32_t)((wn * 64 + np * 16 + b_row) * (TROW * 2) +
                               (koff + b_col) * 2);
                uint32_t bh[4], bl[4];
                LDSM_X4(bh[0], bh[1], bh[2], bh[3], st + 2 * SUBTILE_B + boff);
                LDSM_X4(bl[0], bl[1], bl[2], bl[3], st + 3 * SUBTILE_B + boff);
                uint32_t bh0[2] = {bh[0], bh[1]}, bh1[2] = {bh[2], bh[3]};
                uint32_t bl0[2] = {bl[0], bl[1]}, bl1[2] = {bl[2], bl[3]};
#pragma unroll
                for (int mf = 0; mf < 2; mf++) {
                    MMA16816(acc[mf][np * 2],     af[0][mf], bh0);
                    MMA16816(acc[mf][np * 2],     af[0][mf], bl0);
                    MMA16816(acc[mf][np * 2],     af[1][mf], bh0);
                    MMA16816(acc[mf][np * 2 + 1], af[0][mf], bh1);
                    MMA16816(acc[mf][np * 2 + 1], af[0][mf], bl1);
                    MMA16816(acc[mf][np * 2 + 1], af[1][mf], bh1);
                }
            }
        }
        __syncthreads();
        if (kt + 2 < NKT && tid == 0) issue(kt + 2);
    }

    const int m0 = mblk * 128, n0 = nblk * 128;
    const int rbase = m0 + wm * 32 + (lane >> 2);
    const int cbase = n0 + wn * 64 + (lane & 3) * 2;
#pragma unroll
    for (int mf = 0; mf < 2; mf++) {
#pragma unroll
        for (int half = 0; half < 2; half++) {
            const int row = rbase + mf * 16 + half * 8;
            if (row >= M) continue;
            float v[8][2];
#pragma unroll
            for (int nf = 0; nf < 8; nf++) {
                const int col = cbase + nf * 8;
                v[nf][0] = acc[mf][nf][half * 2 + 0] + bias[col];
                v[nf][1] = acc[mf][nf][half * 2 + 1] + bias[col + 1];
            }
            if (EPI == 0) {
#pragma unroll
                for (int nf = 0; nf < 8; nf++) {
                    float2 o; o.x = v[nf][0]; o.y = v[nf][1];
                    *(float2*)(C + (size_t)row * C_DIM + cbase + nf * 8) = o;
                }
            } else if (EPI == 1) {
#pragma unroll
                for (int nf = 0; nf < 8; nf++) {
                    uint32_t h, l;
                    split2(v[nf][0], v[nf][1], h, l);
                    *(uint32_t*)(Oh + (size_t)row * C_DIM + cbase + nf * 8) = h;
                    *(uint32_t*)(Ol + (size_t)row * C_DIM + cbase + nf * 8) = l;
                }
            } else {
                float ss = 0.0f;
#pragma unroll
                for (int nf = 0; nf < 8; nf++)
                    ss += v[nf][0] * v[nf][0] + v[nf][1] * v[nf][1];
                ss += __shfl_xor_sync(0xffffffffu, ss, 1);
                ss += __shfl_xor_sync(0xffffffffu, ss, 2);
                const float r = rsqrtf(ss * (1.0f / HD) + EPS_RMS) * nscale;
                const int d0 = (lane & 3) * 2;
#pragma unroll
                for (int nf = 0; nf < 8; nf++) {
                    const int d = nf * 8 + d0;
                    uint32_t h, l;
                    split2(v[nf][0] * r * nw[d], v[nf][1] * r * nw[d + 1], h, l);
                    *(uint32_t*)(Oh + (size_t)row * C_DIM + cbase + nf * 8) = h;
                    *(uint32_t*)(Ol + (size_t)row * C_DIM + cbase + nf * 8) = l;
                }
            }
        }
    }
}

__global__ __launch_bounds__(256, 2)
void gemm_qkv(const bf16* __restrict__ xh, const bf16* __restrict__ xl,
              const bf16* __restrict__ wqh, const bf16* __restrict__ wql,
              const float* __restrict__ bq,
              const bf16* __restrict__ wkh, const bf16* __restrict__ wkl,
              const float* __restrict__ bk,
              const bf16* __restrict__ wvh, const bf16* __restrict__ wvl,
              const float* __restrict__ bv,
              const float* __restrict__ qn, const float* __restrict__ kn,
              bf16* __restrict__ qh, bf16* __restrict__ ql,
              bf16* __restrict__ kh, bf16* __restrict__ kl,
              bf16* __restrict__ vh, bf16* __restrict__ vl, int M)
{
    extern __shared__ char dsm[];
    const int z = blockIdx.z;
    if (z == 0) {
        gemm_core<2>(xh, xl, wqh, wql, bq, nullptr, qh, ql, qn, 0.125f, M,
                     blockIdx.y, blockIdx.x, dsm);
    } else if (z == 1) {
        gemm_core<2>(xh, xl, wkh, wkl, bk, nullptr, kh, kl, kn, 1.0f, M,
                     blockIdx.y, blockIdx.x, dsm);
    } else {
        gemm_core<1>(xh, xl, wvh, wvl, bv, nullptr, vh, vl, nullptr, 0.f, M,
                     blockIdx.y, blockIdx.x, dsm);
    }
}

__global__ __launch_bounds__(256, 2)
void gemm_single(const bf16* __restrict__ Ah, const bf16* __restrict__ Al,
                 const bf16* __restrict__ Bh, const bf16* __restrict__ Bl,
                 const float* __restrict__ bias, float* __restrict__ C, int M)
{
    extern __shared__ char dsm[];
    gemm_core<0>(Ah, Al, Bh, Bl, bias, C, nullptr, nullptr, nullptr, 0.f, M,
                 blockIdx.y, blockIdx.x, dsm);
}

// ---------------------------------------------------------------------------
// Tensorized varlen attention (flash-2, bf16x3); 512 threads (16 warps),
// 256 queries/block, 3-stage K/V pipeline. Epilogue writes TILED layout.
// ---------------------------------------------------------------------------
#define QT 256
#define KSTRIDE_B 144
#define ARR_B (64 * KSTRIDE_B)
#define ATT_STAGE (4 * ARR_B)            // 36864
#define ATT_NSTAGE 3
#define ATT_SMEM (ATT_NSTAGE * ATT_STAGE) // 110592

__global__ __launch_bounds__(512, 1) void attn_mma(const int* __restrict__ cu)
{
    const int seq = blockIdx.x;
    const int head = blockIdx.y;
    const int s0 = cu[seq];
    const int L = cu[seq + 1] - s0;
    const int q0 = blockIdx.z * QT;
    if (q0 >= L) return;

    extern __shared__ char sm[];
    const uint32_t sb = smem_u32(sm);
    const int tid = threadIdx.x;
    const int wid = tid >> 5;        // 0..15
    const int lane = tid & 31;
    const int colh = head * HD;

    uint32_t aQh[4][4], aQl[4][4];
    {
        int r0 = q0 + wid * 16 + (lane >> 2);
        int r1 = r0 + 8;
        if (r0 >= L) r0 = L - 1;
        if (r1 >= L) r1 = L - 1;
        const size_t b0 = (size_t)(s0 + r0) * C_DIM + colh + (lane & 3) * 2;
        const size_t b1 = (size_t)(s0 + r1) * C_DIM + colh + (lane & 3) * 2;
#pragma unroll
        for (int kc = 0; kc < 4; kc++) {
            aQh[kc][0] = *(const uint32_t*)(g_qh + b0 + kc * 16);
            aQh[kc][1] = *(const uint32_t*)(g_qh + b1 + kc * 16);
            aQh[kc][2] = *(const uint32_t*)(g_qh + b0 + kc * 16 + 8);
            aQh[kc][3] = *(const uint32_t*)(g_qh + b1 + kc * 16 + 8);
            aQl[kc][0] = *(const uint32_t*)(g_ql + b0 + kc * 16);
            aQl[kc][1] = *(const uint32_t*)(g_ql + b1 + kc * 16);
            aQl[kc][2] = *(const uint32_t*)(g_ql + b0 + kc * 16 + 8);
            aQl[kc][3] = *(const uint32_t*)(g_ql + b1 + kc * 16 + 8);
        }
    }

    float o[8][4];
#pragma unroll
    for (int i = 0; i < 8; i++)
#pragma unroll
        for (int j = 0; j < 4; j++) o[i][j] = 0.0f;
    float m0 = -1e30f, m1 = -1e30f, l0 = 0.0f, l1 = 0.0f;

    const int ntiles = (L + 63) >> 6;

    auto load_tile = [&](int t) {
        const int s = t % ATT_NSTAGE;
        const uint32_t st = sb + s * ATT_STAGE;
        const int kb = t * 64;
        const bf16* srcs[4] = {g_kh2, g_kl2, g_vh2, g_vl2};
#pragma unroll
        for (int i = 0; i < 4; i++) {
            int c = tid + i * 512;
            int arr = c >> 9;
            int r = (c >> 3) & 63;
            int cc = c & 7;
            int key = kb + r;
            if (key >= L) key = L - 1;
            const void* g = srcs[arr] + (size_t)(s0 + key) * C_DIM + colh + cc * 8;
            CP_ASYNC16(st + arr * ARR_B + r * KSTRIDE_B + cc * 16, g);
        }
    };

    load_tile(0);
    CP_COMMIT();
    if (1 < ntiles) load_tile(1);
    CP_COMMIT();

    for (int t = 0; t < ntiles; t++) {
        if (t + 2 < ntiles) load_tile(t + 2);
        CP_COMMIT();                 // possibly-empty group keeps count uniform
        CP_WAIT(2);
        __syncthreads();
        const uint32_t st = sb + (t % ATT_NSTAGE) * ATT_STAGE;
        const int kb = t * 64;

        float s[8][4];
#pragma unroll
        for (int i = 0; i < 8; i++)
#pragma unroll
            for (int j = 0; j < 4; j++) s[i][j] = 0.0f;

        const int mat = lane >> 3;
#pragma unroll
        for (int kc = 0; kc < 4; kc++) {
#pragma unroll
            for (int pair = 0; pair < 4; pair++) {
                const int krow = (pair * 2 + (mat >> 1)) * 8 + (lane & 7);
                const uint32_t cb = (uint32_t)(kc * 32 + (mat & 1) * 16);
                uint32_t kh[4], kl[4];
                LDSM_X4(kh[0], kh[1], kh[2], kh[3], st + 0     + krow * KSTRIDE_B + cb);
                LDSM_X4(kl[0], kl[1], kl[2], kl[3], st + ARR_B + krow * KSTRIDE_B + cb);
                uint32_t bh0[2] = {kh[0], kh[1]}, bh1[2] = {kh[2], kh[3]};
                uint32_t bl0[2] = {kl[0], kl[1]}, bl1[2] = {kl[2], kl[3]};
                MMA16816(s[pair * 2],     aQh[kc], bh0);
                MMA16816(s[pair * 2],     aQh[kc], bl0);
                MMA16816(s[pair * 2],     aQl[kc], bh0);
                MMA16816(s[pair * 2 + 1], aQh[kc], bh1);
                MMA16816(s[pair * 2 + 1], aQh[kc], bl1);
                MMA16816(s[pair * 2 + 1], aQl[kc], bh1);
            }
        }

        const int cb0 = (lane & 3) * 2;
#pragma unroll
        for (int nf = 0; nf < 8; nf++) {
            int colk = kb + nf * 8 + cb0;
            if (colk >= L)     { s[nf][0] = -1e30f; s[nf][2] = -1e30f; }
            if (colk + 1 >= L) { s[nf][1] = -1e30f; s[nf][3] = -1e30f; }
        }

        float mx0 = -1e30f, mx1 = -1e30f;
#pragma unroll
        for (int nf = 0; nf < 8; nf++) {
            mx0 = fmaxf(mx0, fmaxf(s[nf][0], s[nf][1]));
            mx1 = fmaxf(mx1, fmaxf(s[nf][2], s[nf][3]));
        }
        mx0 = fmaxf(mx0, __shfl_xor_sync(0xffffffffu, mx0, 1));
        mx0 = fmaxf(mx0, __shfl_xor_sync(0xffffffffu, mx0, 2));
        mx1 = fmaxf(mx1, __shfl_xor_sync(0xffffffffu, mx1, 1));
        mx1 = fmaxf(mx1, __shfl_xor_sync(0xffffffffu, mx1, 2));
        const float nm0 = fmaxf(m0, mx0);
        const float nm1 = fmaxf(m1, mx1);
        const float corr0 = __expf(m0 - nm0);
        const float corr1 = __expf(m1 - nm1);
        m0 = nm0; m1 = nm1;
        l0 *= corr0; l1 *= corr1;
#pragma unroll
        for (int nf = 0; nf < 8; nf++) {
            o[nf][0] *= corr0; o[nf][1] *= corr0;
            o[nf][2] *= corr1; o[nf][3] *= corr1;
        }
#pragma unroll
        for (int nf = 0; nf < 8; nf++) {
            s[nf][0] = __expf(s[nf][0] - m0);
            s[nf][1] = __expf(s[nf][1] - m0);
            s[nf][2] = __expf(s[nf][2] - m1);
            s[nf][3] = __expf(s[nf][3] - m1);
            l0 += s[nf][0] + s[nf][1];
            l1 += s[nf][2] + s[nf][3];
        }

#pragma unroll
        for (int j = 0; j < 4; j++) {
            uint32_t ph[4], pl[4];
            split2(s[2 * j][0], s[2 * j][1], ph[0], pl[0]);
            split2(s[2 * j][2], s[2 * j][3], ph[1], pl[1]);
            split2(s[2 * j + 1][0], s[2 * j + 1][1], ph[2], pl[2]);
            split2(s[2 * j + 1][2], s[2 * j + 1][3], ph[3], pl[3]);
            const uint32_t vrow = (uint32_t)((j * 16 + (lane & 15)) * KSTRIDE_B +
                                             ((lane >> 4) << 3) * 2);
#pragma unroll
            for (int vp = 0; vp < 4; vp++) {
                const uint32_t addr = st + 2 * ARR_B + vrow + (uint32_t)(vp * 32);
                uint32_t vh[4], vl[4];
                LDSM_X4_T(vh[0], vh[1], vh[2], vh[3], addr);
                LDSM_X4_T(vl[0], vl[1], vl[2], vl[3], addr + ARR_B);
                uint32_t bh0[2] = {vh[0], vh[1]}, bh1[2] = {vh[2], vh[3]};
                uint32_t bl0[2] = {vl[0], vl[1]}, bl1[2] = {vl[2], vl[3]};
                MMA16816(o[vp * 2],     ph, bh0);
                MMA16816(o[vp * 2],     pl, bh0);
                MMA16816(o[vp * 2],     ph, bl0);
                MMA16816(o[vp * 2 + 1], ph, bh1);
                MMA16816(o[vp * 2 + 1], pl, bh1);
                MMA16816(o[vp * 2 + 1], ph, bl1);
            }
        }
        __syncthreads();
    }

    l0 += __shfl_xor_sync(0xffffffffu, l0, 1);
    l0 += __shfl_xor_sync(0xffffffffu, l0, 2);
    l1 += __shfl_xor_sync(0xffffffffu, l1, 1);
    l1 += __shfl_xor_sync(0xffffffffu, l1, 2);
    const float inv0 = 1.0f / l0;
    const float inv1 = 1.0f / l1;
    const int r0 = q0 + wid * 16 + (lane >> 2);
    const int r1 = r0 + 8;
#pragma unroll
    for (int nf = 0; nf < 8; nf++) {
        const int col = colh + nf * 8 + (lane & 3) * 2;
        if (r0 < L) {
            uint32_t h, l;
            split2(o[nf][0] * inv0, o[nf][1] * inv0, h, l);
            const size_t off = tiled_off(s0 + r0, col);
            *(uint32_t*)(g_ath + off) = h;
            *(uint32_t*)(g_atl + off) = l;
        }
        if (r1 < L) {
            uint32_t h, l;
            split2(o[nf][2] * inv1, o[nf][3] * inv1, h, l);
            const size_t off = tiled_off(s0 + r1, col);
            *(uint32_t*)(g_ath + off) = h;
            *(uint32_t*)(g_atl + off) = l;
        }
    }
}

// ---------------------------------------------------------------------------
// Launch
// ---------------------------------------------------------------------------
extern "C" void kernel_launch(void* const* d_in, const int* in_sizes, int n_in,
                              void* d_out, int out_size)
{
    const float* x  = (const float*)d_in[0];
    const int* cu   = (const int*)d_in[1];
    const float* Wq = (const float*)d_in[2];
    const float* bq = (const float*)d_in[3];
    const float* Wk = (const float*)d_in[4];
    const float* bk = (const float*)d_in[5];
    const float* Wv = (const float*)d_in[6];
    const float* bv = (const float*)d_in[7];
    const float* qn = (const float*)d_in[8];
    const float* kn = (const float*)d_in[9];
    const float* Wo = (const float*)d_in[10];
    const float* bo = (const float*)d_in[11];
    float* out = (float*)d_out;

    const int T = in_sizes[0] / C_DIM;
    const int nseq = in_sizes[1] - 1;

    bf16 *xh, *xl, *qh, *ql, *kh, *kl, *vh, *vl, *ath, *atl;
    bf16 *wqh, *wql, *wkh, *wkl, *wvh, *wvl, *woh, *wol;
    cudaGetSymbolAddress((void**)&xh, g_xh);
    cudaGetSymbolAddress((void**)&xl, g_xl);
    cudaGetSymbolAddress((void**)&qh, g_qh);
    cudaGetSymbolAddress((void**)&ql, g_ql);
    cudaGetSymbolAddress((void**)&kh, g_kh2);
    cudaGetSymbolAddress((void**)&kl, g_kl2);
    cudaGetSymbolAddress((void**)&vh, g_vh2);
    cudaGetSymbolAddress((void**)&vl, g_vl2);
    cudaGetSymbolAddress((void**)&ath, g_ath);
    cudaGetSymbolAddress((void**)&atl, g_atl);
    cudaGetSymbolAddress((void**)&wqh, g_wqh);
    cudaGetSymbolAddress((void**)&wql, g_wql);
    cudaGetSymbolAddress((void**)&wkh, g_wkh);
    cudaGetSymbolAddress((void**)&wkl, g_wkl);
    cudaGetSymbolAddress((void**)&wvh, g_wvh);
    cudaGetSymbolAddress((void**)&wvl, g_wvl);
    cudaGetSymbolAddress((void**)&woh, g_woh);
    cudaGetSymbolAddress((void**)&wol, g_wol);

    cudaFuncSetAttribute(gemm_qkv, cudaFuncAttributeMaxDynamicSharedMemorySize, GEMM_SMEM);
    cudaFuncSetAttribute(gemm_single, cudaFuncAttributeMaxDynamicSharedMemorySize, GEMM_SMEM);
    cudaFuncSetAttribute(attn_mma, cudaFuncAttributeMaxDynamicSharedMemorySize, ATT_SMEM);

    const int xn4 = T * C_DIM / 4;
    const int wn4 = C_DIM * C_DIM / 4;
    const int total = xn4 + 4 * wn4;
    split_all_tiled<<<(total + 255) / 256, 256>>>(
        (const float4*)x,
        (const float4*)Wq, (const float4*)Wk, (const float4*)Wv, (const float4*)Wo,
        xh, xl, wqh, wql, wkh, wkl, wvh, wvl, woh, wol, xn4, wn4);

    dim3 qkv_grid(C_DIM / 128, (T + 127) / 128, 3);
    gemm_qkv<<<qkv_grid, 256, GEMM_SMEM>>>(xh, xl,
                                           wqh, wql, bq,
                                           wkh, wkl, bk,
                                           wvh, wvl, bv,
                                           qn, kn,
                                           qh, ql, kh, kl, vh, vl, T);

    dim3 attn_grid(nseq, NH, LMAX / QT);
    attn_mma<<<attn_grid, 512, ATT_SMEM>>>(cu);

    dim3 ggrid(C_DIM / 128, (T + 127) / 128);
    gemm_single<<<ggrid, 256, GEMM_SMEM>>>(ath, atl, woh, wol, bo, out, T);
}

// round 11
// speedup vs baseline: 1.5846x; 1.5846x over previous
#include <cuda_runtime.h>
#include <cuda_bf16.h>
#include <cstdint>

#define C_DIM 1024
#define NH 16
#define HD 64
#define MAX_T 8192
#define LMAX 1024
#define EPS_RMS 1.1920929e-07f

typedef __nv_bfloat16 bf16;

// ---------------- scratch (device globals; allocation-free rule) ----------
// linear layouts (attention operands)
__device__ bf16 g_qh[MAX_T * C_DIM];
__device__ bf16 g_ql[MAX_T * C_DIM];
__device__ bf16 g_kh2[MAX_T * C_DIM];
__device__ bf16 g_kl2[MAX_T * C_DIM];
__device__ bf16 g_vh2[MAX_T * C_DIM];
__device__ bf16 g_vl2[MAX_T * C_DIM];

// tiled layouts (GEMM operands): [blk128][kblk32][128 rows x 40 elems]
#define TROW 40
#define TBLK_ELEMS (128 * TROW)       // 5120 elems
#define TBLK_BYTES (TBLK_ELEMS * 2)   // 10240 B
#define NKB (C_DIM / 32)              // 32 k-blocks
__device__ bf16 g_xh[(MAX_T / 128) * NKB * TBLK_ELEMS];
__device__ bf16 g_xl[(MAX_T / 128) * NKB * TBLK_ELEMS];
__device__ bf16 g_ath[(MAX_T / 128) * NKB * TBLK_ELEMS];
__device__ bf16 g_atl[(MAX_T / 128) * NKB * TBLK_ELEMS];
__device__ bf16 g_wqh[8 * NKB * TBLK_ELEMS];
__device__ bf16 g_wql[8 * NKB * TBLK_ELEMS];
__device__ bf16 g_wkh[8 * NKB * TBLK_ELEMS];
__device__ bf16 g_wkl[8 * NKB * TBLK_ELEMS];
__device__ bf16 g_wvh[8 * NKB * TBLK_ELEMS];
__device__ bf16 g_wvl[8 * NKB * TBLK_ELEMS];
__device__ bf16 g_woh[8 * NKB * TBLK_ELEMS];
__device__ bf16 g_wol[8 * NKB * TBLK_ELEMS];

// ---------------- helpers ---------------------------------------------
__device__ __forceinline__ uint32_t smem_u32(const void* p) {
    uint32_t a;
    asm("{ .reg .u64 t; cvta.to.shared.u64 t, %1; cvt.u32.u64 %0, t; }"
        : "=r"(a) : "l"(p));
    return a;
}

__device__ __forceinline__ size_t tiled_off(int r, int c) {
    return ((size_t)((r >> 7) * NKB + (c >> 5))) * TBLK_ELEMS +
           (size_t)((r & 127) * TROW + (c & 31));
}

#define LDSM_X4(r0, r1, r2, r3, addr) \
    asm volatile("ldmatrix.sync.aligned.m8n8.x4.shared.b16 {%0,%1,%2,%3}, [%4];" \
                 : "=r"(r0), "=r"(r1), "=r"(r2), "=r"(r3) : "r"(addr))

#define LDSM_X4_T(r0, r1, r2, r3, addr) \
    asm volatile("ldmatrix.sync.aligned.m8n8.x4.trans.shared.b16 {%0,%1,%2,%3}, [%4];" \
                 : "=r"(r0), "=r"(r1), "=r"(r2), "=r"(r3) : "r"(addr))

#define MMA16816(d, a, b) \
    asm volatile("mma.sync.aligned.m16n8k16.row.col.f32.bf16.bf16.f32 " \
                 "{%0,%1,%2,%3}, {%4,%5,%6,%7}, {%8,%9}, {%0,%1,%2,%3};" \
                 : "+f"((d)[0]), "+f"((d)[1]), "+f"((d)[2]), "+f"((d)[3]) \
                 : "r"((a)[0]), "r"((a)[1]), "r"((a)[2]), "r"((a)[3]), \
                   "r"((b)[0]), "r"((b)[1]))

#define CP_ASYNC16(dst, src) \
    asm volatile("cp.async.cg.shared.global [%0], [%1], 16;" :: "r"(dst), "l"(src))
#define CP_COMMIT() asm volatile("cp.async.commit_group;" ::: "memory")
#define CP_WAIT(n)  asm volatile("cp.async.wait_group %0;" :: "n"(n) : "memory")

#define MBAR_INIT(a, cnt) \
    asm volatile("mbarrier.init.shared.b64 [%0], %1;" :: "r"(a), "r"(cnt) : "memory")
#define MBAR_EXPECT_TX(a, bytes) \
    asm volatile("mbarrier.arrive.expect_tx.shared.b64 _, [%0], %1;" \
                 :: "r"(a), "r"(bytes) : "memory")
#define BULK_G2S(dst, src, bytes, mbar) \
    asm volatile("cp.async.bulk.shared::cta.global.mbarrier::complete_tx::bytes " \
                 "[%0], [%1], %2, [%3];" \
                 :: "r"(dst), "l"(src), "r"(bytes), "r"(mbar) : "memory")

__device__ __forceinline__ void mbar_wait(uint32_t a, int phase) {
    asm volatile(
        "{ .reg .pred P;\n"
        "WL%=:\n"
        " mbarrier.try_wait.parity.acquire.cta.shared::cta.b64 P, [%0], %1, 0x989680;\n"
        " @P bra WD%=;\n"
        " bra WL%=;\n"
        "WD%=: }"
        :: "r"(a), "r"(phase) : "memory");
}

__device__ __forceinline__ void split2(float x, float y, uint32_t& h, uint32_t& l) {
    bf16 hx = __float2bfloat16(x);
    bf16 hy = __float2bfloat16(y);
    __nv_bfloat162 H; H.x = hx; H.y = hy;
    __nv_bfloat162 L;
    L.x = __float2bfloat16(x - __bfloat162float(hx));
    L.y = __float2bfloat16(y - __bfloat162float(hy));
    h = *(uint32_t*)&H;
    l = *(uint32_t*)&L;
}

// ---------------------------------------------------------------------------
// fused fp32 -> (hi,lo) split into TILED layout: x + 4 weight matrices
// ---------------------------------------------------------------------------
__global__ __launch_bounds__(256) void split_all_tiled(
    const float4* __restrict__ x,
    const float4* __restrict__ w0, const float4* __restrict__ w1,
    const float4* __restrict__ w2, const float4* __restrict__ w3,
    bf16* __restrict__ xh, bf16* __restrict__ xl,
    bf16* __restrict__ h0p, bf16* __restrict__ l0p,
    bf16* __restrict__ h1p, bf16* __restrict__ l1p,
    bf16* __restrict__ h2p, bf16* __restrict__ l2p,
    bf16* __restrict__ h3p, bf16* __restrict__ l3p,
    int xn4, int wn4)
{
    int gid = blockIdx.x * blockDim.x + threadIdx.x;
    const float4* in; bf16 *hi, *lo; int i;
    if (gid < xn4) {
        in = x; hi = xh; lo = xl; i = gid;
    } else {
        int g = gid - xn4;
        int sel = g / wn4;
        if (sel >= 4) return;
        i = g - sel * wn4;
        if (sel == 0)      { in = w0; hi = h0p; lo = l0p; }
        else if (sel == 1) { in = w1; hi = h1p; lo = l1p; }
        else if (sel == 2) { in = w2; hi = h2p; lo = l2p; }
        else               { in = w3; hi = h3p; lo = l3p; }
    }
    float4 v = in[i];
    const int row = i >> 8;
    const int c = (i & 255) * 4;
    const size_t off = tiled_off(row, c);
    uint32_t a0, b0, a1, b1;
    split2(v.x, v.y, a0, b0);
    split2(v.z, v.w, a1, b1);
    *(uint2*)(hi + off) = make_uint2(a0, a1);
    *(uint2*)(lo + off) = make_uint2(b0, b1);
}

// ---------------------------------------------------------------------------
// bf16x3 GEMM: BM=128, BN=128, BK=32; 8 warps (4x2), warp tile 32x64;
// 2-stage bulk-copy double buffer; occupancy 2.
// EPI: 0 = fp32 C + bias; 1 = bias + split to linear hi/lo;
//      2 = bias + RMSNORM(warp's 64-col head span) + scale + split to hi/lo.
// ---------------------------------------------------------------------------
#define NKT NKB
#define SUBTILE_B TBLK_BYTES              // 10240
#define STAGE_BYTES (4 * SUBTILE_B)       // 40960 (Ah, Al, Bh, Bl)
#define GEMM_SMEM (128 + 2 * STAGE_BYTES) // 82048

template <int EPI>
__device__ __forceinline__ void gemm_core(
    const bf16* __restrict__ Ah, const bf16* __restrict__ Al,
    const bf16* __restrict__ Bh, const bf16* __restrict__ Bl,
    const float* __restrict__ bias, float* __restrict__ C,
    bf16* __restrict__ Oh, bf16* __restrict__ Ol,
    const float* __restrict__ nw, float nscale, int M,
    int mblk, int nblk, char* dsm)
{
    const uint32_t sbase = smem_u32(dsm);
    const uint32_t mb0 = sbase, mb1 = sbase + 8;
    const uint32_t tiles = sbase + 128;
    const int tid = threadIdx.x;
    const int wid = tid >> 5;
    const int lane = tid & 31;
    const int wm = wid & 3;
    const int wn = wid >> 2;

    float acc[2][8][4];
#pragma unroll
    for (int i = 0; i < 2; i++)
#pragma unroll
        for (int j = 0; j < 8; j++)
#pragma unroll
            for (int r = 0; r < 4; r++) acc[i][j][r] = 0.0f;

    if (tid == 0) { MBAR_INIT(mb0, 1); MBAR_INIT(mb1, 1); }
    __syncthreads();

    const size_t abase_blk = (size_t)mblk * NKB;
    const size_t bbase_blk = (size_t)nblk * NKB;

    auto issue = [&](int kt) {
        const int s = kt & 1;
        const uint32_t dst = tiles + s * STAGE_BYTES;
        const uint32_t m = s ? mb1 : mb0;
        MBAR_EXPECT_TX(m, (uint32_t)STAGE_BYTES);
        const size_t ao = (abase_blk + kt) * TBLK_ELEMS;
        const size_t bo = (bbase_blk + kt) * TBLK_ELEMS;
        BULK_G2S(dst,                  Ah + ao, (uint32_t)TBLK_BYTES, m);
        BULK_G2S(dst + SUBTILE_B,      Al + ao, (uint32_t)TBLK_BYTES, m);
        BULK_G2S(dst + 2 * SUBTILE_B,  Bh + bo, (uint32_t)TBLK_BYTES, m);
        BULK_G2S(dst + 3 * SUBTILE_B,  Bl + bo, (uint32_t)TBLK_BYTES, m);
    };
    if (tid == 0) { issue(0); issue(1); }

    const int a_row = (lane & 15);
    const int a_col = (lane >> 4) * 8;
    const int b_row = (lane & 7) + ((lane >> 4) & 1) * 8;
    const int b_col = ((lane >> 3) & 1) * 8;

    int ph0 = 0, ph1 = 0;
    for (int kt = 0; kt < NKT; kt++) {
        const int s = kt & 1;
        if (s == 0) { mbar_wait(mb0, ph0); ph0 ^= 1; }
        else        { mbar_wait(mb1, ph1); ph1 ^= 1; }
        const uint32_t st = tiles + s * STAGE_BYTES;

#pragma unroll
        for (int ph = 0; ph < 2; ph++) {
            const int koff = ph * 16;
            uint32_t af[2][2][4];
#pragma unroll
            for (int prod = 0; prod < 2; prod++) {
                const uint32_t abase = st + prod * SUBTILE_B;
#pragma unroll
                for (int mf = 0; mf < 2; mf++) {
                    const uint32_t addr = abase +
                        (uint32_t)((wm * 32 + mf * 16 + a_row) * (TROW * 2) +
                                   (koff + a_col) * 2);
                    LDSM_X4(af[prod][mf][0], af[prod][mf][1],
                            af[prod][mf][2], af[prod][mf][3], addr);
                }
            }
#pragma unroll
            for (int np = 0; np < 4; np++) {
                const uint32_t boff =
                    (uint32_t)((wn * 64 + np * 16 + b_row) * (TROW * 2) +
                               (koff + b_col) * 2);
                uint32_t bh[4], bl[4];
                LDSM_X4(bh[0], bh[1], bh[2], bh[3], st + 2 * SUBTILE_B + boff);
                LDSM_X4(bl[0], bl[1], bl[2], bl[3], st + 3 * SUBTILE_B + boff);
                uint32_t bh0[2] = {bh[0], bh[1]}, bh1[2] = {bh[2], bh[3]};
                uint32_t bl0[2] = {bl[0], bl[1]}, bl1[2] = {bl[2], bl[3]};
#pragma unroll
                for (int mf = 0; mf < 2; mf++) {
                    MMA16816(acc[mf][np * 2],     af[0][mf], bh0);
                    MMA16816(acc[mf][np * 2],     af[0][mf], bl0);
                    MMA16816(acc[mf][np * 2],     af[1][mf], bh0);
                    MMA16816(acc[mf][np * 2 + 1], af[0][mf], bh1);
                    MMA16816(acc[mf][np * 2 + 1], af[0][mf], bl1);
                    MMA16816(acc[mf][np * 2 + 1], af[1][mf], bh1);
                }
            }
        }
        __syncthreads();
        if (kt + 2 < NKT && tid == 0) issue(kt + 2);
    }

    const int m0 = mblk * 128, n0 = nblk * 128;
    const int rbase = m0 + wm * 32 + (lane >> 2);
    const int cbase = n0 + wn * 64 + (lane & 3) * 2;
#pragma unroll
    for (int mf = 0; mf < 2; mf++) {
#pragma unroll
        for (int half = 0; half < 2; half++) {
            const int row = rbase + mf * 16 + half * 8;
            if (row >= M) continue;
            float v[8][2];
#pragma unroll
            for (int nf = 0; nf < 8; nf++) {
                const int col = cbase + nf * 8;
                v[nf][0] = acc[mf][nf][half * 2 + 0] + bias[col];
                v[nf][1] = acc[mf][nf][half * 2 + 1] + bias[col + 1];
            }
            if (EPI == 0) {
#pragma unroll
                for (int nf = 0; nf < 8; nf++) {
                    float2 o; o.x = v[nf][0]; o.y = v[nf][1];
                    *(float2*)(C + (size_t)row * C_DIM + cbase + nf * 8) = o;
                }
            } else if (EPI == 1) {
#pragma unroll
                for (int nf = 0; nf < 8; nf++) {
                    uint32_t h, l;
                    split2(v[nf][0], v[nf][1], h, l);
                    *(uint32_t*)(Oh + (size_t)row * C_DIM + cbase + nf * 8) = h;
                    *(uint32_t*)(Ol + (size_t)row * C_DIM + cbase + nf * 8) = l;
                }
            } else {
                float ss = 0.0f;
#pragma unroll
                for (int nf = 0; nf < 8; nf++)
                    ss += v[nf][0] * v[nf][0] + v[nf][1] * v[nf][1];
                ss += __shfl_xor_sync(0xffffffffu, ss, 1);
                ss += __shfl_xor_sync(0xffffffffu, ss, 2);
                const float r = rsqrtf(ss * (1.0f / HD) + EPS_RMS) * nscale;
                const int d0 = (lane & 3) * 2;
#pragma unroll
                for (int nf = 0; nf < 8; nf++) {
                    const int d = nf * 8 + d0;
                    uint32_t h, l;
                    split2(v[nf][0] * r * nw[d], v[nf][1] * r * nw[d + 1], h, l);
                    *(uint32_t*)(Oh + (size_t)row * C_DIM + cbase + nf * 8) = h;
                    *(uint32_t*)(Ol + (size_t)row * C_DIM + cbase + nf * 8) = l;
                }
            }
        }
    }
}

__global__ __launch_bounds__(256, 2)
void gemm_qkv(const bf16* __restrict__ xh, const bf16* __restrict__ xl,
              const bf16* __restrict__ wqh, const bf16* __restrict__ wql,
              const float* __restrict__ bq,
              const bf16* __restrict__ wkh, const bf16* __restrict__ wkl,
              const float* __restrict__ bk,
              const bf16* __restrict__ wvh, const bf16* __restrict__ wvl,
              const float* __restrict__ bv,
              const float* __restrict__ qn, const float* __restrict__ kn,
              bf16* __restrict__ qh, bf16* __restrict__ ql,
              bf16* __restrict__ kh, bf16* __restrict__ kl,
              bf16* __restrict__ vh, bf16* __restrict__ vl, int M)
{
    extern __shared__ char dsm[];
    const int z = blockIdx.z;
    if (z == 0) {
        gemm_core<2>(xh, xl, wqh, wql, bq, nullptr, qh, ql, qn, 0.125f, M,
                     blockIdx.y, blockIdx.x, dsm);
    } else if (z == 1) {
        gemm_core<2>(xh, xl, wkh, wkl, bk, nullptr, kh, kl, kn, 1.0f, M,
                     blockIdx.y, blockIdx.x, dsm);
    } else {
        gemm_core<1>(xh, xl, wvh, wvl, bv, nullptr, vh, vl, nullptr, 0.f, M,
                     blockIdx.y, blockIdx.x, dsm);
    }
}

// ---------------------------------------------------------------------------
// Output-projection GEMM, BM=64 variant: 8 warps each 16x64, more CTAs to
// reduce wave-quantization tail. A half-blocks are contiguous 5120B slices
// of the tiled layout.
// ---------------------------------------------------------------------------
#define AHALF_B (64 * TROW * 2)            // 5120
#define STAGE64 (2 * AHALF_B + 2 * TBLK_BYTES)  // 30720
#define GEMM64_SMEM (128 + 2 * STAGE64)    // 61568

__global__ __launch_bounds__(256, 2)
void gemm_out64(const bf16* __restrict__ Ah, const bf16* __restrict__ Al,
                const bf16* __restrict__ Bh, const bf16* __restrict__ Bl,
                const float* __restrict__ bias, float* __restrict__ C, int M)
{
    extern __shared__ char dsm[];
    const uint32_t sbase = smem_u32(dsm);
    const uint32_t mb0 = sbase, mb1 = sbase + 8;
    const uint32_t tiles = sbase + 128;
    const int tid = threadIdx.x;
    const int wid = tid >> 5;
    const int lane = tid & 31;
    const int wm = wid & 3;      // 4 warp-rows of 16
    const int wn = wid >> 2;     // 2 warp-cols of 64
    const int mblk = blockIdx.y; // 64-row block
    const int nblk = blockIdx.x;
    const int ablk = mblk >> 1, ahalf = mblk & 1;

    float acc[8][4];
#pragma unroll
    for (int j = 0; j < 8; j++)
#pragma unroll
        for (int r = 0; r < 4; r++) acc[j][r] = 0.0f;

    if (tid == 0) { MBAR_INIT(mb0, 1); MBAR_INIT(mb1, 1); }
    __syncthreads();

    const size_t abase_blk = (size_t)ablk * NKB;
    const size_t bbase_blk = (size_t)nblk * NKB;

    auto issue = [&](int kt) {
        const int s = kt & 1;
        const uint32_t dst = tiles + s * STAGE64;
        const uint32_t m = s ? mb1 : mb0;
        MBAR_EXPECT_TX(m, (uint32_t)STAGE64);
        const size_t ao = (abase_blk + kt) * TBLK_ELEMS + (size_t)ahalf * (64 * TROW);
        const size_t bo = (bbase_blk + kt) * TBLK_ELEMS;
        BULK_G2S(dst,                        Ah + ao, (uint32_t)AHALF_B, m);
        BULK_G2S(dst + AHALF_B,              Al + ao, (uint32_t)AHALF_B, m);
        BULK_G2S(dst + 2 * AHALF_B,               Bh + bo, (uint32_t)TBLK_BYTES, m);
        BULK_G2S(dst + 2 * AHALF_B + TBLK_BYTES,  Bl + bo, (uint32_t)TBLK_BYTES, m);
    };
    if (tid == 0) { issue(0); issue(1); }

    const int a_row = (lane & 15);
    const int a_col = (lane >> 4) * 8;
    const int b_row = (lane & 7) + ((lane >> 4) & 1) * 8;
    const int b_col = ((lane >> 3) & 1) * 8;

    int ph0 = 0, ph1 = 0;
    for (int kt = 0; kt < NKT; kt++) {
        const int s = kt & 1;
        if (s == 0) { mbar_wait(mb0, ph0); ph0 ^= 1; }
        else        { mbar_wait(mb1, ph1); ph1 ^= 1; }
        const uint32_t st = tiles + s * STAGE64;

#pragma unroll
        for (int ph = 0; ph < 2; ph++) {
            const int koff = ph * 16;
            uint32_t af[2][4];
#pragma unroll
            for (int prod = 0; prod < 2; prod++) {
                const uint32_t addr = st + prod * AHALF_B +
                    (uint32_t)((wm * 16 + a_row) * (TROW * 2) + (koff + a_col) * 2);
                LDSM_X4(af[prod][0], af[prod][1], af[prod][2], af[prod][3], addr);
            }
#pragma unroll
            for (int np = 0; np < 4; np++) {
                const uint32_t boff =
                    (uint32_t)((wn * 64 + np * 16 + b_row) * (TROW * 2) +
                               (koff + b_col) * 2);
                uint32_t bh[4], bl[4];
                LDSM_X4(bh[0], bh[1], bh[2], bh[3], st + 2 * AHALF_B + boff);
                LDSM_X4(bl[0], bl[1], bl[2], bl[3], st + 2 * AHALF_B + TBLK_BYTES + boff);
                uint32_t bh0[2] = {bh[0], bh[1]}, bh1[2] = {bh[2], bh[3]};
                uint32_t bl0[2] = {bl[0], bl[1]}, bl1[2] = {bl[2], bl[3]};
                MMA16816(acc[np * 2],     af[0], bh0);
                MMA16816(acc[np * 2],     af[0], bl0);
                MMA16816(acc[np * 2],     af[1], bh0);
                MMA16816(acc[np * 2 + 1], af[0], bh1);
                MMA16816(acc[np * 2 + 1], af[0], bl1);
                MMA16816(acc[np * 2 + 1], af[1], bh1);
            }
        }
        __syncthreads();
        if (kt + 2 < NKT && tid == 0) issue(kt + 2);
    }

    const int m0 = mblk * 64, n0 = nblk * 128;
    const int rbase = m0 + wm * 16 + (lane >> 2);
    const int cbase = n0 + wn * 64 + (lane & 3) * 2;
#pragma unroll
    for (int half = 0; half < 2; half++) {
        const int row = rbase + half * 8;
        if (row >= M) continue;
#pragma unroll
        for (int nf = 0; nf < 8; nf++) {
            const int col = cbase + nf * 8;
            float2 o;
            o.x = acc[nf][half * 2 + 0] + bias[col];
            o.y = acc[nf][half * 2 + 1] + bias[col + 1];
            *(float2*)(C + (size_t)row * C_DIM + col) = o;
        }
    }
}

// ---------------------------------------------------------------------------
// Tensorized varlen attention (flash-2, bf16x3); R8 config: 256 thr, occ 2,
// 128 queries/block, 2-stage K/V pipeline. Epilogue writes TILED layout.
// ---------------------------------------------------------------------------
#define KSTRIDE_B 144
#define ARR_B (64 * KSTRIDE_B)
#define ATT_STAGE (4 * ARR_B)
#define ATT_SMEM (2 * ATT_STAGE)

__global__ __launch_bounds__(256, 2) void attn_mma(const int* __restrict__ cu)
{
    const int seq = blockIdx.x;
    const int head = blockIdx.y;
    const int s0 = cu[seq];
    const int L = cu[seq + 1] - s0;
    const int q0 = blockIdx.z * 128;
    if (q0 >= L) return;

    extern __shared__ char sm[];
    const uint32_t sb = smem_u32(sm);
    const int tid = threadIdx.x;
    const int wid = tid >> 5;
    const int lane = tid & 31;
    const int colh = head * HD;

    uint32_t aQh[4][4], aQl[4][4];
    {
        int r0 = q0 + wid * 16 + (lane >> 2);
        int r1 = r0 + 8;
        if (r0 >= L) r0 = L - 1;
        if (r1 >= L) r1 = L - 1;
        const size_t b0 = (size_t)(s0 + r0) * C_DIM + colh + (lane & 3) * 2;
        const size_t b1 = (size_t)(s0 + r1) * C_DIM + colh + (lane & 3) * 2;
#pragma unroll
        for (int kc = 0; kc < 4; kc++) {
            aQh[kc][0] = *(const uint32_t*)(g_qh + b0 + kc * 16);
            aQh[kc][1] = *(const uint32_t*)(g_qh + b1 + kc * 16);
            aQh[kc][2] = *(const uint32_t*)(g_qh + b0 + kc * 16 + 8);
            aQh[kc][3] = *(const uint32_t*)(g_qh + b1 + kc * 16 + 8);
            aQl[kc][0] = *(const uint32_t*)(g_ql + b0 + kc * 16);
            aQl[kc][1] = *(const uint32_t*)(g_ql + b1 + kc * 16);
            aQl[kc][2] = *(const uint32_t*)(g_ql + b0 + kc * 16 + 8);
            aQl[kc][3] = *(const uint32_t*)(g_ql + b1 + kc * 16 + 8);
        }
    }

    float o[8][4];
#pragma unroll
    for (int i = 0; i < 8; i++)
#pragma unroll
        for (int j = 0; j < 4; j++) o[i][j] = 0.0f;
    float m0 = -1e30f, m1 = -1e30f, l0 = 0.0f, l1 = 0.0f;

    const int ntiles = (L + 63) >> 6;

    auto load_tile = [&](int t) {
        const uint32_t st = sb + (t & 1) * ATT_STAGE;
        const int kb = t * 64;
        const bf16* srcs[4] = {g_kh2, g_kl2, g_vh2, g_vl2};
#pragma unroll
        for (int i = 0; i < 8; i++) {
            int c = tid + i * 256;
            int arr = c >> 9;
            int r = (c >> 3) & 63;
            int cc = c & 7;
            int key = kb + r;
            if (key >= L) key = L - 1;
            const void* g = srcs[arr] + (size_t)(s0 + key) * C_DIM + colh + cc * 8;
            CP_ASYNC16(st + arr * ARR_B + r * KSTRIDE_B + cc * 16, g);
        }
    };

    load_tile(0);
    CP_COMMIT();

    for (int t = 0; t < ntiles; t++) {
        if (t + 1 < ntiles) { load_tile(t + 1); CP_COMMIT(); CP_WAIT(1); }
        else { CP_WAIT(0); }
        __syncthreads();
        const uint32_t st = sb + (t & 1) * ATT_STAGE;
        const int kb = t * 64;

        float s[8][4];
#pragma unroll
        for (int i = 0; i < 8; i++)
#pragma unroll
            for (int j = 0; j < 4; j++) s[i][j] = 0.0f;

        const int mat = lane >> 3;
#pragma unroll
        for (int kc = 0; kc < 4; kc++) {
#pragma unroll
            for (int pair = 0; pair < 4; pair++) {
                const int krow = (pair * 2 + (mat >> 1)) * 8 + (lane & 7);
                const uint32_t cb = (uint32_t)(kc * 32 + (mat & 1) * 16);
                uint32_t kh[4], kl[4];
                LDSM_X4(kh[0], kh[1], kh[2], kh[3], st + 0     + krow * KSTRIDE_B + cb);
                LDSM_X4(kl[0], kl[1], kl[2], kl[3], st + ARR_B + krow * KSTRIDE_B + cb);
                uint32_t bh0[2] = {kh[0], kh[1]}, bh1[2] = {kh[2], kh[3]};
                uint32_t bl0[2] = {kl[0], kl[1]}, bl1[2] = {kl[2], kl[3]};
                MMA16816(s[pair * 2],     aQh[kc], bh0);
                MMA16816(s[pair * 2],     aQh[kc], bl0);
                MMA16816(s[pair * 2],     aQl[kc], bh0);
                MMA16816(s[pair * 2 + 1], aQh[kc], bh1);
                MMA16816(s[pair * 2 + 1], aQh[kc], bl1);
                MMA16816(s[pair * 2 + 1], aQl[kc], bh1);
            }
        }

        const int cb0 = (lane & 3) * 2;
#pragma unroll
        for (int nf = 0; nf < 8; nf++) {
            int colk = kb + nf * 8 + cb0;
            if (colk >= L)     { s[nf][0] = -1e30f; s[nf][2] = -1e30f; }
            if (colk + 1 >= L) { s[nf][1] = -1e30f; s[nf][3] = -1e30f; }
        }

        float mx0 = -1e30f, mx1 = -1e30f;
#pragma unroll
        for (int nf = 0; nf < 8; nf++) {
            mx0 = fmaxf(mx0, fmaxf(s[nf][0], s[nf][1]));
            mx1 = fmaxf(mx1, fmaxf(s[nf][2], s[nf][3]));
        }
        mx0 = fmaxf(mx0, __shfl_xor_sync(0xffffffffu, mx0, 1));
        mx0 = fmaxf(mx0, __shfl_xor_sync(0xffffffffu, mx0, 2));
        mx1 = fmaxf(mx1, __shfl_xor_sync(0xffffffffu, mx1, 1));
        mx1 = fmaxf(mx1, __shfl_xor_sync(0xffffffffu, mx1, 2));
        const float nm0 = fmaxf(m0, mx0);
        const float nm1 = fmaxf(m1, mx1);
        const float corr0 = __expf(m0 - nm0);
        const float corr1 = __expf(m1 - nm1);
        m0 = nm0; m1 = nm1;
        l0 *= corr0; l1 *= corr1;
#pragma unroll
        for (int nf = 0; nf < 8; nf++) {
            o[nf][0] *= corr0; o[nf][1] *= corr0;
            o[nf][2] *= corr1; o[nf][3] *= corr1;
        }
#pragma unroll
        for (int nf = 0; nf < 8; nf++) {
            s[nf][0] = __expf(s[nf][0] - m0);
            s[nf][1] = __expf(s[nf][1] - m0);
            s[nf][2] = __expf(s[nf][2] - m1);
            s[nf][3] = __expf(s[nf][3] - m1);
            l0 += s[nf][0] + s[nf][1];
            l1 += s[nf][2] + s[nf][3];
        }

#pragma unroll
        for (int j = 0; j < 4; j++) {
            uint32_t ph[4], pl[4];
            split2(s[2 * j][0], s[2 * j][1], ph[0], pl[0]);
            split2(s[2 * j][2], s[2 * j][3], ph[1], pl[1]);
            split2(s[2 * j + 1][0], s[2 * j + 1][1], ph[2], pl[2]);
            split2(s[2 * j + 1][2], s[2 * j + 1][3], ph[3], pl[3]);
            const uint32_t vrow = (uint32_t)((j * 16 + (lane & 15)) * KSTRIDE_B +
                                             ((lane >> 4) << 3) * 2);
#pragma unroll
            for (int vp = 0; vp < 4; vp++) {
                const uint32_t addr = st + 2 * ARR_B + vrow + (uint32_t)(vp * 32);
                uint32_t vh[4], vl[4];
                LDSM_X4_T(vh[0], vh[1], vh[2], vh[3], addr);
                LDSM_X4_T(vl[0], vl[1], vl[2], vl[3], addr + ARR_B);
                uint32_t bh0[2] = {vh[0], vh[1]}, bh1[2] = {vh[2], vh[3]};
                uint32_t bl0[2] = {vl[0], vl[1]}, bl1[2] = {vl[2], vl[3]};
                MMA16816(o[vp * 2],     ph, bh0);
                MMA16816(o[vp * 2],     pl, bh0);
                MMA16816(o[vp * 2],     ph, bl0);
                MMA16816(o[vp * 2 + 1], ph, bh1);
                MMA16816(o[vp * 2 + 1], pl, bh1);
                MMA16816(o[vp * 2 + 1], ph, bl1);
            }
        }
        __syncthreads();
    }

    l0 += __shfl_xor_sync(0xffffffffu, l0, 1);
    l0 += __shfl_xor_sync(0xffffffffu, l0, 2);
    l1 += __shfl_xor_sync(0xffffffffu, l1, 1);
    l1 += __shfl_xor_sync(0xffffffffu, l1, 2);
    const float inv0 = 1.0f / l0;
    const float inv1 = 1.0f / l1;
    const int r0 = q0 + wid * 16 + (lane >> 2);
    const int r1 = r0 + 8;
#pragma unroll
    for (int nf = 0; nf < 8; nf++) {
        const int col = colh + nf * 8 + (lane & 3) * 2;
        if (r0 < L) {
            uint32_t h, l;
            split2(o[nf][0] * inv0, o[nf][1] * inv0, h, l);
            const size_t off = tiled_off(s0 + r0, col);
            *(uint32_t*)(g_ath + off) = h;
            *(uint32_t*)(g_atl + off) = l;
        }
        if (r1 < L) {
            uint32_t h, l;
            split2(o[nf][2] * inv1, o[nf][3] * inv1, h, l);
            const size_t off = tiled_off(s0 + r1, col);
            *(uint32_t*)(g_ath + off) = h;
            *(uint32_t*)(g_atl + off) = l;
        }
    }
}

// ---------------------------------------------------------------------------
// Launch
// ---------------------------------------------------------------------------
extern "C" void kernel_launch(void* const* d_in, const int* in_sizes, int n_in,
                              void* d_out, int out_size)
{
    const float* x  = (const float*)d_in[0];
    const int* cu   = (const int*)d_in[1];
    const float* Wq = (const float*)d_in[2];
    const float* bq = (const float*)d_in[3];
    const float* Wk = (const float*)d_in[4];
    const float* bk = (const float*)d_in[5];
    const float* Wv = (const float*)d_in[6];
    const float* bv = (const float*)d_in[7];
    const float* qn = (const float*)d_in[8];
    const float* kn = (const float*)d_in[9];
    const float* Wo = (const float*)d_in[10];
    const float* bo = (const float*)d_in[11];
    float* out = (float*)d_out;

    const int T = in_sizes[0] / C_DIM;
    const int nseq = in_sizes[1] - 1;

    bf16 *xh, *xl, *qh, *ql, *kh, *kl, *vh, *vl, *ath, *atl;
    bf16 *wqh, *wql, *wkh, *wkl, *wvh, *wvl, *woh, *wol;
    cudaGetSymbolAddress((void**)&xh, g_xh);
    cudaGetSymbolAddress((void**)&xl, g_xl);
    cudaGetSymbolAddress((void**)&qh, g_qh);
    cudaGetSymbolAddress((void**)&ql, g_ql);
    cudaGetSymbolAddress((void**)&kh, g_kh2);
    cudaGetSymbolAddress((void**)&kl, g_kl2);
    cudaGetSymbolAddress((void**)&vh, g_vh2);
    cudaGetSymbolAddress((void**)&vl, g_vl2);
    cudaGetSymbolAddress((void**)&ath, g_ath);
    cudaGetSymbolAddress((void**)&atl, g_atl);
    cudaGetSymbolAddress((void**)&wqh, g_wqh);
    cudaGetSymbolAddress((void**)&wql, g_wql);
    cudaGetSymbolAddress((void**)&wkh, g_wkh);
    cudaGetSymbolAddress((void**)&wkl, g_wkl);
    cudaGetSymbolAddress((void**)&wvh, g_wvh);
    cudaGetSymbolAddress((void**)&wvl, g_wvl);
    cudaGetSymbolAddress((void**)&woh, g_woh);
    cudaGetSymbolAddress((void**)&wol, g_wol);

    cudaFuncSetAttribute(gemm_qkv, cudaFuncAttributeMaxDynamicSharedMemorySize, GEMM_SMEM);
    cudaFuncSetAttribute(gemm_out64, cudaFuncAttributeMaxDynamicSharedMemorySize, GEMM64_SMEM);
    cudaFuncSetAttribute(attn_mma, cudaFuncAttributeMaxDynamicSharedMemorySize, ATT_SMEM);

    const int xn4 = T * C_DIM / 4;
    const int wn4 = C_DIM * C_DIM / 4;
    const int total = xn4 + 4 * wn4;
    split_all_tiled<<<(total + 255) / 256, 256>>>(
        (const float4*)x,
        (const float4*)Wq, (const float4*)Wk, (const float4*)Wv, (const float4*)Wo,
        xh, xl, wqh, wql, wkh, wkl, wvh, wvl, woh, wol, xn4, wn4);

    dim3 qkv_grid(C_DIM / 128, (T + 127) / 128, 3);
    gemm_qkv<<<qkv_grid, 256, GEMM_SMEM>>>(xh, xl,
                                           wqh, wql, bq,
                                           wkh, wkl, bk,
                                           wvh, wvl, bv,
                                           qn, kn,
                                           qh, ql, kh, kl, vh, vl, T);

    dim3 attn_grid(nseq, NH, LMAX / 128);
    attn_mma<<<attn_grid, 256, ATT_SMEM>>>(cu);

    dim3 ogrid(C_DIM / 128, (T + 63) / 64);
    gemm_out64<<<ogrid, 256, GEMM64_SMEM>>>(ath, atl, woh, wol, bo, out, T);
}

// round 12
// speedup vs baseline: 1.6085x; 1.0151x over previous
#include <cuda_runtime.h>
#include <cuda_bf16.h>
#include <cstdint>

#define C_DIM 1024
#define NH 16
#define HD 64
#define MAX_T 8192
#define LMAX 1024
#define EPS_RMS 1.1920929e-07f

typedef __nv_bfloat16 bf16;

// ---------------- scratch (device globals; allocation-free rule) ----------
// linear layouts (attention operands)
__device__ bf16 g_qh[MAX_T * C_DIM];
__device__ bf16 g_ql[MAX_T * C_DIM];
__device__ bf16 g_kh2[MAX_T * C_DIM];
__device__ bf16 g_kl2[MAX_T * C_DIM];
__device__ bf16 g_vh2[MAX_T * C_DIM];
__device__ bf16 g_vl2[MAX_T * C_DIM];

// tiled layouts (GEMM operands): [blk128][kblk32][128 rows x 40 elems]
#define TROW 40
#define TBLK_ELEMS (128 * TROW)       // 5120 elems
#define TBLK_BYTES (TBLK_ELEMS * 2)   // 10240 B
#define NKB (C_DIM / 32)              // 32 k-blocks
__device__ bf16 g_xh[(MAX_T / 128) * NKB * TBLK_ELEMS];
__device__ bf16 g_xl[(MAX_T / 128) * NKB * TBLK_ELEMS];
__device__ bf16 g_ath[(MAX_T / 128) * NKB * TBLK_ELEMS];
__device__ bf16 g_atl[(MAX_T / 128) * NKB * TBLK_ELEMS];
__device__ bf16 g_wqh[8 * NKB * TBLK_ELEMS];
__device__ bf16 g_wql[8 * NKB * TBLK_ELEMS];
__device__ bf16 g_wkh[8 * NKB * TBLK_ELEMS];
__device__ bf16 g_wkl[8 * NKB * TBLK_ELEMS];
__device__ bf16 g_wvh[8 * NKB * TBLK_ELEMS];
__device__ bf16 g_wvl[8 * NKB * TBLK_ELEMS];
__device__ bf16 g_woh[8 * NKB * TBLK_ELEMS];
__device__ bf16 g_wol[8 * NKB * TBLK_ELEMS];

// ---------------- helpers ---------------------------------------------
__device__ __forceinline__ uint32_t smem_u32(const void* p) {
    uint32_t a;
    asm("{ .reg .u64 t; cvta.to.shared.u64 t, %1; cvt.u32.u64 %0, t; }"
        : "=r"(a) : "l"(p));
    return a;
}

__device__ __forceinline__ size_t tiled_off(int r, int c) {
    return ((size_t)((r >> 7) * NKB + (c >> 5))) * TBLK_ELEMS +
           (size_t)((r & 127) * TROW + (c & 31));
}

#define LDSM_X4(r0, r1, r2, r3, addr) \
    asm volatile("ldmatrix.sync.aligned.m8n8.x4.shared.b16 {%0,%1,%2,%3}, [%4];" \
                 : "=r"(r0), "=r"(r1), "=r"(r2), "=r"(r3) : "r"(addr))

#define LDSM_X4_T(r0, r1, r2, r3, addr) \
    asm volatile("ldmatrix.sync.aligned.m8n8.x4.trans.shared.b16 {%0,%1,%2,%3}, [%4];" \
                 : "=r"(r0), "=r"(r1), "=r"(r2), "=r"(r3) : "r"(addr))

#define MMA16816(d, a, b) \
    asm volatile("mma.sync.aligned.m16n8k16.row.col.f32.bf16.bf16.f32 " \
                 "{%0,%1,%2,%3}, {%4,%5,%6,%7}, {%8,%9}, {%0,%1,%2,%3};" \
                 : "+f"((d)[0]), "+f"((d)[1]), "+f"((d)[2]), "+f"((d)[3]) \
                 : "r"((a)[0]), "r"((a)[1]), "r"((a)[2]), "r"((a)[3]), \
                   "r"((b)[0]), "r"((b)[1]))

#define CP_ASYNC16(dst, src) \
    asm volatile("cp.async.cg.shared.global [%0], [%1], 16;" :: "r"(dst), "l"(src))
#define CP_COMMIT() asm volatile("cp.async.commit_group;" ::: "memory")
#define CP_WAIT(n)  asm volatile("cp.async.wait_group %0;" :: "n"(n) : "memory")

#define MBAR_INIT(a, cnt) \
    asm volatile("mbarrier.init.shared.b64 [%0], %1;" :: "r"(a), "r"(cnt) : "memory")
#define MBAR_EXPECT_TX(a, bytes) \
    asm volatile("mbarrier.arrive.expect_tx.shared.b64 _, [%0], %1;" \
                 :: "r"(a), "r"(bytes) : "memory")
#define BULK_G2S(dst, src, bytes, mbar) \
    asm volatile("cp.async.bulk.shared::cta.global.mbarrier::complete_tx::bytes " \
                 "[%0], [%1], %2, [%3];" \
                 :: "r"(dst), "l"(src), "r"(bytes), "r"(mbar) : "memory")

__device__ __forceinline__ void mbar_wait(uint32_t a, int phase) {
    asm volatile(
        "{ .reg .pred P;\n"
        "WL%=:\n"
        " mbarrier.try_wait.parity.acquire.cta.shared::cta.b64 P, [%0], %1, 0x989680;\n"
        " @P bra WD%=;\n"
        " bra WL%=;\n"
        "WD%=: }"
        :: "r"(a), "r"(phase) : "memory");
}

__device__ __forceinline__ void split2(float x, float y, uint32_t& h, uint32_t& l) {
    bf16 hx = __float2bfloat16(x);
    bf16 hy = __float2bfloat16(y);
    __nv_bfloat162 H; H.x = hx; H.y = hy;
    __nv_bfloat162 L;
    L.x = __float2bfloat16(x - __bfloat162float(hx));
    L.y = __float2bfloat16(y - __bfloat162float(hy));
    h = *(uint32_t*)&H;
    l = *(uint32_t*)&L;
}

// ---------------------------------------------------------------------------
// fused fp32 -> (hi,lo) split into TILED layout: x + 4 weight matrices
// ---------------------------------------------------------------------------
__global__ __launch_bounds__(256) void split_all_tiled(
    const float4* __restrict__ x,
    const float4* __restrict__ w0, const float4* __restrict__ w1,
    const float4* __restrict__ w2, const float4* __restrict__ w3,
    bf16* __restrict__ xh, bf16* __restrict__ xl,
    bf16* __restrict__ h0p, bf16* __restrict__ l0p,
    bf16* __restrict__ h1p, bf16* __restrict__ l1p,
    bf16* __restrict__ h2p, bf16* __restrict__ l2p,
    bf16* __restrict__ h3p, bf16* __restrict__ l3p,
    int xn4, int wn4)
{
    int gid = blockIdx.x * blockDim.x + threadIdx.x;
    const float4* in; bf16 *hi, *lo; int i;
    if (gid < xn4) {
        in = x; hi = xh; lo = xl; i = gid;
    } else {
        int g = gid - xn4;
        int sel = g / wn4;
        if (sel >= 4) return;
        i = g - sel * wn4;
        if (sel == 0)      { in = w0; hi = h0p; lo = l0p; }
        else if (sel == 1) { in = w1; hi = h1p; lo = l1p; }
        else if (sel == 2) { in = w2; hi = h2p; lo = l2p; }
        else               { in = w3; hi = h3p; lo = l3p; }
    }
    float4 v = in[i];
    const int row = i >> 8;
    const int c = (i & 255) * 4;
    const size_t off = tiled_off(row, c);
    uint32_t a0, b0, a1, b1;
    split2(v.x, v.y, a0, b0);
    split2(v.z, v.w, a1, b1);
    *(uint2*)(hi + off) = make_uint2(a0, a1);
    *(uint2*)(lo + off) = make_uint2(b0, b1);
}

// ---------------------------------------------------------------------------
// bf16x3 GEMM: BM=128, BN=128, BK=32; 8 warps (4x2), warp tile 32x64;
// 2-stage bulk-copy double buffer; occupancy 2.
// EPI: 0 = fp32 C + bias; 1 = bias + split to linear hi/lo;
//      2 = bias + RMSNORM(warp's 64-col head span) + scale + split to hi/lo.
// ---------------------------------------------------------------------------
#define NKT NKB
#define SUBTILE_B TBLK_BYTES              // 10240
#define STAGE_BYTES (4 * SUBTILE_B)       // 40960 (Ah, Al, Bh, Bl)
#define GEMM_SMEM (128 + 2 * STAGE_BYTES) // 82048

template <int EPI>
__device__ __forceinline__ void gemm_core(
    const bf16* __restrict__ Ah, const bf16* __restrict__ Al,
    const bf16* __restrict__ Bh, const bf16* __restrict__ Bl,
    const float* __restrict__ bias, float* __restrict__ C,
    bf16* __restrict__ Oh, bf16* __restrict__ Ol,
    const float* __restrict__ nw, float nscale, int M,
    int mblk, int nblk, char* dsm)
{
    const uint32_t sbase = smem_u32(dsm);
    const uint32_t mb0 = sbase, mb1 = sbase + 8;
    const uint32_t tiles = sbase + 128;
    const int tid = threadIdx.x;
    const int wid = tid >> 5;
    const int lane = tid & 31;
    const int wm = wid & 3;
    const int wn = wid >> 2;

    float acc[2][8][4];
#pragma unroll
    for (int i = 0; i < 2; i++)
#pragma unroll
        for (int j = 0; j < 8; j++)
#pragma unroll
            for (int r = 0; r < 4; r++) acc[i][j][r] = 0.0f;

    if (tid == 0) { MBAR_INIT(mb0, 1); MBAR_INIT(mb1, 1); }
    __syncthreads();

    const size_t abase_blk = (size_t)mblk * NKB;
    const size_t bbase_blk = (size_t)nblk * NKB;

    auto issue = [&](int kt) {
        const int s = kt & 1;
        const uint32_t dst = tiles + s * STAGE_BYTES;
        const uint32_t m = s ? mb1 : mb0;
        MBAR_EXPECT_TX(m, (uint32_t)STAGE_BYTES);
        const size_t ao = (abase_blk + kt) * TBLK_ELEMS;
        const size_t bo = (bbase_blk + kt) * TBLK_ELEMS;
        BULK_G2S(dst,                  Ah + ao, (uint32_t)TBLK_BYTES, m);
        BULK_G2S(dst + SUBTILE_B,      Al + ao, (uint32_t)TBLK_BYTES, m);
        BULK_G2S(dst + 2 * SUBTILE_B,  Bh + bo, (uint32_t)TBLK_BYTES, m);
        BULK_G2S(dst + 3 * SUBTILE_B,  Bl + bo, (uint32_t)TBLK_BYTES, m);
    };
    if (tid == 0) { issue(0); issue(1); }

    const int a_row = (lane & 15);
    const int a_col = (lane >> 4) * 8;
    const int b_row = (lane & 7) + ((lane >> 4) & 1) * 8;
    const int b_col = ((lane >> 3) & 1) * 8;

    int ph0 = 0, ph1 = 0;
    for (int kt = 0; kt < NKT; kt++) {
        const int s = kt & 1;
        if (s == 0) { mbar_wait(mb0, ph0); ph0 ^= 1; }
        else        { mbar_wait(mb1, ph1); ph1 ^= 1; }
        const uint32_t st = tiles + s * STAGE_BYTES;

#pragma unroll
        for (int ph = 0; ph < 2; ph++) {
            const int koff = ph * 16;
            uint32_t af[2][2][4];
#pragma unroll
            for (int prod = 0; prod < 2; prod++) {
                const uint32_t abase = st + prod * SUBTILE_B;
#pragma unroll
                for (int mf = 0; mf < 2; mf++) {
                    const uint32_t addr = abase +
                        (uint32_t)((wm * 32 + mf * 16 + a_row) * (TROW * 2) +
                                   (koff + a_col) * 2);
                    LDSM_X4(af[prod][mf][0], af[prod][mf][1],
                            af[prod][mf][2], af[prod][mf][3], addr);
                }
            }
#pragma unroll
            for (int np = 0; np < 4; np++) {
                const uint32_t boff =
                    (uint32_t)((wn * 64 + np * 16 + b_row) * (TROW * 2) +
                               (koff + b_col) * 2);
                uint32_t bh[4], bl[4];
                LDSM_X4(bh[0], bh[1], bh[2], bh[3], st + 2 * SUBTILE_B + boff);
                LDSM_X4(bl[0], bl[1], bl[2], bl[3], st + 3 * SUBTILE_B + boff);
                uint32_t bh0[2] = {bh[0], bh[1]}, bh1[2] = {bh[2], bh[3]};
                uint32_t bl0[2] = {bl[0], bl[1]}, bl1[2] = {bl[2], bl[3]};
#pragma unroll
                for (int mf = 0; mf < 2; mf++) {
                    MMA16816(acc[mf][np * 2],     af[0][mf], bh0);
                    MMA16816(acc[mf][np * 2],     af[0][mf], bl0);
                    MMA16816(acc[mf][np * 2],     af[1][mf], bh0);
                    MMA16816(acc[mf][np * 2 + 1], af[0][mf], bh1);
                    MMA16816(acc[mf][np * 2 + 1], af[0][mf], bl1);
                    MMA16816(acc[mf][np * 2 + 1], af[1][mf], bh1);
                }
            }
        }
        __syncthreads();
        if (kt + 2 < NKT && tid == 0) issue(kt + 2);
    }

    const int m0 = mblk * 128, n0 = nblk * 128;
    const int rbase = m0 + wm * 32 + (lane >> 2);
    const int cbase = n0 + wn * 64 + (lane & 3) * 2;
#pragma unroll
    for (int mf = 0; mf < 2; mf++) {
#pragma unroll
        for (int half = 0; half < 2; half++) {
            const int row = rbase + mf * 16 + half * 8;
            if (row >= M) continue;
            float v[8][2];
#pragma unroll
            for (int nf = 0; nf < 8; nf++) {
                const int col = cbase + nf * 8;
                v[nf][0] = acc[mf][nf][half * 2 + 0] + bias[col];
                v[nf][1] = acc[mf][nf][half * 2 + 1] + bias[col + 1];
            }
            if (EPI == 0) {
#pragma unroll
                for (int nf = 0; nf < 8; nf++) {
                    float2 o; o.x = v[nf][0]; o.y = v[nf][1];
                    *(float2*)(C + (size_t)row * C_DIM + cbase + nf * 8) = o;
                }
            } else if (EPI == 1) {
#pragma unroll
                for (int nf = 0; nf < 8; nf++) {
                    uint32_t h, l;
                    split2(v[nf][0], v[nf][1], h, l);
                    *(uint32_t*)(Oh + (size_t)row * C_DIM + cbase + nf * 8) = h;
                    *(uint32_t*)(Ol + (size_t)row * C_DIM + cbase + nf * 8) = l;
                }
            } else {
                float ss = 0.0f;
#pragma unroll
                for (int nf = 0; nf < 8; nf++)
                    ss += v[nf][0] * v[nf][0] + v[nf][1] * v[nf][1];
                ss += __shfl_xor_sync(0xffffffffu, ss, 1);
                ss += __shfl_xor_sync(0xffffffffu, ss, 2);
                const float r = rsqrtf(ss * (1.0f / HD) + EPS_RMS) * nscale;
                const int d0 = (lane & 3) * 2;
#pragma unroll
                for (int nf = 0; nf < 8; nf++) {
                    const int d = nf * 8 + d0;
                    uint32_t h, l;
                    split2(v[nf][0] * r * nw[d], v[nf][1] * r * nw[d + 1], h, l);
                    *(uint32_t*)(Oh + (size_t)row * C_DIM + cbase + nf * 8) = h;
                    *(uint32_t*)(Ol + (size_t)row * C_DIM + cbase + nf * 8) = l;
                }
            }
        }
    }
}

__global__ __launch_bounds__(256, 2)
void gemm_qkv(const bf16* __restrict__ xh, const bf16* __restrict__ xl,
              const bf16* __restrict__ wqh, const bf16* __restrict__ wql,
              const float* __restrict__ bq,
              const bf16* __restrict__ wkh, const bf16* __restrict__ wkl,
              const float* __restrict__ bk,
              const bf16* __restrict__ wvh, const bf16* __restrict__ wvl,
              const float* __restrict__ bv,
              const float* __restrict__ qn, const float* __restrict__ kn,
              bf16* __restrict__ qh, bf16* __restrict__ ql,
              bf16* __restrict__ kh, bf16* __restrict__ kl,
              bf16* __restrict__ vh, bf16* __restrict__ vl, int M)
{
    extern __shared__ char dsm[];
    const int z = blockIdx.z;
    if (z == 0) {
        gemm_core<2>(xh, xl, wqh, wql, bq, nullptr, qh, ql, qn, 0.125f, M,
                     blockIdx.y, blockIdx.x, dsm);
    } else if (z == 1) {
        gemm_core<2>(xh, xl, wkh, wkl, bk, nullptr, kh, kl, kn, 1.0f, M,
                     blockIdx.y, blockIdx.x, dsm);
    } else {
        gemm_core<1>(xh, xl, wvh, wvl, bv, nullptr, vh, vl, nullptr, 0.f, M,
                     blockIdx.y, blockIdx.x, dsm);
    }
}

// ---------------------------------------------------------------------------
// Output-projection GEMM, BM=64 variant
// ---------------------------------------------------------------------------
#define AHALF_B (64 * TROW * 2)            // 5120
#define STAGE64 (2 * AHALF_B + 2 * TBLK_BYTES)  // 30720
#define GEMM64_SMEM (128 + 2 * STAGE64)    // 61568

__global__ __launch_bounds__(256, 2)
void gemm_out64(const bf16* __restrict__ Ah, const bf16* __restrict__ Al,
                const bf16* __restrict__ Bh, const bf16* __restrict__ Bl,
                const float* __restrict__ bias, float* __restrict__ C, int M)
{
    extern __shared__ char dsm[];
    const uint32_t sbase = smem_u32(dsm);
    const uint32_t mb0 = sbase, mb1 = sbase + 8;
    const uint32_t tiles = sbase + 128;
    const int tid = threadIdx.x;
    const int wid = tid >> 5;
    const int lane = tid & 31;
    const int wm = wid & 3;
    const int wn = wid >> 2;
    const int mblk = blockIdx.y;
    const int nblk = blockIdx.x;
    const int ablk = mblk >> 1, ahalf = mblk & 1;

    float acc[8][4];
#pragma unroll
    for (int j = 0; j < 8; j++)
#pragma unroll
        for (int r = 0; r < 4; r++) acc[j][r] = 0.0f;

    if (tid == 0) { MBAR_INIT(mb0, 1); MBAR_INIT(mb1, 1); }
    __syncthreads();

    const size_t abase_blk = (size_t)ablk * NKB;
    const size_t bbase_blk = (size_t)nblk * NKB;

    auto issue = [&](int kt) {
        const int s = kt & 1;
        const uint32_t dst = tiles + s * STAGE64;
        const uint32_t m = s ? mb1 : mb0;
        MBAR_EXPECT_TX(m, (uint32_t)STAGE64);
        const size_t ao = (abase_blk + kt) * TBLK_ELEMS + (size_t)ahalf * (64 * TROW);
        const size_t bo = (bbase_blk + kt) * TBLK_ELEMS;
        BULK_G2S(dst,                        Ah + ao, (uint32_t)AHALF_B, m);
        BULK_G2S(dst + AHALF_B,              Al + ao, (uint32_t)AHALF_B, m);
        BULK_G2S(dst + 2 * AHALF_B,               Bh + bo, (uint32_t)TBLK_BYTES, m);
        BULK_G2S(dst + 2 * AHALF_B + TBLK_BYTES,  Bl + bo, (uint32_t)TBLK_BYTES, m);
    };
    if (tid == 0) { issue(0); issue(1); }

    const int a_row = (lane & 15);
    const int a_col = (lane >> 4) * 8;
    const int b_row = (lane & 7) + ((lane >> 4) & 1) * 8;
    const int b_col = ((lane >> 3) & 1) * 8;

    int ph0 = 0, ph1 = 0;
    for (int kt = 0; kt < NKT; kt++) {
        const int s = kt & 1;
        if (s == 0) { mbar_wait(mb0, ph0); ph0 ^= 1; }
        else        { mbar_wait(mb1, ph1); ph1 ^= 1; }
        const uint32_t st = tiles + s * STAGE64;

#pragma unroll
        for (int ph = 0; ph < 2; ph++) {
            const int koff = ph * 16;
            uint32_t af[2][4];
#pragma unroll
            for (int prod = 0; prod < 2; prod++) {
                const uint32_t addr = st + prod * AHALF_B +
                    (uint32_t)((wm * 16 + a_row) * (TROW * 2) + (koff + a_col) * 2);
                LDSM_X4(af[prod][0], af[prod][1], af[prod][2], af[prod][3], addr);
            }
#pragma unroll
            for (int np = 0; np < 4; np++) {
                const uint32_t boff =
                    (uint32_t)((wn * 64 + np * 16 + b_row) * (TROW * 2) +
                               (koff + b_col) * 2);
                uint32_t bh[4], bl[4];
                LDSM_X4(bh[0], bh[1], bh[2], bh[3], st + 2 * AHALF_B + boff);
                LDSM_X4(bl[0], bl[1], bl[2], bl[3], st + 2 * AHALF_B + TBLK_BYTES + boff);
                uint32_t bh0[2] = {bh[0], bh[1]}, bh1[2] = {bh[2], bh[3]};
                uint32_t bl0[2] = {bl[0], bl[1]}, bl1[2] = {bl[2], bl[3]};
                MMA16816(acc[np * 2],     af[0], bh0);
                MMA16816(acc[np * 2],     af[0], bl0);
                MMA16816(acc[np * 2],     af[1], bh0);
                MMA16816(acc[np * 2 + 1], af[0], bh1);
                MMA16816(acc[np * 2 + 1], af[0], bl1);
                MMA16816(acc[np * 2 + 1], af[1], bh1);
            }
        }
        __syncthreads();
        if (kt + 2 < NKT && tid == 0) issue(kt + 2);
    }

    const int m0 = mblk * 64, n0 = nblk * 128;
    const int rbase = m0 + wm * 16 + (lane >> 2);
    const int cbase = n0 + wn * 64 + (lane & 3) * 2;
#pragma unroll
    for (int half = 0; half < 2; half++) {
        const int row = rbase + half * 8;
        if (row >= M) continue;
#pragma unroll
        for (int nf = 0; nf < 8; nf++) {
            const int col = cbase + nf * 8;
            float2 o;
            o.x = acc[nf][half * 2 + 0] + bias[col];
            o.y = acc[nf][half * 2 + 1] + bias[col + 1];
            *(float2*)(C + (size_t)row * C_DIM + col) = o;
        }
    }
}

// ---------------------------------------------------------------------------
// Tensorized varlen attention (bf16x3). Fixed-shift softmax: scores provably
// bounded |s|<=8 (rmsnorm'd q scaled by 1/8, rmsnorm'd k, unit norm weights),
// so p = exp(s-8) needs no online max / rescaling.
// 256 thr, occ 2, 128 queries/block, 2-stage K/V pipeline. TILED output.
// ---------------------------------------------------------------------------
#define KSTRIDE_B 144
#define ARR_B (64 * KSTRIDE_B)
#define ATT_STAGE (4 * ARR_B)
#define ATT_SMEM (2 * ATT_STAGE)

__global__ __launch_bounds__(256, 2) void attn_mma(const int* __restrict__ cu)
{
    const int seq = blockIdx.x;
    const int head = blockIdx.y;
    const int s0 = cu[seq];
    const int L = cu[seq + 1] - s0;
    const int q0 = blockIdx.z * 128;
    if (q0 >= L) return;

    extern __shared__ char sm[];
    const uint32_t sb = smem_u32(sm);
    const int tid = threadIdx.x;
    const int wid = tid >> 5;
    const int lane = tid & 31;
    const int colh = head * HD;

    uint32_t aQh[4][4], aQl[4][4];
    {
        int r0 = q0 + wid * 16 + (lane >> 2);
        int r1 = r0 + 8;
        if (r0 >= L) r0 = L - 1;
        if (r1 >= L) r1 = L - 1;
        const size_t b0 = (size_t)(s0 + r0) * C_DIM + colh + (lane & 3) * 2;
        const size_t b1 = (size_t)(s0 + r1) * C_DIM + colh + (lane & 3) * 2;
#pragma unroll
        for (int kc = 0; kc < 4; kc++) {
            aQh[kc][0] = *(const uint32_t*)(g_qh + b0 + kc * 16);
            aQh[kc][1] = *(const uint32_t*)(g_qh + b1 + kc * 16);
            aQh[kc][2] = *(const uint32_t*)(g_qh + b0 + kc * 16 + 8);
            aQh[kc][3] = *(const uint32_t*)(g_qh + b1 + kc * 16 + 8);
            aQl[kc][0] = *(const uint32_t*)(g_ql + b0 + kc * 16);
            aQl[kc][1] = *(const uint32_t*)(g_ql + b1 + kc * 16);
            aQl[kc][2] = *(const uint32_t*)(g_ql + b0 + kc * 16 + 8);
            aQl[kc][3] = *(const uint32_t*)(g_ql + b1 + kc * 16 + 8);
        }
    }

    float o[8][4];
#pragma unroll
    for (int i = 0; i < 8; i++)
#pragma unroll
        for (int j = 0; j < 4; j++) o[i][j] = 0.0f;
    float l0 = 0.0f, l1 = 0.0f;

    const int ntiles = (L + 63) >> 6;

    auto load_tile = [&](int t) {
        const uint32_t st = sb + (t & 1) * ATT_STAGE;
        const int kb = t * 64;
        const bf16* srcs[4] = {g_kh2, g_kl2, g_vh2, g_vl2};
#pragma unroll
        for (int i = 0; i < 8; i++) {
            int c = tid + i * 256;
            int arr = c >> 9;
            int r = (c >> 3) & 63;
            int cc = c & 7;
            int key = kb + r;
            if (key >= L) key = L - 1;
            const void* g = srcs[arr] + (size_t)(s0 + key) * C_DIM + colh + cc * 8;
            CP_ASYNC16(st + arr * ARR_B + r * KSTRIDE_B + cc * 16, g);
        }
    };

    load_tile(0);
    CP_COMMIT();

    for (int t = 0; t < ntiles; t++) {
        if (t + 1 < ntiles) { load_tile(t + 1); CP_COMMIT(); CP_WAIT(1); }
        else { CP_WAIT(0); }
        __syncthreads();
        const uint32_t st = sb + (t & 1) * ATT_STAGE;
        const int kb = t * 64;

        float s[8][4];
#pragma unroll
        for (int i = 0; i < 8; i++)
#pragma unroll
            for (int j = 0; j < 4; j++) s[i][j] = 0.0f;

        const int mat = lane >> 3;
#pragma unroll
        for (int kc = 0; kc < 4; kc++) {
#pragma unroll
            for (int pair = 0; pair < 4; pair++) {
                const int krow = (pair * 2 + (mat >> 1)) * 8 + (lane & 7);
                const uint32_t cb = (uint32_t)(kc * 32 + (mat & 1) * 16);
                uint32_t kh[4], kl[4];
                LDSM_X4(kh[0], kh[1], kh[2], kh[3], st + 0     + krow * KSTRIDE_B + cb);
                LDSM_X4(kl[0], kl[1], kl[2], kl[3], st + ARR_B + krow * KSTRIDE_B + cb);
                uint32_t bh0[2] = {kh[0], kh[1]}, bh1[2] = {kh[2], kh[3]};
                uint32_t bl0[2] = {kl[0], kl[1]}, bl1[2] = {kl[2], kl[3]};
                MMA16816(s[pair * 2],     aQh[kc], bh0);
                MMA16816(s[pair * 2],     aQh[kc], bl0);
                MMA16816(s[pair * 2],     aQl[kc], bh0);
                MMA16816(s[pair * 2 + 1], aQh[kc], bh1);
                MMA16816(s[pair * 2 + 1], aQh[kc], bl1);
                MMA16816(s[pair * 2 + 1], aQl[kc], bh1);
            }
        }

        // fixed-shift softmax: p = exp(s - 8); masked -> exp(-inf) = 0
        const int cb0 = (lane & 3) * 2;
#pragma unroll
        for (int nf = 0; nf < 8; nf++) {
            int colk = kb + nf * 8 + cb0;
            if (colk >= L)     { s[nf][0] = -1e30f; s[nf][2] = -1e30f; }
            if (colk + 1 >= L) { s[nf][1] = -1e30f; s[nf][3] = -1e30f; }
        }
#pragma unroll
        for (int nf = 0; nf < 8; nf++) {
            s[nf][0] = __expf(s[nf][0] - 8.0f);
            s[nf][1] = __expf(s[nf][1] - 8.0f);
            s[nf][2] = __expf(s[nf][2] - 8.0f);
            s[nf][3] = __expf(s[nf][3] - 8.0f);
            l0 += s[nf][0] + s[nf][1];
            l1 += s[nf][2] + s[nf][3];
        }

#pragma unroll
        for (int j = 0; j < 4; j++) {
            uint32_t ph[4], pl[4];
            split2(s[2 * j][0], s[2 * j][1], ph[0], pl[0]);
            split2(s[2 * j][2], s[2 * j][3], ph[1], pl[1]);
            split2(s[2 * j + 1][0], s[2 * j + 1][1], ph[2], pl[2]);
            split2(s[2 * j + 1][2], s[2 * j + 1][3], ph[3], pl[3]);
            const uint32_t vrow = (uint32_t)((j * 16 + (lane & 15)) * KSTRIDE_B +
                                             ((lane >> 4) << 3) * 2);
#pragma unroll
            for (int vp = 0; vp < 4; vp++) {
                const uint32_t addr = st + 2 * ARR_B + vrow + (uint32_t)(vp * 32);
                uint32_t vh[4], vl[4];
                LDSM_X4_T(vh[0], vh[1], vh[2], vh[3], addr);
                LDSM_X4_T(vl[0], vl[1], vl[2], vl[3], addr + ARR_B);
                uint32_t bh0[2] = {vh[0], vh[1]}, bh1[2] = {vh[2], vh[3]};
                uint32_t bl0[2] = {vl[0], vl[1]}, bl1[2] = {vl[2], vl[3]};
                MMA16816(o[vp * 2],     ph, bh0);
                MMA16816(o[vp * 2],     pl, bh0);
                MMA16816(o[vp * 2],     ph, bl0);
                MMA16816(o[vp * 2 + 1], ph, bh1);
                MMA16816(o[vp * 2 + 1], pl, bh1);
                MMA16816(o[vp * 2 + 1], ph, bl1);
            }
        }
        __syncthreads();
    }

    l0 += __shfl_xor_sync(0xffffffffu, l0, 1);
    l0 += __shfl_xor_sync(0xffffffffu, l0, 2);
    l1 += __shfl_xor_sync(0xffffffffu, l1, 1);
    l1 += __shfl_xor_sync(0xffffffffu, l1, 2);
    const float inv0 = 1.0f / l0;
    const float inv1 = 1.0f / l1;
    const int r0 = q0 + wid * 16 + (lane >> 2);
    const int r1 = r0 + 8;
#pragma unroll
    for (int nf = 0; nf < 8; nf++) {
        const int col = colh + nf * 8 + (lane & 3) * 2;
        if (r0 < L) {
            uint32_t h, l;
            split2(o[nf][0] * inv0, o[nf][1] * inv0, h, l);
            const size_t off = tiled_off(s0 + r0, col);
            *(uint32_t*)(g_ath + off) = h;
            *(uint32_t*)(g_atl + off) = l;
        }
        if (r1 < L) {
            uint32_t h, l;
            split2(o[nf][2] * inv1, o[nf][3] * inv1, h, l);
            const size_t off = tiled_off(s0 + r1, col);
            *(uint32_t*)(g_ath + off) = h;
            *(uint32_t*)(g_atl + off) = l;
        }
    }
}

// ---------------------------------------------------------------------------
// Launch
// ---------------------------------------------------------------------------
extern "C" void kernel_launch(void* const* d_in, const int* in_sizes, int n_in,
                              void* d_out, int out_size)
{
    const float* x  = (const float*)d_in[0];
    const int* cu   = (const int*)d_in[1];
    const float* Wq = (const float*)d_in[2];
    const float* bq = (const float*)d_in[3];
    const float* Wk = (const float*)d_in[4];
    const float* bk = (const float*)d_in[5];
    const float* Wv = (const float*)d_in[6];
    const float* bv = (const float*)d_in[7];
    const float* qn = (const float*)d_in[8];
    const float* kn = (const float*)d_in[9];
    const float* Wo = (const float*)d_in[10];
    const float* bo = (const float*)d_in[11];
    float* out = (float*)d_out;

    const int T = in_sizes[0] / C_DIM;
    const int nseq = in_sizes[1] - 1;

    bf16 *xh, *xl, *qh, *ql, *kh, *kl, *vh, *vl, *ath, *atl;
    bf16 *wqh, *wql, *wkh, *wkl, *wvh, *wvl, *woh, *wol;
    cudaGetSymbolAddress((void**)&xh, g_xh);
    cudaGetSymbolAddress((void**)&xl, g_xl);
    cudaGetSymbolAddress((void**)&qh, g_qh);
    cudaGetSymbolAddress((void**)&ql, g_ql);
    cudaGetSymbolAddress((void**)&kh, g_kh2);
    cudaGetSymbolAddress((void**)&kl, g_kl2);
    cudaGetSymbolAddress((void**)&vh, g_vh2);
    cudaGetSymbolAddress((void**)&vl, g_vl2);
    cudaGetSymbolAddress((void**)&ath, g_ath);
    cudaGetSymbolAddress((void**)&atl, g_atl);
    cudaGetSymbolAddress((void**)&wqh, g_wqh);
    cudaGetSymbolAddress((void**)&wql, g_wql);
    cudaGetSymbolAddress((void**)&wkh, g_wkh);
    cudaGetSymbolAddress((void**)&wkl, g_wkl);
    cudaGetSymbolAddress((void**)&wvh, g_wvh);
    cudaGetSymbolAddress((void**)&wvl, g_wvl);
    cudaGetSymbolAddress((void**)&woh, g_woh);
    cudaGetSymbolAddress((void**)&wol, g_wol);

    cudaFuncSetAttribute(gemm_qkv, cudaFuncAttributeMaxDynamicSharedMemorySize, GEMM_SMEM);
    cudaFuncSetAttribute(gemm_out64, cudaFuncAttributeMaxDynamicSharedMemorySize, GEMM64_SMEM);
    cudaFuncSetAttribute(attn_mma, cudaFuncAttributeMaxDynamicSharedMemorySize, ATT_SMEM);

    const int xn4 = T * C_DIM / 4;
    const int wn4 = C_DIM * C_DIM / 4;
    const int total = xn4 + 4 * wn4;
    split_all_tiled<<<(total + 255) / 256, 256>>>(
        (const float4*)x,
        (const float4*)Wq, (const float4*)Wk, (const float4*)Wv, (const float4*)Wo,
        xh, xl, wqh, wql, wkh, wkl, wvh, wvl, woh, wol, xn4, wn4);

    dim3 qkv_grid(C_DIM / 128, (T + 127) / 128, 3);
    gemm_qkv<<<qkv_grid, 256, GEMM_SMEM>>>(xh, xl,
                                           wqh, wql, bq,
                                           wkh, wkl, bk,
                                           wvh, wvl, bv,
                                           qn, kn,
                                           qh, ql, kh, kl, vh, vl, T);

    dim3 attn_grid(nseq, NH, LMAX / 128);
    attn_mma<<<attn_grid, 256, ATT_SMEM>>>(cu);

    dim3 ogrid(C_DIM / 128, (T + 63) / 64);
    gemm_out64<<<ogrid, 256, GEMM64_SMEM>>>(ath, atl, woh, wol, bo, out, T);
}

// round 13
// speedup vs baseline: 1.6495x; 1.0255x over previous
#include <cuda_runtime.h>
#include <cuda_bf16.h>
#include <cstdint>

#define C_DIM 1024
#define NH 16
#define HD 64
#define MAX_T 8192
#define LMAX 1024
#define EPS_RMS 1.1920929e-07f

typedef __nv_bfloat16 bf16;

// ---------------- scratch (device globals; allocation-free rule) ----------
// Q: linear layout (per-thread register loads in attention)
__device__ bf16 g_qh[MAX_T * C_DIM];
__device__ bf16 g_ql[MAX_T * C_DIM];

// K/V: head-major padded-tile layout [head][tile64][64 rows x 72 elems]
// one (head, tile) block = 64*72 elems = 9216 B contiguous (bulk-copyable),
// 144B row stride keeps ldmatrix conflict-free.
#define HM_ROW 72
#define HM_TILE_ELEMS (64 * HM_ROW)            // 4608
#define HM_TILE_BYTES (HM_TILE_ELEMS * 2)      // 9216
#define NT64 (MAX_T / 64)                      // 128
__device__ bf16 g_khm[NH * NT64 * HM_TILE_ELEMS];
__device__ bf16 g_klm[NH * NT64 * HM_TILE_ELEMS];
__device__ bf16 g_vhm[NH * NT64 * HM_TILE_ELEMS];
__device__ bf16 g_vlm[NH * NT64 * HM_TILE_ELEMS];

// tiled layouts (GEMM operands): [blk128][kblk32][128 rows x 40 elems]
#define TROW 40
#define TBLK_ELEMS (128 * TROW)       // 5120 elems
#define TBLK_BYTES (TBLK_ELEMS * 2)   // 10240 B
#define NKB (C_DIM / 32)              // 32 k-blocks
__device__ bf16 g_xh[(MAX_T / 128) * NKB * TBLK_ELEMS];
__device__ bf16 g_xl[(MAX_T / 128) * NKB * TBLK_ELEMS];
__device__ bf16 g_ath[(MAX_T / 128) * NKB * TBLK_ELEMS];
__device__ bf16 g_atl[(MAX_T / 128) * NKB * TBLK_ELEMS];
__device__ bf16 g_wqh[8 * NKB * TBLK_ELEMS];
__device__ bf16 g_wql[8 * NKB * TBLK_ELEMS];
__device__ bf16 g_wkh[8 * NKB * TBLK_ELEMS];
__device__ bf16 g_wkl[8 * NKB * TBLK_ELEMS];
__device__ bf16 g_wvh[8 * NKB * TBLK_ELEMS];
__device__ bf16 g_wvl[8 * NKB * TBLK_ELEMS];
__device__ bf16 g_woh[8 * NKB * TBLK_ELEMS];
__device__ bf16 g_wol[8 * NKB * TBLK_ELEMS];

// ---------------- helpers ---------------------------------------------
__device__ __forceinline__ uint32_t smem_u32(const void* p) {
    uint32_t a;
    asm("{ .reg .u64 t; cvta.to.shared.u64 t, %1; cvt.u32.u64 %0, t; }"
        : "=r"(a) : "l"(p));
    return a;
}

__device__ __forceinline__ size_t tiled_off(int r, int c) {
    return ((size_t)((r >> 7) * NKB + (c >> 5))) * TBLK_ELEMS +
           (size_t)((r & 127) * TROW + (c & 31));
}

// head-major padded-tile offset for (token row, channel col)
__device__ __forceinline__ size_t hm_off(int row, int col) {
    const int head = col >> 6;
    const int d = col & 63;
    return ((size_t)(head * NT64 + (row >> 6)) * 64 + (row & 63)) * HM_ROW + d;
}

#define LDSM_X4(r0, r1, r2, r3, addr) \
    asm volatile("ldmatrix.sync.aligned.m8n8.x4.shared.b16 {%0,%1,%2,%3}, [%4];" \
                 : "=r"(r0), "=r"(r1), "=r"(r2), "=r"(r3) : "r"(addr))

#define LDSM_X4_T(r0, r1, r2, r3, addr) \
    asm volatile("ldmatrix.sync.aligned.m8n8.x4.trans.shared.b16 {%0,%1,%2,%3}, [%4];" \
                 : "=r"(r0), "=r"(r1), "=r"(r2), "=r"(r3) : "r"(addr))

#define MMA16816(d, a, b) \
    asm volatile("mma.sync.aligned.m16n8k16.row.col.f32.bf16.bf16.f32 " \
                 "{%0,%1,%2,%3}, {%4,%5,%6,%7}, {%8,%9}, {%0,%1,%2,%3};" \
                 : "+f"((d)[0]), "+f"((d)[1]), "+f"((d)[2]), "+f"((d)[3]) \
                 : "r"((a)[0]), "r"((a)[1]), "r"((a)[2]), "r"((a)[3]), \
                   "r"((b)[0]), "r"((b)[1]))

#define MBAR_INIT(a, cnt) \
    asm volatile("mbarrier.init.shared.b64 [%0], %1;" :: "r"(a), "r"(cnt) : "memory")
#define MBAR_EXPECT_TX(a, bytes) \
    asm volatile("mbarrier.arrive.expect_tx.shared.b64 _, [%0], %1;" \
                 :: "r"(a), "r"(bytes) : "memory")
#define BULK_G2S(dst, src, bytes, mbar) \
    asm volatile("cp.async.bulk.shared::cta.global.mbarrier::complete_tx::bytes " \
                 "[%0], [%1], %2, [%3];" \
                 :: "r"(dst), "l"(src), "r"(bytes), "r"(mbar) : "memory")

__device__ __forceinline__ void mbar_wait(uint32_t a, int phase) {
    asm volatile(
        "{ .reg .pred P;\n"
        "WL%=:\n"
        " mbarrier.try_wait.parity.acquire.cta.shared::cta.b64 P, [%0], %1, 0x989680;\n"
        " @P bra WD%=;\n"
        " bra WL%=;\n"
        "WD%=: }"
        :: "r"(a), "r"(phase) : "memory");
}

__device__ __forceinline__ void split2(float x, float y, uint32_t& h, uint32_t& l) {
    bf16 hx = __float2bfloat16(x);
    bf16 hy = __float2bfloat16(y);
    __nv_bfloat162 H; H.x = hx; H.y = hy;
    __nv_bfloat162 L;
    L.x = __float2bfloat16(x - __bfloat162float(hx));
    L.y = __float2bfloat16(y - __bfloat162float(hy));
    h = *(uint32_t*)&H;
    l = *(uint32_t*)&L;
}

// ---------------------------------------------------------------------------
// fused fp32 -> (hi,lo) split into TILED layout: x + 4 weight matrices
// ---------------------------------------------------------------------------
__global__ __launch_bounds__(256) void split_all_tiled(
    const float4* __restrict__ x,
    const float4* __restrict__ w0, const float4* __restrict__ w1,
    const float4* __restrict__ w2, const float4* __restrict__ w3,
    bf16* __restrict__ xh, bf16* __restrict__ xl,
    bf16* __restrict__ h0p, bf16* __restrict__ l0p,
    bf16* __restrict__ h1p, bf16* __restrict__ l1p,
    bf16* __restrict__ h2p, bf16* __restrict__ l2p,
    bf16* __restrict__ h3p, bf16* __restrict__ l3p,
    int xn4, int wn4)
{
    int gid = blockIdx.x * blockDim.x + threadIdx.x;
    const float4* in; bf16 *hi, *lo; int i;
    if (gid < xn4) {
        in = x; hi = xh; lo = xl; i = gid;
    } else {
        int g = gid - xn4;
        int sel = g / wn4;
        if (sel >= 4) return;
        i = g - sel * wn4;
        if (sel == 0)      { in = w0; hi = h0p; lo = l0p; }
        else if (sel == 1) { in = w1; hi = h1p; lo = l1p; }
        else if (sel == 2) { in = w2; hi = h2p; lo = l2p; }
        else               { in = w3; hi = h3p; lo = l3p; }
    }
    float4 v = in[i];
    const int row = i >> 8;
    const int c = (i & 255) * 4;
    const size_t off = tiled_off(row, c);
    uint32_t a0, b0, a1, b1;
    split2(v.x, v.y, a0, b0);
    split2(v.z, v.w, a1, b1);
    *(uint2*)(hi + off) = make_uint2(a0, a1);
    *(uint2*)(lo + off) = make_uint2(b0, b1);
}

// ---------------------------------------------------------------------------
// bf16x3 GEMM: BM=128, BN=128, BK=32; 8 warps (4x2), warp tile 32x64;
// 2-stage bulk-copy double buffer; occupancy 2.
// EPI: 0 = fp32 C + bias
//      1 = bias + split -> HEAD-MAJOR hi/lo (V)
//      2 = bias + rmsnorm + scale + split -> LINEAR hi/lo (Q)
//      3 = bias + rmsnorm + scale + split -> HEAD-MAJOR hi/lo (K)
// ---------------------------------------------------------------------------
#define NKT NKB
#define SUBTILE_B TBLK_BYTES              // 10240
#define STAGE_BYTES (4 * SUBTILE_B)       // 40960 (Ah, Al, Bh, Bl)
#define GEMM_SMEM (128 + 2 * STAGE_BYTES) // 82048

template <int EPI>
__device__ __forceinline__ void gemm_core(
    const bf16* __restrict__ Ah, const bf16* __restrict__ Al,
    const bf16* __restrict__ Bh, const bf16* __restrict__ Bl,
    const float* __restrict__ bias, float* __restrict__ C,
    bf16* __restrict__ Oh, bf16* __restrict__ Ol,
    const float* __restrict__ nw, float nscale, int M,
    int mblk, int nblk, char* dsm)
{
    const uint32_t sbase = smem_u32(dsm);
    const uint32_t mb0 = sbase, mb1 = sbase + 8;
    const uint32_t tiles = sbase + 128;
    const int tid = threadIdx.x;
    const int wid = tid >> 5;
    const int lane = tid & 31;
    const int wm = wid & 3;
    const int wn = wid >> 2;

    float acc[2][8][4];
#pragma unroll
    for (int i = 0; i < 2; i++)
#pragma unroll
        for (int j = 0; j < 8; j++)
#pragma unroll
            for (int r = 0; r < 4; r++) acc[i][j][r] = 0.0f;

    if (tid == 0) { MBAR_INIT(mb0, 1); MBAR_INIT(mb1, 1); }
    __syncthreads();

    const size_t abase_blk = (size_t)mblk * NKB;
    const size_t bbase_blk = (size_t)nblk * NKB;

    auto issue = [&](int kt) {
        const int s = kt & 1;
        const uint32_t dst = tiles + s * STAGE_BYTES;
        const uint32_t m = s ? mb1 : mb0;
        MBAR_EXPECT_TX(m, (uint32_t)STAGE_BYTES);
        const size_t ao = (abase_blk + kt) * TBLK_ELEMS;
        const size_t bo = (bbase_blk + kt) * TBLK_ELEMS;
        BULK_G2S(dst,                  Ah + ao, (uint32_t)TBLK_BYTES, m);
        BULK_G2S(dst + SUBTILE_B,      Al + ao, (uint32_t)TBLK_BYTES, m);
        BULK_G2S(dst + 2 * SUBTILE_B,  Bh + bo, (uint32_t)TBLK_BYTES, m);
        BULK_G2S(dst + 3 * SUBTILE_B,  Bl + bo, (uint32_t)TBLK_BYTES, m);
    };
    if (tid == 0) { issue(0); issue(1); }

    const int a_row = (lane & 15);
    const int a_col = (lane >> 4) * 8;
    const int b_row = (lane & 7) + ((lane >> 4) & 1) * 8;
    const int b_col = ((lane >> 3) & 1) * 8;

    int ph0 = 0, ph1 = 0;
    for (int kt = 0; kt < NKT; kt++) {
        const int s = kt & 1;
        if (s == 0) { mbar_wait(mb0, ph0); ph0 ^= 1; }
        else        { mbar_wait(mb1, ph1); ph1 ^= 1; }
        const uint32_t st = tiles + s * STAGE_BYTES;

#pragma unroll
        for (int ph = 0; ph < 2; ph++) {
            const int koff = ph * 16;
            uint32_t af[2][2][4];
#pragma unroll
            for (int prod = 0; prod < 2; prod++) {
                const uint32_t abase = st + prod * SUBTILE_B;
#pragma unroll
                for (int mf = 0; mf < 2; mf++) {
                    const uint32_t addr = abase +
                        (uint32_t)((wm * 32 + mf * 16 + a_row) * (TROW * 2) +
                                   (koff + a_col) * 2);
                    LDSM_X4(af[prod][mf][0], af[prod][mf][1],
                            af[prod][mf][2], af[prod][mf][3], addr);
                }
            }
#pragma unroll
            for (int np = 0; np < 4; np++) {
                const uint32_t boff =
                    (uint32_t)((wn * 64 + np * 16 + b_row) * (TROW * 2) +
                               (koff + b_col) * 2);
                uint32_t bh[4], bl[4];
                LDSM_X4(bh[0], bh[1], bh[2], bh[3], st + 2 * SUBTILE_B + boff);
                LDSM_X4(bl[0], bl[1], bl[2], bl[3], st + 3 * SUBTILE_B + boff);
                uint32_t bh0[2] = {bh[0], bh[1]}, bh1[2] = {bh[2], bh[3]};
                uint32_t bl0[2] = {bl[0], bl[1]}, bl1[2] = {bl[2], bl[3]};
#pragma unroll
                for (int mf = 0; mf < 2; mf++) {
                    MMA16816(acc[mf][np * 2],     af[0][mf], bh0);
                    MMA16816(acc[mf][np * 2],     af[0][mf], bl0);
                    MMA16816(acc[mf][np * 2],     af[1][mf], bh0);
                    MMA16816(acc[mf][np * 2 + 1], af[0][mf], bh1);
                    MMA16816(acc[mf][np * 2 + 1], af[0][mf], bl1);
                    MMA16816(acc[mf][np * 2 + 1], af[1][mf], bh1);
                }
            }
        }
        __syncthreads();
        if (kt + 2 < NKT && tid == 0) issue(kt + 2);
    }

    const int m0 = mblk * 128, n0 = nblk * 128;
    const int rbase = m0 + wm * 32 + (lane >> 2);
    const int cbase = n0 + wn * 64 + (lane & 3) * 2;
#pragma unroll
    for (int mf = 0; mf < 2; mf++) {
#pragma unroll
        for (int half = 0; half < 2; half++) {
            const int row = rbase + mf * 16 + half * 8;
            if (row >= M) continue;
            float v[8][2];
#pragma unroll
            for (int nf = 0; nf < 8; nf++) {
                const int col = cbase + nf * 8;
                v[nf][0] = acc[mf][nf][half * 2 + 0] + bias[col];
                v[nf][1] = acc[mf][nf][half * 2 + 1] + bias[col + 1];
            }
            if (EPI == 0) {
#pragma unroll
                for (int nf = 0; nf < 8; nf++) {
                    float2 o; o.x = v[nf][0]; o.y = v[nf][1];
                    *(float2*)(C + (size_t)row * C_DIM + cbase + nf * 8) = o;
                }
            } else if (EPI == 1) {
#pragma unroll
                for (int nf = 0; nf < 8; nf++) {
                    uint32_t h, l;
                    split2(v[nf][0], v[nf][1], h, l);
                    const size_t off = hm_off(row, cbase + nf * 8);
                    *(uint32_t*)(Oh + off) = h;
                    *(uint32_t*)(Ol + off) = l;
                }
            } else {
                float ss = 0.0f;
#pragma unroll
                for (int nf = 0; nf < 8; nf++)
                    ss += v[nf][0] * v[nf][0] + v[nf][1] * v[nf][1];
                ss += __shfl_xor_sync(0xffffffffu, ss, 1);
                ss += __shfl_xor_sync(0xffffffffu, ss, 2);
                const float r = rsqrtf(ss * (1.0f / HD) + EPS_RMS) * nscale;
                const int d0 = (lane & 3) * 2;
#pragma unroll
                for (int nf = 0; nf < 8; nf++) {
                    const int d = nf * 8 + d0;
                    uint32_t h, l;
                    split2(v[nf][0] * r * nw[d], v[nf][1] * r * nw[d + 1], h, l);
                    if (EPI == 2) {
                        *(uint32_t*)(Oh + (size_t)row * C_DIM + cbase + nf * 8) = h;
                        *(uint32_t*)(Ol + (size_t)row * C_DIM + cbase + nf * 8) = l;
                    } else {
                        const size_t off = hm_off(row, cbase + nf * 8);
                        *(uint32_t*)(Oh + off) = h;
                        *(uint32_t*)(Ol + off) = l;
                    }
                }
            }
        }
    }
}

__global__ __launch_bounds__(256, 2)
void gemm_qkv(const bf16* __restrict__ xh, const bf16* __restrict__ xl,
              const bf16* __restrict__ wqh, const bf16* __restrict__ wql,
              const float* __restrict__ bq,
              const bf16* __restrict__ wkh, const bf16* __restrict__ wkl,
              const float* __restrict__ bk,
              const bf16* __restrict__ wvh, const bf16* __restrict__ wvl,
              const float* __restrict__ bv,
              const float* __restrict__ qn, const float* __restrict__ kn,
              bf16* __restrict__ qh, bf16* __restrict__ ql,
              bf16* __restrict__ kh, bf16* __restrict__ kl,
              bf16* __restrict__ vh, bf16* __restrict__ vl, int M)
{
    extern __shared__ char dsm[];
    const int z = blockIdx.z;
    if (z == 0) {
        gemm_core<2>(xh, xl, wqh, wql, bq, nullptr, qh, ql, qn, 0.125f, M,
                     blockIdx.y, blockIdx.x, dsm);
    } else if (z == 1) {
        gemm_core<3>(xh, xl, wkh, wkl, bk, nullptr, kh, kl, kn, 1.0f, M,
                     blockIdx.y, blockIdx.x, dsm);
    } else {
        gemm_core<1>(xh, xl, wvh, wvl, bv, nullptr, vh, vl, nullptr, 0.f, M,
                     blockIdx.y, blockIdx.x, dsm);
    }
}

// ---------------------------------------------------------------------------
// Output-projection GEMM, BM=64, 3-stage bulk pipeline, occupancy 2.
// ---------------------------------------------------------------------------
#define AHALF_B (64 * TROW * 2)            // 5120
#define STAGE64 (2 * AHALF_B + 2 * TBLK_BYTES)  // 30720
#define GEMM64_SMEM (128 + 3 * STAGE64)    // 92288

__global__ __launch_bounds__(256, 2)
void gemm_out64(const bf16* __restrict__ Ah, const bf16* __restrict__ Al,
                const bf16* __restrict__ Bh, const bf16* __restrict__ Bl,
                const float* __restrict__ bias, float* __restrict__ C, int M)
{
    extern __shared__ char dsm[];
    const uint32_t sbase = smem_u32(dsm);
    const uint32_t tiles = sbase + 128;
    const int tid = threadIdx.x;
    const int wid = tid >> 5;
    const int lane = tid & 31;
    const int wm = wid & 3;
    const int wn = wid >> 2;
    const int mblk = blockIdx.y;
    const int nblk = blockIdx.x;
    const int ablk = mblk >> 1, ahalf = mblk & 1;

    float acc[8][4];
#pragma unroll
    for (int j = 0; j < 8; j++)
#pragma unroll
        for (int r = 0; r < 4; r++) acc[j][r] = 0.0f;

    if (tid == 0) {
        MBAR_INIT(sbase + 0, 1);
        MBAR_INIT(sbase + 8, 1);
        MBAR_INIT(sbase + 16, 1);
    }
    __syncthreads();

    const size_t abase_blk = (size_t)ablk * NKB;
    const size_t bbase_blk = (size_t)nblk * NKB;

    auto issue = [&](int kt) {
        const int s = kt - (kt / 3) * 3;
        const uint32_t dst = tiles + s * STAGE64;
        const uint32_t m = sbase + s * 8;
        MBAR_EXPECT_TX(m, (uint32_t)STAGE64);
        const size_t ao = (abase_blk + kt) * TBLK_ELEMS + (size_t)ahalf * (64 * TROW);
        const size_t bo = (bbase_blk + kt) * TBLK_ELEMS;
        BULK_G2S(dst,                        Ah + ao, (uint32_t)AHALF_B, m);
        BULK_G2S(dst + AHALF_B,              Al + ao, (uint32_t)AHALF_B, m);
        BULK_G2S(dst + 2 * AHALF_B,               Bh + bo, (uint32_t)TBLK_BYTES, m);
        BULK_G2S(dst + 2 * AHALF_B + TBLK_BYTES,  Bl + bo, (uint32_t)TBLK_BYTES, m);
    };
    if (tid == 0) { issue(0); issue(1); issue(2); }

    const int a_row = (lane & 15);
    const int a_col = (lane >> 4) * 8;
    const int b_row = (lane & 7) + ((lane >> 4) & 1) * 8;
    const int b_col = ((lane >> 3) & 1) * 8;

    int phase[3] = {0, 0, 0};
    for (int kt = 0; kt < NKT; kt++) {
        const int s = kt - (kt / 3) * 3;
        mbar_wait(sbase + s * 8, phase[s]);
        phase[s] ^= 1;
        const uint32_t st = tiles + s * STAGE64;

#pragma unroll
        for (int ph = 0; ph < 2; ph++) {
            const int koff = ph * 16;
            uint32_t af[2][4];
#pragma unroll
            for (int prod = 0; prod < 2; prod++) {
                const uint32_t addr = st + prod * AHALF_B +
                    (uint32_t)((wm * 16 + a_row) * (TROW * 2) + (koff + a_col) * 2);
                LDSM_X4(af[prod][0], af[prod][1], af[prod][2], af[prod][3], addr);
            }
#pragma unroll
            for (int np = 0; np < 4; np++) {
                const uint32_t boff =
                    (uint32_t)((wn * 64 + np * 16 + b_row) * (TROW * 2) +
                               (koff + b_col) * 2);
                uint32_t bh[4], bl[4];
                LDSM_X4(bh[0], bh[1], bh[2], bh[3], st + 2 * AHALF_B + boff);
                LDSM_X4(bl[0], bl[1], bl[2], bl[3], st + 2 * AHALF_B + TBLK_BYTES + boff);
                uint32_t bh0[2] = {bh[0], bh[1]}, bh1[2] = {bh[2], bh[3]};
                uint32_t bl0[2] = {bl[0], bl[1]}, bl1[2] = {bl[2], bl[3]};
                MMA16816(acc[np * 2],     af[0], bh0);
                MMA16816(acc[np * 2],     af[0], bl0);
                MMA16816(acc[np * 2],     af[1], bh0);
                MMA16816(acc[np * 2 + 1], af[0], bh1);
                MMA16816(acc[np * 2 + 1], af[0], bl1);
                MMA16816(acc[np * 2 + 1], af[1], bh1);
            }
        }
        __syncthreads();
        if (kt + 3 < NKT && tid == 0) issue(kt + 3);
    }

    const int m0 = mblk * 64, n0 = nblk * 128;
    const int rbase = m0 + wm * 16 + (lane >> 2);
    const int cbase = n0 + wn * 64 + (lane & 3) * 2;
#pragma unroll
    for (int half = 0; half < 2; half++) {
        const int row = rbase + half * 8;
        if (row >= M) continue;
#pragma unroll
        for (int nf = 0; nf < 8; nf++) {
            const int col = cbase + nf * 8;
            float2 o;
            o.x = acc[nf][half * 2 + 0] + bias[col];
            o.y = acc[nf][half * 2 + 1] + bias[col + 1];
            *(float2*)(C + (size_t)row * C_DIM + col) = o;
        }
    }
}

// ---------------------------------------------------------------------------
// Tensorized varlen attention (bf16x3), fixed-shift softmax (|s|<=8),
// K/V tiles loaded via cp.async.bulk from head-major padded-tile layout.
// 256 thr, occ 2, 128 queries/block, 2-stage mbarrier pipeline. TILED output.
// ---------------------------------------------------------------------------
#define KSTRIDE_B 144
#define ARR_B (64 * KSTRIDE_B)            // 9216 == HM_TILE_BYTES
#define ATT_STAGE (4 * ARR_B)             // 36864
#define ATT_SMEM (128 + 2 * ATT_STAGE)    // 73856

__global__ __launch_bounds__(256, 2) void attn_mma(const int* __restrict__ cu)
{
    const int seq = blockIdx.x;
    const int head = blockIdx.y;
    const int s0 = cu[seq];
    const int L = cu[seq + 1] - s0;
    const int q0 = blockIdx.z * 128;
    if (q0 >= L) return;

    extern __shared__ char sm[];
    const uint32_t sb = smem_u32(sm);
    const uint32_t mb0 = sb, mb1 = sb + 8;
    const uint32_t tiles = sb + 128;
    const int tid = threadIdx.x;
    const int wid = tid >> 5;
    const int lane = tid & 31;
    const int colh = head * HD;

    if (tid == 0) { MBAR_INIT(mb0, 1); MBAR_INIT(mb1, 1); }
    __syncthreads();

    uint32_t aQh[4][4], aQl[4][4];
    {
        int r0 = q0 + wid * 16 + (lane >> 2);
        int r1 = r0 + 8;
        if (r0 >= L) r0 = L - 1;
        if (r1 >= L) r1 = L - 1;
        const size_t b0 = (size_t)(s0 + r0) * C_DIM + colh + (lane & 3) * 2;
        const size_t b1 = (size_t)(s0 + r1) * C_DIM + colh + (lane & 3) * 2;
#pragma unroll
        for (int kc = 0; kc < 4; kc++) {
            aQh[kc][0] = *(const uint32_t*)(g_qh + b0 + kc * 16);
            aQh[kc][1] = *(const uint32_t*)(g_qh + b1 + kc * 16);
            aQh[kc][2] = *(const uint32_t*)(g_qh + b0 + kc * 16 + 8);
            aQh[kc][3] = *(const uint32_t*)(g_qh + b1 + kc * 16 + 8);
            aQl[kc][0] = *(const uint32_t*)(g_ql + b0 + kc * 16);
            aQl[kc][1] = *(const uint32_t*)(g_ql + b1 + kc * 16);
            aQl[kc][2] = *(const uint32_t*)(g_ql + b0 + kc * 16 + 8);
            aQl[kc][3] = *(const uint32_t*)(g_ql + b1 + kc * 16 + 8);
        }
    }

    float o[8][4];
#pragma unroll
    for (int i = 0; i < 8; i++)
#pragma unroll
        for (int j = 0; j < 4; j++) o[i][j] = 0.0f;
    float l0 = 0.0f, l1 = 0.0f;

    const int ntiles = (L + 63) >> 6;
    const size_t hbase = (size_t)(head * NT64 + (s0 >> 6)) * HM_TILE_ELEMS;

    auto issue = [&](int t) {
        const int s = t & 1;
        const uint32_t dst = tiles + s * ATT_STAGE;
        const uint32_t m = s ? mb1 : mb0;
        MBAR_EXPECT_TX(m, (uint32_t)ATT_STAGE);
        const size_t off = hbase + (size_t)t * HM_TILE_ELEMS;
        BULK_G2S(dst,               g_khm + off, (uint32_t)ARR_B, m);
        BULK_G2S(dst + ARR_B,       g_klm + off, (uint32_t)ARR_B, m);
        BULK_G2S(dst + 2 * ARR_B,   g_vhm + off, (uint32_t)ARR_B, m);
        BULK_G2S(dst + 3 * ARR_B,   g_vlm + off, (uint32_t)ARR_B, m);
    };
    if (tid == 0) { issue(0); if (ntiles > 1) issue(1); }

    int ph0 = 0, ph1 = 0;
    for (int t = 0; t < ntiles; t++) {
        const int s = t & 1;
        if (s == 0) { mbar_wait(mb0, ph0); ph0 ^= 1; }
        else        { mbar_wait(mb1, ph1); ph1 ^= 1; }
        const uint32_t st = tiles + s * ATT_STAGE;
        const int kb = t * 64;

        float sc[8][4];
#pragma unroll
        for (int i = 0; i < 8; i++)
#pragma unroll
            for (int j = 0; j < 4; j++) sc[i][j] = 0.0f;

        const int mat = lane >> 3;
#pragma unroll
        for (int kc = 0; kc < 4; kc++) {
#pragma unroll
            for (int pair = 0; pair < 4; pair++) {
                const int krow = (pair * 2 + (mat >> 1)) * 8 + (lane & 7);
                const uint32_t cb = (uint32_t)(kc * 32 + (mat & 1) * 16);
                uint32_t kh[4], kl[4];
                LDSM_X4(kh[0], kh[1], kh[2], kh[3], st + 0     + krow * KSTRIDE_B + cb);
                LDSM_X4(kl[0], kl[1], kl[2], kl[3], st + ARR_B + krow * KSTRIDE_B + cb);
                uint32_t bh0[2] = {kh[0], kh[1]}, bh1[2] = {kh[2], kh[3]};
                uint32_t bl0[2] = {kl[0], kl[1]}, bl1[2] = {kl[2], kl[3]};
                MMA16816(sc[pair * 2],     aQh[kc], bh0);
                MMA16816(sc[pair * 2],     aQh[kc], bl0);
                MMA16816(sc[pair * 2],     aQl[kc], bh0);
                MMA16816(sc[pair * 2 + 1], aQh[kc], bh1);
                MMA16816(sc[pair * 2 + 1], aQh[kc], bl1);
                MMA16816(sc[pair * 2 + 1], aQl[kc], bh1);
            }
        }

        // fixed-shift softmax: p = exp(s - 8); masked -> 0
        const int cb0 = (lane & 3) * 2;
#pragma unroll
        for (int nf = 0; nf < 8; nf++) {
            int colk = kb + nf * 8 + cb0;
            if (colk >= L)     { sc[nf][0] = -1e30f; sc[nf][2] = -1e30f; }
            if (colk + 1 >= L) { sc[nf][1] = -1e30f; sc[nf][3] = -1e30f; }
        }
#pragma unroll
        for (int nf = 0; nf < 8; nf++) {
            sc[nf][0] = __expf(sc[nf][0] - 8.0f);
            sc[nf][1] = __expf(sc[nf][1] - 8.0f);
            sc[nf][2] = __expf(sc[nf][2] - 8.0f);
            sc[nf][3] = __expf(sc[nf][3] - 8.0f);
            l0 += sc[nf][0] + sc[nf][1];
            l1 += sc[nf][2] + sc[nf][3];
        }

#pragma unroll
        for (int j = 0; j < 4; j++) {
            uint32_t phh[4], pll[4];
            split2(sc[2 * j][0], sc[2 * j][1], phh[0], pll[0]);
            split2(sc[2 * j][2], sc[2 * j][3], phh[1], pll[1]);
            split2(sc[2 * j + 1][0], sc[2 * j + 1][1], phh[2], pll[2]);
            split2(sc[2 * j + 1][2], sc[2 * j + 1][3], phh[3], pll[3]);
            const uint32_t vrow = (uint32_t)((j * 16 + (lane & 15)) * KSTRIDE_B +
                                             ((lane >> 4) << 3) * 2);
#pragma unroll
            for (int vp = 0; vp < 4; vp++) {
                const uint32_t addr = st + 2 * ARR_B + vrow + (uint32_t)(vp * 32);
                uint32_t vh[4], vl[4];
                LDSM_X4_T(vh[0], vh[1], vh[2], vh[3], addr);
                LDSM_X4_T(vl[0], vl[1], vl[2], vl[3], addr + ARR_B);
                uint32_t bh0[2] = {vh[0], vh[1]}, bh1[2] = {vh[2], vh[3]};
                uint32_t bl0[2] = {vl[0], vl[1]}, bl1[2] = {vl[2], vl[3]};
                MMA16816(o[vp * 2],     phh, bh0);
                MMA16816(o[vp * 2],     pll, bh0);
                MMA16816(o[vp * 2],     phh, bl0);
                MMA16816(o[vp * 2 + 1], phh, bh1);
                MMA16816(o[vp * 2 + 1], pll, bh1);
                MMA16816(o[vp * 2 + 1], phh, bl1);
            }
        }
        __syncthreads();
        if (t + 2 < ntiles && tid == 0) issue(t + 2);
    }

    l0 += __shfl_xor_sync(0xffffffffu, l0, 1);
    l0 += __shfl_xor_sync(0xffffffffu, l0, 2);
    l1 += __shfl_xor_sync(0xffffffffu, l1, 1);
    l1 += __shfl_xor_sync(0xffffffffu, l1, 2);
    const float inv0 = 1.0f / l0;
    const float inv1 = 1.0f / l1;
    const int r0 = q0 + wid * 16 + (lane >> 2);
    const int r1 = r0 + 8;
#pragma unroll
    for (int nf = 0; nf < 8; nf++) {
        const int col = colh + nf * 8 + (lane & 3) * 2;
        if (r0 < L) {
            uint32_t h, l;
            split2(o[nf][0] * inv0, o[nf][1] * inv0, h, l);
            const size_t off = tiled_off(s0 + r0, col);
            *(uint32_t*)(g_ath + off) = h;
            *(uint32_t*)(g_atl + off) = l;
        }
        if (r1 < L) {
            uint32_t h, l;
            split2(o[nf][2] * inv1, o[nf][3] * inv1, h, l);
            const size_t off = tiled_off(s0 + r1, col);
            *(uint32_t*)(g_ath + off) = h;
            *(uint32_t*)(g_atl + off) = l;
        }
    }
}

// ---------------------------------------------------------------------------
// Launch
// ---------------------------------------------------------------------------
extern "C" void kernel_launch(void* const* d_in, const int* in_sizes, int n_in,
                              void* d_out, int out_size)
{
    const float* x  = (const float*)d_in[0];
    const int* cu   = (const int*)d_in[1];
    const float* Wq = (const float*)d_in[2];
    const float* bq = (const float*)d_in[3];
    const float* Wk = (const float*)d_in[4];
    const float* bk = (const float*)d_in[5];
    const float* Wv = (const float*)d_in[6];
    const float* bv = (const float*)d_in[7];
    const float* qn = (const float*)d_in[8];
    const float* kn = (const float*)d_in[9];
    const float* Wo = (const float*)d_in[10];
    const float* bo = (const float*)d_in[11];
    float* out = (float*)d_out;

    const int T = in_sizes[0] / C_DIM;
    const int nseq = in_sizes[1] - 1;

    bf16 *xh, *xl, *qh, *ql, *kh, *kl, *vh, *vl, *ath, *atl;
    bf16 *wqh, *wql, *wkh, *wkl, *wvh, *wvl, *woh, *wol;
    cudaGetSymbolAddress((void**)&xh, g_xh);
    cudaGetSymbolAddress((void**)&xl, g_xl);
    cudaGetSymbolAddress((void**)&qh, g_qh);
    cudaGetSymbolAddress((void**)&ql, g_ql);
    cudaGetSymbolAddress((void**)&kh, g_khm);
    cudaGetSymbolAddress((void**)&kl, g_klm);
    cudaGetSymbolAddress((void**)&vh, g_vhm);
    cudaGetSymbolAddress((void**)&vl, g_vlm);
    cudaGetSymbolAddress((void**)&ath, g_ath);
    cudaGetSymbolAddress((void**)&atl, g_atl);
    cudaGetSymbolAddress((void**)&wqh, g_wqh);
    cudaGetSymbolAddress((void**)&wql, g_wql);
    cudaGetSymbolAddress((void**)&wkh, g_wkh);
    cudaGetSymbolAddress((void**)&wkl, g_wkl);
    cudaGetSymbolAddress((void**)&wvh, g_wvh);
    cudaGetSymbolAddress((void**)&wvl, g_wvl);
    cudaGetSymbolAddress((void**)&woh, g_woh);
    cudaGetSymbolAddress((void**)&wol, g_wol);

    cudaFuncSetAttribute(gemm_qkv, cudaFuncAttributeMaxDynamicSharedMemorySize, GEMM_SMEM);
    cudaFuncSetAttribute(gemm_out64, cudaFuncAttributeMaxDynamicSharedMemorySize, GEMM64_SMEM);
    cudaFuncSetAttribute(attn_mma, cudaFuncAttributeMaxDynamicSharedMemorySize, ATT_SMEM);

    const int xn4 = T * C_DIM / 4;
    const int wn4 = C_DIM * C_DIM / 4;
    const int total = xn4 + 4 * wn4;
    split_all_tiled<<<(total + 255) / 256, 256>>>(
        (const float4*)x,
        (const float4*)Wq, (const float4*)Wk, (const float4*)Wv, (const float4*)Wo,
        xh, xl, wqh, wql, wkh, wkl, wvh, wvl, woh, wol, xn4, wn4);

    dim3 qkv_grid(C_DIM / 128, (T + 127) / 128, 3);
    gemm_qkv<<<qkv_grid, 256, GEMM_SMEM>>>(xh, xl,
                                           wqh, wql, bq,
                                           wkh, wkl, bk,
                                           wvh, wvl, bv,
                                           qn, kn,
                                           qh, ql, kh, kl, vh, vl, T);

    dim3 attn_grid(nseq, NH, LMAX / 128);
    attn_mma<<<attn_grid, 256, ATT_SMEM>>>(cu);

    dim3 ogrid(C_DIM / 128, (T + 63) / 64);
    gemm_out64<<<ogrid, 256, GEMM64_SMEM>>>(ath, atl, woh, wol, bo, out, T);
}

// round 14
// speedup vs baseline: 1.6550x; 1.0033x over previous
#include <cuda_runtime.h>
#include <cuda_bf16.h>
#include <cstdint>

#define C_DIM 1024
#define NH 16
#define HD 64
#define MAX_T 8192
#define LMAX 1024
#define EPS_RMS 1.1920929e-07f

typedef __nv_bfloat16 bf16;

// ---------------- scratch (device globals; allocation-free rule) ----------
// Q: linear layout (per-thread register loads in attention)
__device__ bf16 g_qh[MAX_T * C_DIM];
__device__ bf16 g_ql[MAX_T * C_DIM];

// K/V: head-major padded-tile layout [head][tile64][64 rows x 72 elems]
#define HM_ROW 72
#define HM_TILE_ELEMS (64 * HM_ROW)            // 4608
#define HM_TILE_BYTES (HM_TILE_ELEMS * 2)      // 9216
#define NT64 (MAX_T / 64)                      // 128
__device__ bf16 g_khm[NH * NT64 * HM_TILE_ELEMS];
__device__ bf16 g_klm[NH * NT64 * HM_TILE_ELEMS];
__device__ bf16 g_vhm[NH * NT64 * HM_TILE_ELEMS];
__device__ bf16 g_vlm[NH * NT64 * HM_TILE_ELEMS];

// tiled layouts (GEMM operands): [blk128][kblk32][128 rows x 40 elems]
#define TROW 40
#define TBLK_ELEMS (128 * TROW)       // 5120 elems
#define TBLK_BYTES (TBLK_ELEMS * 2)   // 10240 B
#define NKB (C_DIM / 32)              // 32 k-blocks
__device__ bf16 g_xh[(MAX_T / 128) * NKB * TBLK_ELEMS];
__device__ bf16 g_xl[(MAX_T / 128) * NKB * TBLK_ELEMS];
__device__ bf16 g_ath[(MAX_T / 128) * NKB * TBLK_ELEMS];
__device__ bf16 g_atl[(MAX_T / 128) * NKB * TBLK_ELEMS];
__device__ bf16 g_wqh[8 * NKB * TBLK_ELEMS];
__device__ bf16 g_wql[8 * NKB * TBLK_ELEMS];
__device__ bf16 g_wkh[8 * NKB * TBLK_ELEMS];
__device__ bf16 g_wkl[8 * NKB * TBLK_ELEMS];
__device__ bf16 g_wvh[8 * NKB * TBLK_ELEMS];
__device__ bf16 g_wvl[8 * NKB * TBLK_ELEMS];
__device__ bf16 g_woh[8 * NKB * TBLK_ELEMS];
__device__ bf16 g_wol[8 * NKB * TBLK_ELEMS];

// ---------------- helpers ---------------------------------------------
__device__ __forceinline__ uint32_t smem_u32(const void* p) {
    uint32_t a;
    asm("{ .reg .u64 t; cvta.to.shared.u64 t, %1; cvt.u32.u64 %0, t; }"
        : "=r"(a) : "l"(p));
    return a;
}

__device__ __forceinline__ size_t tiled_off(int r, int c) {
    return ((size_t)((r >> 7) * NKB + (c >> 5))) * TBLK_ELEMS +
           (size_t)((r & 127) * TROW + (c & 31));
}

__device__ __forceinline__ size_t hm_off(int row, int col) {
    const int head = col >> 6;
    const int d = col & 63;
    return ((size_t)(head * NT64 + (row >> 6)) * 64 + (row & 63)) * HM_ROW + d;
}

#define LDSM_X4(r0, r1, r2, r3, addr) \
    asm volatile("ldmatrix.sync.aligned.m8n8.x4.shared.b16 {%0,%1,%2,%3}, [%4];" \
                 : "=r"(r0), "=r"(r1), "=r"(r2), "=r"(r3) : "r"(addr))

#define LDSM_X4_T(r0, r1, r2, r3, addr) \
    asm volatile("ldmatrix.sync.aligned.m8n8.x4.trans.shared.b16 {%0,%1,%2,%3}, [%4];" \
                 : "=r"(r0), "=r"(r1), "=r"(r2), "=r"(r3) : "r"(addr))

#define MMA16816(d, a, b) \
    asm volatile("mma.sync.aligned.m16n8k16.row.col.f32.bf16.bf16.f32 " \
                 "{%0,%1,%2,%3}, {%4,%5,%6,%7}, {%8,%9}, {%0,%1,%2,%3};" \
                 : "+f"((d)[0]), "+f"((d)[1]), "+f"((d)[2]), "+f"((d)[3]) \
                 : "r"((a)[0]), "r"((a)[1]), "r"((a)[2]), "r"((a)[3]), \
                   "r"((b)[0]), "r"((b)[1]))

#define MBAR_INIT(a, cnt) \
    asm volatile("mbarrier.init.shared.b64 [%0], %1;" :: "r"(a), "r"(cnt) : "memory")
#define MBAR_EXPECT_TX(a, bytes) \
    asm volatile("mbarrier.arrive.expect_tx.shared.b64 _, [%0], %1;" \
                 :: "r"(a), "r"(bytes) : "memory")
#define BULK_G2S(dst, src, bytes, mbar) \
    asm volatile("cp.async.bulk.shared::cta.global.mbarrier::complete_tx::bytes " \
                 "[%0], [%1], %2, [%3];" \
                 :: "r"(dst), "l"(src), "r"(bytes), "r"(mbar) : "memory")

__device__ __forceinline__ void mbar_wait(uint32_t a, int phase) {
    asm volatile(
        "{ .reg .pred P;\n"
        "WL%=:\n"
        " mbarrier.try_wait.parity.acquire.cta.shared::cta.b64 P, [%0], %1, 0x989680;\n"
        " @P bra WD%=;\n"
        " bra WL%=;\n"
        "WD%=: }"
        :: "r"(a), "r"(phase) : "memory");
}

__device__ __forceinline__ void split2(float x, float y, uint32_t& h, uint32_t& l) {
    bf16 hx = __float2bfloat16(x);
    bf16 hy = __float2bfloat16(y);
    __nv_bfloat162 H; H.x = hx; H.y = hy;
    __nv_bfloat162 L;
    L.x = __float2bfloat16(x - __bfloat162float(hx));
    L.y = __float2bfloat16(y - __bfloat162float(hy));
    h = *(uint32_t*)&H;
    l = *(uint32_t*)&L;
}

// ---------------------------------------------------------------------------
// fused fp32 -> (hi,lo) split into TILED layout: x + 4 weight matrices
// ---------------------------------------------------------------------------
__global__ __launch_bounds__(256) void split_all_tiled(
    const float4* __restrict__ x,
    const float4* __restrict__ w0, const float4* __restrict__ w1,
    const float4* __restrict__ w2, const float4* __restrict__ w3,
    bf16* __restrict__ xh, bf16* __restrict__ xl,
    bf16* __restrict__ h0p, bf16* __restrict__ l0p,
    bf16* __restrict__ h1p, bf16* __restrict__ l1p,
    bf16* __restrict__ h2p, bf16* __restrict__ l2p,
    bf16* __restrict__ h3p, bf16* __restrict__ l3p,
    int xn4, int wn4)
{
    int gid = blockIdx.x * blockDim.x + threadIdx.x;
    const float4* in; bf16 *hi, *lo; int i;
    if (gid < xn4) {
        in = x; hi = xh; lo = xl; i = gid;
    } else {
        int g = gid - xn4;
        int sel = g / wn4;
        if (sel >= 4) return;
        i = g - sel * wn4;
        if (sel == 0)      { in = w0; hi = h0p; lo = l0p; }
        else if (sel == 1) { in = w1; hi = h1p; lo = l1p; }
        else if (sel == 2) { in = w2; hi = h2p; lo = l2p; }
        else               { in = w3; hi = h3p; lo = l3p; }
    }
    float4 v = in[i];
    const int row = i >> 8;
    const int c = (i & 255) * 4;
    const size_t off = tiled_off(row, c);
    uint32_t a0, b0, a1, b1;
    split2(v.x, v.y, a0, b0);
    split2(v.z, v.w, a1, b1);
    *(uint2*)(hi + off) = make_uint2(a0, a1);
    *(uint2*)(lo + off) = make_uint2(b0, b1);
}

// ---------------------------------------------------------------------------
// bf16x3 GEMM: BM=128, BN=128, BK=32; 8 warps (4x2), warp tile 32x64;
// 2-stage bulk-copy double buffer; occupancy 2.
// EPI: 0 = fp32 C + bias
//      1 = bias + split -> HEAD-MAJOR hi/lo (V)
//      2 = bias + rmsnorm + scale + split -> LINEAR hi/lo (Q)
//      3 = bias + rmsnorm + scale + split -> HEAD-MAJOR hi/lo (K)
// ---------------------------------------------------------------------------
#define NKT NKB
#define SUBTILE_B TBLK_BYTES              // 10240
#define STAGE_BYTES (4 * SUBTILE_B)       // 40960 (Ah, Al, Bh, Bl)
#define GEMM_SMEM (128 + 2 * STAGE_BYTES) // 82048

template <int EPI>
__device__ __forceinline__ void gemm_core(
    const bf16* __restrict__ Ah, const bf16* __restrict__ Al,
    const bf16* __restrict__ Bh, const bf16* __restrict__ Bl,
    const float* __restrict__ bias, float* __restrict__ C,
    bf16* __restrict__ Oh, bf16* __restrict__ Ol,
    const float* __restrict__ nw, float nscale, int M,
    int mblk, int nblk, char* dsm)
{
    const uint32_t sbase = smem_u32(dsm);
    const uint32_t mb0 = sbase, mb1 = sbase + 8;
    const uint32_t tiles = sbase + 128;
    const int tid = threadIdx.x;
    const int wid = tid >> 5;
    const int lane = tid & 31;
    const int wm = wid & 3;
    const int wn = wid >> 2;

    float acc[2][8][4];
#pragma unroll
    for (int i = 0; i < 2; i++)
#pragma unroll
        for (int j = 0; j < 8; j++)
#pragma unroll
            for (int r = 0; r < 4; r++) acc[i][j][r] = 0.0f;

    if (tid == 0) { MBAR_INIT(mb0, 1); MBAR_INIT(mb1, 1); }
    __syncthreads();

    const size_t abase_blk = (size_t)mblk * NKB;
    const size_t bbase_blk = (size_t)nblk * NKB;

    auto issue = [&](int kt) {
        const int s = kt & 1;
        const uint32_t dst = tiles + s * STAGE_BYTES;
        const uint32_t m = s ? mb1 : mb0;
        MBAR_EXPECT_TX(m, (uint32_t)STAGE_BYTES);
        const size_t ao = (abase_blk + kt) * TBLK_ELEMS;
        const size_t bo = (bbase_blk + kt) * TBLK_ELEMS;
        BULK_G2S(dst,                  Ah + ao, (uint32_t)TBLK_BYTES, m);
        BULK_G2S(dst + SUBTILE_B,      Al + ao, (uint32_t)TBLK_BYTES, m);
        BULK_G2S(dst + 2 * SUBTILE_B,  Bh + bo, (uint32_t)TBLK_BYTES, m);
        BULK_G2S(dst + 3 * SUBTILE_B,  Bl + bo, (uint32_t)TBLK_BYTES, m);
    };
    if (tid == 0) { issue(0); issue(1); }

    const int a_row = (lane & 15);
    const int a_col = (lane >> 4) * 8;
    const int b_row = (lane & 7) + ((lane >> 4) & 1) * 8;
    const int b_col = ((lane >> 3) & 1) * 8;

    int ph0 = 0, ph1 = 0;
    for (int kt = 0; kt < NKT; kt++) {
        const int s = kt & 1;
        if (s == 0) { mbar_wait(mb0, ph0); ph0 ^= 1; }
        else        { mbar_wait(mb1, ph1); ph1 ^= 1; }
        const uint32_t st = tiles + s * STAGE_BYTES;

#pragma unroll
        for (int ph = 0; ph < 2; ph++) {
            const int koff = ph * 16;
            uint32_t af[2][2][4];
#pragma unroll
            for (int prod = 0; prod < 2; prod++) {
                const uint32_t abase = st + prod * SUBTILE_B;
#pragma unroll
                for (int mf = 0; mf < 2; mf++) {
                    const uint32_t addr = abase +
                        (uint32_t)((wm * 32 + mf * 16 + a_row) * (TROW * 2) +
                                   (koff + a_col) * 2);
                    LDSM_X4(af[prod][mf][0], af[prod][mf][1],
                            af[prod][mf][2], af[prod][mf][3], addr);
                }
            }
#pragma unroll
            for (int np = 0; np < 4; np++) {
                const uint32_t boff =
                    (uint32_t)((wn * 64 + np * 16 + b_row) * (TROW * 2) +
                               (koff + b_col) * 2);
                uint32_t bh[4], bl[4];
                LDSM_X4(bh[0], bh[1], bh[2], bh[3], st + 2 * SUBTILE_B + boff);
                LDSM_X4(bl[0], bl[1], bl[2], bl[3], st + 3 * SUBTILE_B + boff);
                uint32_t bh0[2] = {bh[0], bh[1]}, bh1[2] = {bh[2], bh[3]};
                uint32_t bl0[2] = {bl[0], bl[1]}, bl1[2] = {bl[2], bl[3]};
#pragma unroll
                for (int mf = 0; mf < 2; mf++) {
                    MMA16816(acc[mf][np * 2],     af[0][mf], bh0);
                    MMA16816(acc[mf][np * 2],     af[0][mf], bl0);
                    MMA16816(acc[mf][np * 2],     af[1][mf], bh0);
                    MMA16816(acc[mf][np * 2 + 1], af[0][mf], bh1);
                    MMA16816(acc[mf][np * 2 + 1], af[0][mf], bl1);
                    MMA16816(acc[mf][np * 2 + 1], af[1][mf], bh1);
                }
            }
        }
        __syncthreads();
        if (kt + 2 < NKT && tid == 0) issue(kt + 2);
    }

    const int m0 = mblk * 128, n0 = nblk * 128;
    const int rbase = m0 + wm * 32 + (lane >> 2);
    const int cbase = n0 + wn * 64 + (lane & 3) * 2;
#pragma unroll
    for (int mf = 0; mf < 2; mf++) {
#pragma unroll
        for (int half = 0; half < 2; half++) {
            const int row = rbase + mf * 16 + half * 8;
            if (row >= M) continue;
            float v[8][2];
#pragma unroll
            for (int nf = 0; nf < 8; nf++) {
                const int col = cbase + nf * 8;
                v[nf][0] = acc[mf][nf][half * 2 + 0] + bias[col];
                v[nf][1] = acc[mf][nf][half * 2 + 1] + bias[col + 1];
            }
            if (EPI == 0) {
#pragma unroll
                for (int nf = 0; nf < 8; nf++) {
                    float2 o; o.x = v[nf][0]; o.y = v[nf][1];
                    *(float2*)(C + (size_t)row * C_DIM + cbase + nf * 8) = o;
                }
            } else if (EPI == 1) {
#pragma unroll
                for (int nf = 0; nf < 8; nf++) {
                    uint32_t h, l;
                    split2(v[nf][0], v[nf][1], h, l);
                    const size_t off = hm_off(row, cbase + nf * 8);
                    *(uint32_t*)(Oh + off) = h;
                    *(uint32_t*)(Ol + off) = l;
                }
            } else {
                float ss = 0.0f;
#pragma unroll
                for (int nf = 0; nf < 8; nf++)
                    ss += v[nf][0] * v[nf][0] + v[nf][1] * v[nf][1];
                ss += __shfl_xor_sync(0xffffffffu, ss, 1);
                ss += __shfl_xor_sync(0xffffffffu, ss, 2);
                const float r = rsqrtf(ss * (1.0f / HD) + EPS_RMS) * nscale;
                const int d0 = (lane & 3) * 2;
#pragma unroll
                for (int nf = 0; nf < 8; nf++) {
                    const int d = nf * 8 + d0;
                    uint32_t h, l;
                    split2(v[nf][0] * r * nw[d], v[nf][1] * r * nw[d + 1], h, l);
                    if (EPI == 2) {
                        *(uint32_t*)(Oh + (size_t)row * C_DIM + cbase + nf * 8) = h;
                        *(uint32_t*)(Ol + (size_t)row * C_DIM + cbase + nf * 8) = l;
                    } else {
                        const size_t off = hm_off(row, cbase + nf * 8);
                        *(uint32_t*)(Oh + off) = h;
                        *(uint32_t*)(Ol + off) = l;
                    }
                }
            }
        }
    }
}

__global__ __launch_bounds__(256, 2)
void gemm_qkv(const bf16* __restrict__ xh, const bf16* __restrict__ xl,
              const bf16* __restrict__ wqh, const bf16* __restrict__ wql,
              const float* __restrict__ bq,
              const bf16* __restrict__ wkh, const bf16* __restrict__ wkl,
              const float* __restrict__ bk,
              const bf16* __restrict__ wvh, const bf16* __restrict__ wvl,
              const float* __restrict__ bv,
              const float* __restrict__ qn, const float* __restrict__ kn,
              bf16* __restrict__ qh, bf16* __restrict__ ql,
              bf16* __restrict__ kh, bf16* __restrict__ kl,
              bf16* __restrict__ vh, bf16* __restrict__ vl, int M)
{
    extern __shared__ char dsm[];
    const int z = blockIdx.z;
    if (z == 0) {
        gemm_core<2>(xh, xl, wqh, wql, bq, nullptr, qh, ql, qn, 0.125f, M,
                     blockIdx.y, blockIdx.x, dsm);
    } else if (z == 1) {
        gemm_core<3>(xh, xl, wkh, wkl, bk, nullptr, kh, kl, kn, 1.0f, M,
                     blockIdx.y, blockIdx.x, dsm);
    } else {
        gemm_core<1>(xh, xl, wvh, wvl, bv, nullptr, vh, vl, nullptr, 0.f, M,
                     blockIdx.y, blockIdx.x, dsm);
    }
}

// ---------------------------------------------------------------------------
// Output-projection GEMM, BM=64, 2-stage (R10 proven config).
// ---------------------------------------------------------------------------
#define AHALF_B (64 * TROW * 2)            // 5120
#define STAGE64 (2 * AHALF_B + 2 * TBLK_BYTES)  // 30720
#define GEMM64_SMEM (128 + 2 * STAGE64)    // 61568

__global__ __launch_bounds__(256, 2)
void gemm_out64(const bf16* __restrict__ Ah, const bf16* __restrict__ Al,
                const bf16* __restrict__ Bh, const bf16* __restrict__ Bl,
                const float* __restrict__ bias, float* __restrict__ C, int M)
{
    extern __shared__ char dsm[];
    const uint32_t sbase = smem_u32(dsm);
    const uint32_t mb0 = sbase, mb1 = sbase + 8;
    const uint32_t tiles = sbase + 128;
    const int tid = threadIdx.x;
    const int wid = tid >> 5;
    const int lane = tid & 31;
    const int wm = wid & 3;
    const int wn = wid >> 2;
    const int mblk = blockIdx.y;
    const int nblk = blockIdx.x;
    const int ablk = mblk >> 1, ahalf = mblk & 1;

    float acc[8][4];
#pragma unroll
    for (int j = 0; j < 8; j++)
#pragma unroll
        for (int r = 0; r < 4; r++) acc[j][r] = 0.0f;

    if (tid == 0) { MBAR_INIT(mb0, 1); MBAR_INIT(mb1, 1); }
    __syncthreads();

    const size_t abase_blk = (size_t)ablk * NKB;
    const size_t bbase_blk = (size_t)nblk * NKB;

    auto issue = [&](int kt) {
        const int s = kt & 1;
        const uint32_t dst = tiles + s * STAGE64;
        const uint32_t m = s ? mb1 : mb0;
        MBAR_EXPECT_TX(m, (uint32_t)STAGE64);
        const size_t ao = (abase_blk + kt) * TBLK_ELEMS + (size_t)ahalf * (64 * TROW);
        const size_t bo = (bbase_blk + kt) * TBLK_ELEMS;
        BULK_G2S(dst,                        Ah + ao, (uint32_t)AHALF_B, m);
        BULK_G2S(dst + AHALF_B,              Al + ao, (uint32_t)AHALF_B, m);
        BULK_G2S(dst + 2 * AHALF_B,               Bh + bo, (uint32_t)TBLK_BYTES, m);
        BULK_G2S(dst + 2 * AHALF_B + TBLK_BYTES,  Bl + bo, (uint32_t)TBLK_BYTES, m);
    };
    if (tid == 0) { issue(0); issue(1); }

    const int a_row = (lane & 15);
    const int a_col = (lane >> 4) * 8;
    const int b_row = (lane & 7) + ((lane >> 4) & 1) * 8;
    const int b_col = ((lane >> 3) & 1) * 8;

    int ph0 = 0, ph1 = 0;
    for (int kt = 0; kt < NKT; kt++) {
        const int s = kt & 1;
        if (s == 0) { mbar_wait(mb0, ph0); ph0 ^= 1; }
        else        { mbar_wait(mb1, ph1); ph1 ^= 1; }
        const uint32_t st = tiles + s * STAGE64;

#pragma unroll
        for (int ph = 0; ph < 2; ph++) {
            const int koff = ph * 16;
            uint32_t af[2][4];
#pragma unroll
            for (int prod = 0; prod < 2; prod++) {
                const uint32_t addr = st + prod * AHALF_B +
                    (uint32_t)((wm * 16 + a_row) * (TROW * 2) + (koff + a_col) * 2);
                LDSM_X4(af[prod][0], af[prod][1], af[prod][2], af[prod][3], addr);
            }
#pragma unroll
            for (int np = 0; np < 4; np++) {
                const uint32_t boff =
                    (uint32_t)((wn * 64 + np * 16 + b_row) * (TROW * 2) +
                               (koff + b_col) * 2);
                uint32_t bh[4], bl[4];
                LDSM_X4(bh[0], bh[1], bh[2], bh[3], st + 2 * AHALF_B + boff);
                LDSM_X4(bl[0], bl[1], bl[2], bl[3], st + 2 * AHALF_B + TBLK_BYTES + boff);
                uint32_t bh0[2] = {bh[0], bh[1]}, bh1[2] = {bh[2], bh[3]};
                uint32_t bl0[2] = {bl[0], bl[1]}, bl1[2] = {bl[2], bl[3]};
                MMA16816(acc[np * 2],     af[0], bh0);
                MMA16816(acc[np * 2],     af[0], bl0);
                MMA16816(acc[np * 2],     af[1], bh0);
                MMA16816(acc[np * 2 + 1], af[0], bh1);
                MMA16816(acc[np * 2 + 1], af[0], bl1);
                MMA16816(acc[np * 2 + 1], af[1], bh1);
            }
        }
        __syncthreads();
        if (kt + 2 < NKT && tid == 0) issue(kt + 2);
    }

    const int m0 = mblk * 64, n0 = nblk * 128;
    const int rbase = m0 + wm * 16 + (lane >> 2);
    const int cbase = n0 + wn * 64 + (lane & 3) * 2;
#pragma unroll
    for (int half = 0; half < 2; half++) {
        const int row = rbase + half * 8;
        if (row >= M) continue;
#pragma unroll
        for (int nf = 0; nf < 8; nf++) {
            const int col = cbase + nf * 8;
            float2 o;
            o.x = acc[nf][half * 2 + 0] + bias[col];
            o.y = acc[nf][half * 2 + 1] + bias[col + 1];
            *(float2*)(C + (size_t)row * C_DIM + col) = o;
        }
    }
}

// ---------------------------------------------------------------------------
// Tensorized varlen attention (bf16x3), fixed-shift softmax (|s|<=8),
// K/V via cp.async.bulk from head-major layout. 3-stage pipeline with EARLY
// issue (prefetch lead ~2 tiles). 256 thr, occ 2, 128 q/block. TILED output.
// ---------------------------------------------------------------------------
#define KSTRIDE_B 144
#define ARR_B (64 * KSTRIDE_B)            // 9216 == HM_TILE_BYTES
#define ATT_STAGE (4 * ARR_B)             // 36864
#define ATT_NST 3
#define ATT_SMEM (128 + ATT_NST * ATT_STAGE)  // 110720 (x2 CTAs = 221KB)

__global__ __launch_bounds__(256, 2) void attn_mma(const int* __restrict__ cu)
{
    const int seq = blockIdx.x;
    const int head = blockIdx.y;
    const int s0 = cu[seq];
    const int L = cu[seq + 1] - s0;
    const int q0 = blockIdx.z * 128;
    if (q0 >= L) return;

    extern __shared__ char sm[];
    const uint32_t sb = smem_u32(sm);
    const uint32_t tiles = sb + 128;
    const int tid = threadIdx.x;
    const int wid = tid >> 5;
    const int lane = tid & 31;
    const int colh = head * HD;

    if (tid == 0) {
        MBAR_INIT(sb + 0, 1);
        MBAR_INIT(sb + 8, 1);
        MBAR_INIT(sb + 16, 1);
    }
    __syncthreads();

    uint32_t aQh[4][4], aQl[4][4];
    {
        int r0 = q0 + wid * 16 + (lane >> 2);
        int r1 = r0 + 8;
        if (r0 >= L) r0 = L - 1;
        if (r1 >= L) r1 = L - 1;
        const size_t b0 = (size_t)(s0 + r0) * C_DIM + colh + (lane & 3) * 2;
        const size_t b1 = (size_t)(s0 + r1) * C_DIM + colh + (lane & 3) * 2;
#pragma unroll
        for (int kc = 0; kc < 4; kc++) {
            aQh[kc][0] = *(const uint32_t*)(g_qh + b0 + kc * 16);
            aQh[kc][1] = *(const uint32_t*)(g_qh + b1 + kc * 16);
            aQh[kc][2] = *(const uint32_t*)(g_qh + b0 + kc * 16 + 8);
            aQh[kc][3] = *(const uint32_t*)(g_qh + b1 + kc * 16 + 8);
            aQl[kc][0] = *(const uint32_t*)(g_ql + b0 + kc * 16);
            aQl[kc][1] = *(const uint32_t*)(g_ql + b1 + kc * 16);
            aQl[kc][2] = *(const uint32_t*)(g_ql + b0 + kc * 16 + 8);
            aQl[kc][3] = *(const uint32_t*)(g_ql + b1 + kc * 16 + 8);
        }
    }

    float o[8][4];
#pragma unroll
    for (int i = 0; i < 8; i++)
#pragma unroll
        for (int j = 0; j < 4; j++) o[i][j] = 0.0f;
    float l0 = 0.0f, l1 = 0.0f;

    const int ntiles = (L + 63) >> 6;
    const size_t hbase = (size_t)(head * NT64 + (s0 >> 6)) * HM_TILE_ELEMS;

    auto issue = [&](int t) {
        const int s = t - (t / ATT_NST) * ATT_NST;
        const uint32_t dst = tiles + s * ATT_STAGE;
        const uint32_t m = sb + s * 8;
        MBAR_EXPECT_TX(m, (uint32_t)ATT_STAGE);
        const size_t off = hbase + (size_t)t * HM_TILE_ELEMS;
        BULK_G2S(dst,               g_khm + off, (uint32_t)ARR_B, m);
        BULK_G2S(dst + ARR_B,       g_klm + off, (uint32_t)ARR_B, m);
        BULK_G2S(dst + 2 * ARR_B,   g_vhm + off, (uint32_t)ARR_B, m);
        BULK_G2S(dst + 3 * ARR_B,   g_vlm + off, (uint32_t)ARR_B, m);
    };
    if (tid == 0) { issue(0); if (ntiles > 1) issue(1); }

    int phase[ATT_NST] = {0, 0, 0};
    for (int t = 0; t < ntiles; t++) {
        const int s = t - (t / ATT_NST) * ATT_NST;
        mbar_wait(sb + s * 8, phase[s]);
        phase[s] ^= 1;
        // EARLY issue: stage (t+2)%3 was last read in iteration t-1, and we
        // passed the end-of-(t-1) __syncthreads, so it is safe to overwrite.
        if (t + 2 < ntiles && tid == 0) issue(t + 2);
        const uint32_t st = tiles + s * ATT_STAGE;
        const int kb = t * 64;

        float sc[8][4];
#pragma unroll
        for (int i = 0; i < 8; i++)
#pragma unroll
            for (int j = 0; j < 4; j++) sc[i][j] = 0.0f;

        const int mat = lane >> 3;
#pragma unroll
        for (int kc = 0; kc < 4; kc++) {
#pragma unroll
            for (int pair = 0; pair < 4; pair++) {
                const int krow = (pair * 2 + (mat >> 1)) * 8 + (lane & 7);
                const uint32_t cb = (uint32_t)(kc * 32 + (mat & 1) * 16);
                uint32_t kh[4], kl[4];
                LDSM_X4(kh[0], kh[1], kh[2], kh[3], st + 0     + krow * KSTRIDE_B + cb);
                LDSM_X4(kl[0], kl[1], kl[2], kl[3], st + ARR_B + krow * KSTRIDE_B + cb);
                uint32_t bh0[2] = {kh[0], kh[1]}, bh1[2] = {kh[2], kh[3]};
                uint32_t bl0[2] = {kl[0], kl[1]}, bl1[2] = {kl[2], kl[3]};
                MMA16816(sc[pair * 2],     aQh[kc], bh0);
                MMA16816(sc[pair * 2],     aQh[kc], bl0);
                MMA16816(sc[pair * 2],     aQl[kc], bh0);
                MMA16816(sc[pair * 2 + 1], aQh[kc], bh1);
                MMA16816(sc[pair * 2 + 1], aQh[kc], bl1);
                MMA16816(sc[pair * 2 + 1], aQl[kc], bh1);
            }
        }

        const int cb0 = (lane & 3) * 2;
#pragma unroll
        for (int nf = 0; nf < 8; nf++) {
            int colk = kb + nf * 8 + cb0;
            if (colk >= L)     { sc[nf][0] = -1e30f; sc[nf][2] = -1e30f; }
            if (colk + 1 >= L) { sc[nf][1] = -1e30f; sc[nf][3] = -1e30f; }
        }
#pragma unroll
        for (int nf = 0; nf < 8; nf++) {
            sc[nf][0] = __expf(sc[nf][0] - 8.0f);
            sc[nf][1] = __expf(sc[nf][1] - 8.0f);
            sc[nf][2] = __expf(sc[nf][2] - 8.0f);
            sc[nf][3] = __expf(sc[nf][3] - 8.0f);
            l0 += sc[nf][0] + sc[nf][1];
            l1 += sc[nf][2] + sc[nf][3];
        }

#pragma unroll
        for (int j = 0; j < 4; j++) {
            uint32_t phh[4], pll[4];
            split2(sc[2 * j][0], sc[2 * j][1], phh[0], pll[0]);
            split2(sc[2 * j][2], sc[2 * j][3], phh[1], pll[1]);
            split2(sc[2 * j + 1][0], sc[2 * j + 1][1], phh[2], pll[2]);
            split2(sc[2 * j + 1][2], sc[2 * j + 1][3], phh[3], pll[3]);
            const uint32_t vrow = (uint32_t)((j * 16 + (lane & 15)) * KSTRIDE_B +
                                             ((lane >> 4) << 3) * 2);
#pragma unroll
            for (int vp = 0; vp < 4; vp++) {
                const uint32_t addr = st + 2 * ARR_B + vrow + (uint32_t)(vp * 32);
                uint32_t vh[4], vl[4];
                LDSM_X4_T(vh[0], vh[1], vh[2], vh[3], addr);
                LDSM_X4_T(vl[0], vl[1], vl[2], vl[3], addr + ARR_B);
                uint32_t bh0[2] = {vh[0], vh[1]}, bh1[2] = {vh[2], vh[3]};
                uint32_t bl0[2] = {vl[0], vl[1]}, bl1[2] = {vl[2], vl[3]};
                MMA16816(o[vp * 2],     phh, bh0);
                MMA16816(o[vp * 2],     pll, bh0);
                MMA16816(o[vp * 2],     phh, bl0);
                MMA16816(o[vp * 2 + 1], phh, bh1);
                MMA16816(o[vp * 2 + 1], pll, bh1);
                MMA16816(o[vp * 2 + 1], phh, bl1);
            }
        }
        __syncthreads();
    }

    l0 += __shfl_xor_sync(0xffffffffu, l0, 1);
    l0 += __shfl_xor_sync(0xffffffffu, l0, 2);
    l1 += __shfl_xor_sync(0xffffffffu, l1, 1);
    l1 += __shfl_xor_sync(0xffffffffu, l1, 2);
    const float inv0 = 1.0f / l0;
    const float inv1 = 1.0f / l1;
    const int r0 = q0 + wid * 16 + (lane >> 2);
    const int r1 = r0 + 8;
#pragma unroll
    for (int nf = 0; nf < 8; nf++) {
        const int col = colh + nf * 8 + (lane & 3) * 2;
        if (r0 < L) {
            uint32_t h, l;
            split2(o[nf][0] * inv0, o[nf][1] * inv0, h, l);
            const size_t off = tiled_off(s0 + r0, col);
            *(uint32_t*)(g_ath + off) = h;
            *(uint32_t*)(g_atl + off) = l;
        }
        if (r1 < L) {
            uint32_t h, l;
            split2(o[nf][2] * inv1, o[nf][3] * inv1, h, l);
            const size_t off = tiled_off(s0 + r1, col);
            *(uint32_t*)(g_ath + off) = h;
            *(uint32_t*)(g_atl + off) = l;
        }
    }
}

// ---------------------------------------------------------------------------
// Launch
// ---------------------------------------------------------------------------
extern "C" void kernel_launch(void* const* d_in, const int* in_sizes, int n_in,
                              void* d_out, int out_size)
{
    const float* x  = (const float*)d_in[0];
    const int* cu   = (const int*)d_in[1];
    const float* Wq = (const float*)d_in[2];
    const float* bq = (const float*)d_in[3];
    const float* Wk = (const float*)d_in[4];
    const float* bk = (const float*)d_in[5];
    const float* Wv = (const float*)d_in[6];
    const float* bv = (const float*)d_in[7];
    const float* qn = (const float*)d_in[8];
    const float* kn = (const float*)d_in[9];
    const float* Wo = (const float*)d_in[10];
    const float* bo = (const float*)d_in[11];
    float* out = (float*)d_out;

    const int T = in_sizes[0] / C_DIM;
    const int nseq = in_sizes[1] - 1;

    bf16 *xh, *xl, *qh, *ql, *kh, *kl, *vh, *vl, *ath, *atl;
    bf16 *wqh, *wql, *wkh, *wkl, *wvh, *wvl, *woh, *wol;
    cudaGetSymbolAddress((void**)&xh, g_xh);
    cudaGetSymbolAddress((void**)&xl, g_xl);
    cudaGetSymbolAddress((void**)&qh, g_qh);
    cudaGetSymbolAddress((void**)&ql, g_ql);
    cudaGetSymbolAddress((void**)&kh, g_khm);
    cudaGetSymbolAddress((void**)&kl, g_klm);
    cudaGetSymbolAddress((void**)&vh, g_vhm);
    cudaGetSymbolAddress((void**)&vl, g_vlm);
    cudaGetSymbolAddress((void**)&ath, g_ath);
    cudaGetSymbolAddress((void**)&atl, g_atl);
    cudaGetSymbolAddress((void**)&wqh, g_wqh);
    cudaGetSymbolAddress((void**)&wql, g_wql);
    cudaGetSymbolAddress((void**)&wkh, g_wkh);
    cudaGetSymbolAddress((void**)&wkl, g_wkl);
    cudaGetSymbolAddress((void**)&wvh, g_wvh);
    cudaGetSymbolAddress((void**)&wvl, g_wvl);
    cudaGetSymbolAddress((void**)&woh, g_woh);
    cudaGetSymbolAddress((void**)&wol, g_wol);

    cudaFuncSetAttribute(gemm_qkv, cudaFuncAttributeMaxDynamicSharedMemorySize, GEMM_SMEM);
    cudaFuncSetAttribute(gemm_out64, cudaFuncAttributeMaxDynamicSharedMemorySize, GEMM64_SMEM);
    cudaFuncSetAttribute(attn_mma, cudaFuncAttributeMaxDynamicSharedMemorySize, ATT_SMEM);

    const int xn4 = T * C_DIM / 4;
    const int wn4 = C_DIM * C_DIM / 4;
    const int total = xn4 + 4 * wn4;
    split_all_tiled<<<(total + 255) / 256, 256>>>(
        (const float4*)x,
        (const float4*)Wq, (const float4*)Wk, (const float4*)Wv, (const float4*)Wo,
        xh, xl, wqh, wql, wkh, wkl, wvh, wvl, woh, wol, xn4, wn4);

    dim3 qkv_grid(C_DIM / 128, (T + 127) / 128, 3);
    gemm_qkv<<<qkv_grid, 256, GEMM_SMEM>>>(xh, xl,
                                           wqh, wql, bq,
                                           wkh, wkl, bk,
                                           wvh, wvl, bv,
                                           qn, kn,
                                           qh, ql, kh, kl, vh, vl, T);

    dim3 attn_grid(nseq, NH, LMAX / 128);
    attn_mma<<<attn_grid, 256, ATT_SMEM>>>(cu);

    dim3 ogrid(C_DIM / 128, (T + 63) / 64);
    gemm_out64<<<ogrid, 256, GEMM64_SMEM>>>(ath, atl, woh, wol, bo, out, T);
}

// round 15
// speedup vs baseline: 1.6647x; 1.0059x over previous
#include <cuda_runtime.h>
#include <cuda_bf16.h>
#include <cstdint>

#define C_DIM 1024
#define NH 16
#define HD 64
#define MAX_T 8192
#define LMAX 1024
#define EPS_RMS 1.1920929e-07f

typedef __nv_bfloat16 bf16;

// ---------------- scratch (device globals; allocation-free rule) ----------
__device__ bf16 g_qh[MAX_T * C_DIM];
__device__ bf16 g_ql[MAX_T * C_DIM];

// K/V: head-major padded-tile layout [head][tile64][64 rows x 72 elems]
#define HM_ROW 72
#define HM_TILE_ELEMS (64 * HM_ROW)            // 4608
#define HM_TILE_BYTES (HM_TILE_ELEMS * 2)      // 9216
#define NT64 (MAX_T / 64)                      // 128
__device__ bf16 g_khm[NH * NT64 * HM_TILE_ELEMS];
__device__ bf16 g_klm[NH * NT64 * HM_TILE_ELEMS];
__device__ bf16 g_vhm[NH * NT64 * HM_TILE_ELEMS];
__device__ bf16 g_vlm[NH * NT64 * HM_TILE_ELEMS];

// tiled layouts (GEMM operands): [blk128][kblk32][128 rows x 40 elems]
#define TROW 40
#define TBLK_ELEMS (128 * TROW)       // 5120 elems
#define TBLK_BYTES (TBLK_ELEMS * 2)   // 10240 B
#define NKB (C_DIM / 32)              // 32 k-blocks
__device__ bf16 g_xh[(MAX_T / 128) * NKB * TBLK_ELEMS];
__device__ bf16 g_xl[(MAX_T / 128) * NKB * TBLK_ELEMS];
__device__ bf16 g_ath[(MAX_T / 128) * NKB * TBLK_ELEMS];
__device__ bf16 g_atl[(MAX_T / 128) * NKB * TBLK_ELEMS];
__device__ bf16 g_wqh[8 * NKB * TBLK_ELEMS];
__device__ bf16 g_wql[8 * NKB * TBLK_ELEMS];
__device__ bf16 g_wkh[8 * NKB * TBLK_ELEMS];
__device__ bf16 g_wkl[8 * NKB * TBLK_ELEMS];
__device__ bf16 g_wvh[8 * NKB * TBLK_ELEMS];
__device__ bf16 g_wvl[8 * NKB * TBLK_ELEMS];
__device__ bf16 g_woh[8 * NKB * TBLK_ELEMS];
__device__ bf16 g_wol[8 * NKB * TBLK_ELEMS];

// ---------------- helpers ---------------------------------------------
__device__ __forceinline__ uint32_t smem_u32(const void* p) {
    uint32_t a;
    asm("{ .reg .u64 t; cvta.to.shared.u64 t, %1; cvt.u32.u64 %0, t; }"
        : "=r"(a) : "l"(p));
    return a;
}

__device__ __forceinline__ size_t tiled_off(int r, int c) {
    return ((size_t)((r >> 7) * NKB + (c >> 5))) * TBLK_ELEMS +
           (size_t)((r & 127) * TROW + (c & 31));
}

__device__ __forceinline__ size_t hm_off(int row, int col) {
    const int head = col >> 6;
    const int d = col & 63;
    return ((size_t)(head * NT64 + (row >> 6)) * 64 + (row & 63)) * HM_ROW + d;
}

#define LDSM_X4(r0, r1, r2, r3, addr) \
    asm volatile("ldmatrix.sync.aligned.m8n8.x4.shared.b16 {%0,%1,%2,%3}, [%4];" \
                 : "=r"(r0), "=r"(r1), "=r"(r2), "=r"(r3) : "r"(addr))

#define LDSM_X4_T(r0, r1, r2, r3, addr) \
    asm volatile("ldmatrix.sync.aligned.m8n8.x4.trans.shared.b16 {%0,%1,%2,%3}, [%4];" \
                 : "=r"(r0), "=r"(r1), "=r"(r2), "=r"(r3) : "r"(addr))

#define MMA16816(d, a, b) \
    asm volatile("mma.sync.aligned.m16n8k16.row.col.f32.bf16.bf16.f32 " \
                 "{%0,%1,%2,%3}, {%4,%5,%6,%7}, {%8,%9}, {%0,%1,%2,%3};" \
                 : "+f"((d)[0]), "+f"((d)[1]), "+f"((d)[2]), "+f"((d)[3]) \
                 : "r"((a)[0]), "r"((a)[1]), "r"((a)[2]), "r"((a)[3]), \
                   "r"((b)[0]), "r"((b)[1]))

#define MBAR_INIT(a, cnt) \
    asm volatile("mbarrier.init.shared.b64 [%0], %1;" :: "r"(a), "r"(cnt) : "memory")
#define MBAR_EXPECT_TX(a, bytes) \
    asm volatile("mbarrier.arrive.expect_tx.shared.b64 _, [%0], %1;" \
                 :: "r"(a), "r"(bytes) : "memory")
#define BULK_G2S(dst, src, bytes, mbar) \
    asm volatile("cp.async.bulk.shared::cta.global.mbarrier::complete_tx::bytes " \
                 "[%0], [%1], %2, [%3];" \
                 :: "r"(dst), "l"(src), "r"(bytes), "r"(mbar) : "memory")

__device__ __forceinline__ void mbar_wait(uint32_t a, int phase) {
    asm volatile(
        "{ .reg .pred P;\n"
        "WL%=:\n"
        " mbarrier.try_wait.parity.acquire.cta.shared::cta.b64 P, [%0], %1, 0x989680;\n"
        " @P bra WD%=;\n"
        " bra WL%=;\n"
        "WD%=: }"
        :: "r"(a), "r"(phase) : "memory");
}

__device__ __forceinline__ void split2(float x, float y, uint32_t& h, uint32_t& l) {
    bf16 hx = __float2bfloat16(x);
    bf16 hy = __float2bfloat16(y);
    __nv_bfloat162 H; H.x = hx; H.y = hy;
    __nv_bfloat162 L;
    L.x = __float2bfloat16(x - __bfloat162float(hx));
    L.y = __float2bfloat16(y - __bfloat162float(hy));
    h = *(uint32_t*)&H;
    l = *(uint32_t*)&L;
}

// ---------------------------------------------------------------------------
// fused fp32 -> (hi,lo) split into TILED layout: 8 elems/thread, 16B stores
// ---------------------------------------------------------------------------
__global__ __launch_bounds__(256) void split_all_tiled(
    const float4* __restrict__ x,
    const float4* __restrict__ w0, const float4* __restrict__ w1,
    const float4* __restrict__ w2, const float4* __restrict__ w3,
    bf16* __restrict__ xh, bf16* __restrict__ xl,
    bf16* __restrict__ h0p, bf16* __restrict__ l0p,
    bf16* __restrict__ h1p, bf16* __restrict__ l1p,
    bf16* __restrict__ h2p, bf16* __restrict__ l2p,
    bf16* __restrict__ h3p, bf16* __restrict__ l3p,
    int xn8, int wn8)
{
    int gid = blockIdx.x * blockDim.x + threadIdx.x;
    const float4* in; bf16 *hi, *lo; int i;
    if (gid < xn8) {
        in = x; hi = xh; lo = xl; i = gid;
    } else {
        int g = gid - xn8;
        int sel = g / wn8;
        if (sel >= 4) return;
        i = g - sel * wn8;
        if (sel == 0)      { in = w0; hi = h0p; lo = l0p; }
        else if (sel == 1) { in = w1; hi = h1p; lo = l1p; }
        else if (sel == 2) { in = w2; hi = h2p; lo = l2p; }
        else               { in = w3; hi = h3p; lo = l3p; }
    }
    float4 v0 = in[i * 2];
    float4 v1 = in[i * 2 + 1];
    const int row = i >> 7;           // 128 groups of 8 per 1024-col row
    const int c = (i & 127) * 8;
    const size_t off = tiled_off(row, c);
    uint4 H, L;
    split2(v0.x, v0.y, H.x, L.x);
    split2(v0.z, v0.w, H.y, L.y);
    split2(v1.x, v1.y, H.z, L.z);
    split2(v1.z, v1.w, H.w, L.w);
    *(uint4*)(hi + off) = H;
    *(uint4*)(lo + off) = L;
}

// ---------------------------------------------------------------------------
// bf16x3 GEMM: BM=128, BN=128, BK=32; 8 warps (4x2), warp tile 32x64;
// 2-stage bulk-copy double buffer; occupancy 2.
// EPI: 0 = fp32 C + bias
//      1 = bias + split -> HEAD-MAJOR hi/lo (V)
//      2 = bias + rmsnorm + scale + split -> LINEAR hi/lo (Q)
//      3 = bias + rmsnorm + scale + split -> HEAD-MAJOR hi/lo (K)
// ---------------------------------------------------------------------------
#define NKT NKB
#define SUBTILE_B TBLK_BYTES              // 10240
#define STAGE_BYTES (4 * SUBTILE_B)       // 40960
#define GEMM_SMEM (128 + 2 * STAGE_BYTES) // 82048

template <int EPI>
__device__ __forceinline__ void gemm_core(
    const bf16* __restrict__ Ah, const bf16* __restrict__ Al,
    const bf16* __restrict__ Bh, const bf16* __restrict__ Bl,
    const float* __restrict__ bias, float* __restrict__ C,
    bf16* __restrict__ Oh, bf16* __restrict__ Ol,
    const float* __restrict__ nw, float nscale, int M,
    int mblk, int nblk, char* dsm)
{
    const uint32_t sbase = smem_u32(dsm);
    const uint32_t mb0 = sbase, mb1 = sbase + 8;
    const uint32_t tiles = sbase + 128;
    const int tid = threadIdx.x;
    const int wid = tid >> 5;
    const int lane = tid & 31;
    const int wm = wid & 3;
    const int wn = wid >> 2;

    float acc[2][8][4];
#pragma unroll
    for (int i = 0; i < 2; i++)
#pragma unroll
        for (int j = 0; j < 8; j++)
#pragma unroll
            for (int r = 0; r < 4; r++) acc[i][j][r] = 0.0f;

    if (tid == 0) { MBAR_INIT(mb0, 1); MBAR_INIT(mb1, 1); }
    __syncthreads();

    const size_t abase_blk = (size_t)mblk * NKB;
    const size_t bbase_blk = (size_t)nblk * NKB;

    auto issue = [&](int kt) {
        const int s = kt & 1;
        const uint32_t dst = tiles + s * STAGE_BYTES;
        const uint32_t m = s ? mb1 : mb0;
        MBAR_EXPECT_TX(m, (uint32_t)STAGE_BYTES);
        const size_t ao = (abase_blk + kt) * TBLK_ELEMS;
        const size_t bo = (bbase_blk + kt) * TBLK_ELEMS;
        BULK_G2S(dst,                  Ah + ao, (uint32_t)TBLK_BYTES, m);
        BULK_G2S(dst + SUBTILE_B,      Al + ao, (uint32_t)TBLK_BYTES, m);
        BULK_G2S(dst + 2 * SUBTILE_B,  Bh + bo, (uint32_t)TBLK_BYTES, m);
        BULK_G2S(dst + 3 * SUBTILE_B,  Bl + bo, (uint32_t)TBLK_BYTES, m);
    };
    if (tid == 0) { issue(0); issue(1); }

    const int a_row = (lane & 15);
    const int a_col = (lane >> 4) * 8;
    const int b_row = (lane & 7) + ((lane >> 4) & 1) * 8;
    const int b_col = ((lane >> 3) & 1) * 8;

    int ph0 = 0, ph1 = 0;
    for (int kt = 0; kt < NKT; kt++) {
        const int s = kt & 1;
        if (s == 0) { mbar_wait(mb0, ph0); ph0 ^= 1; }
        else        { mbar_wait(mb1, ph1); ph1 ^= 1; }
        const uint32_t st = tiles + s * STAGE_BYTES;

#pragma unroll
        for (int ph = 0; ph < 2; ph++) {
            const int koff = ph * 16;
            uint32_t af[2][2][4];
#pragma unroll
            for (int prod = 0; prod < 2; prod++) {
                const uint32_t abase = st + prod * SUBTILE_B;
#pragma unroll
                for (int mf = 0; mf < 2; mf++) {
                    const uint32_t addr = abase +
                        (uint32_t)((wm * 32 + mf * 16 + a_row) * (TROW * 2) +
                                   (koff + a_col) * 2);
                    LDSM_X4(af[prod][mf][0], af[prod][mf][1],
                            af[prod][mf][2], af[prod][mf][3], addr);
                }
            }
#pragma unroll
            for (int np = 0; np < 4; np++) {
                const uint32_t boff =
                    (uint32_t)((wn * 64 + np * 16 + b_row) * (TROW * 2) +
                               (koff + b_col) * 2);
                uint32_t bh[4], bl[4];
                LDSM_X4(bh[0], bh[1], bh[2], bh[3], st + 2 * SUBTILE_B + boff);
                LDSM_X4(bl[0], bl[1], bl[2], bl[3], st + 3 * SUBTILE_B + boff);
                uint32_t bh0[2] = {bh[0], bh[1]}, bh1[2] = {bh[2], bh[3]};
                uint32_t bl0[2] = {bl[0], bl[1]}, bl1[2] = {bl[2], bl[3]};
#pragma unroll
                for (int mf = 0; mf < 2; mf++) {
                    MMA16816(acc[mf][np * 2],     af[0][mf], bh0);
                    MMA16816(acc[mf][np * 2],     af[0][mf], bl0);
                    MMA16816(acc[mf][np * 2],     af[1][mf], bh0);
                    MMA16816(acc[mf][np * 2 + 1], af[0][mf], bh1);
                    MMA16816(acc[mf][np * 2 + 1], af[0][mf], bl1);
                    MMA16816(acc[mf][np * 2 + 1], af[1][mf], bh1);
                }
            }
        }
        __syncthreads();
        if (kt + 2 < NKT && tid == 0) issue(kt + 2);
    }

    const int m0 = mblk * 128, n0 = nblk * 128;
    const int rbase = m0 + wm * 32 + (lane >> 2);
    const int cbase = n0 + wn * 64 + (lane & 3) * 2;
#pragma unroll
    for (int mf = 0; mf < 2; mf++) {
#pragma unroll
        for (int half = 0; half < 2; half++) {
            const int row = rbase + mf * 16 + half * 8;
            if (row >= M) continue;
            float v[8][2];
#pragma unroll
            for (int nf = 0; nf < 8; nf++) {
                const int col = cbase + nf * 8;
                v[nf][0] = acc[mf][nf][half * 2 + 0] + bias[col];
                v[nf][1] = acc[mf][nf][half * 2 + 1] + bias[col + 1];
            }
            if (EPI == 0) {
#pragma unroll
                for (int nf = 0; nf < 8; nf++) {
                    float2 o; o.x = v[nf][0]; o.y = v[nf][1];
                    *(float2*)(C + (size_t)row * C_DIM + cbase + nf * 8) = o;
                }
            } else if (EPI == 1) {
#pragma unroll
                for (int nf = 0; nf < 8; nf++) {
                    uint32_t h, l;
                    split2(v[nf][0], v[nf][1], h, l);
                    const size_t off = hm_off(row, cbase + nf * 8);
                    *(uint32_t*)(Oh + off) = h;
                    *(uint32_t*)(Ol + off) = l;
                }
            } else {
                float ss = 0.0f;
#pragma unroll
                for (int nf = 0; nf < 8; nf++)
                    ss += v[nf][0] * v[nf][0] + v[nf][1] * v[nf][1];
                ss += __shfl_xor_sync(0xffffffffu, ss, 1);
                ss += __shfl_xor_sync(0xffffffffu, ss, 2);
                const float r = rsqrtf(ss * (1.0f / HD) + EPS_RMS) * nscale;
                const int d0 = (lane & 3) * 2;
#pragma unroll
                for (int nf = 0; nf < 8; nf++) {
                    const int d = nf * 8 + d0;
                    uint32_t h, l;
                    split2(v[nf][0] * r * nw[d], v[nf][1] * r * nw[d + 1], h, l);
                    if (EPI == 2) {
                        *(uint32_t*)(Oh + (size_t)row * C_DIM + cbase + nf * 8) = h;
                        *(uint32_t*)(Ol + (size_t)row * C_DIM + cbase + nf * 8) = l;
                    } else {
                        const size_t off = hm_off(row, cbase + nf * 8);
                        *(uint32_t*)(Oh + off) = h;
                        *(uint32_t*)(Ol + off) = l;
                    }
                }
            }
        }
    }
}

__global__ __launch_bounds__(256, 2)
void gemm_qkv(const bf16* __restrict__ xh, const bf16* __restrict__ xl,
              const bf16* __restrict__ wqh, const bf16* __restrict__ wql,
              const float* __restrict__ bq,
              const bf16* __restrict__ wkh, const bf16* __restrict__ wkl,
              const float* __restrict__ bk,
              const bf16* __restrict__ wvh, const bf16* __restrict__ wvl,
              const float* __restrict__ bv,
              const float* __restrict__ qn, const float* __restrict__ kn,
              bf16* __restrict__ qh, bf16* __restrict__ ql,
              bf16* __restrict__ kh, bf16* __restrict__ kl,
              bf16* __restrict__ vh, bf16* __restrict__ vl, int M)
{
    extern __shared__ char dsm[];
    const int z = blockIdx.z;
    if (z == 0) {
        gemm_core<2>(xh, xl, wqh, wql, bq, nullptr, qh, ql, qn, 0.125f, M,
                     blockIdx.y, blockIdx.x, dsm);
    } else if (z == 1) {
        gemm_core<3>(xh, xl, wkh, wkl, bk, nullptr, kh, kl, kn, 1.0f, M,
                     blockIdx.y, blockIdx.x, dsm);
    } else {
        gemm_core<1>(xh, xl, wvh, wvl, bv, nullptr, vh, vl, nullptr, 0.f, M,
                     blockIdx.y, blockIdx.x, dsm);
    }
}

// ---------------------------------------------------------------------------
// Output-projection GEMM, BM=64, 2-stage, occupancy 3 (regs capped at 85).
// ---------------------------------------------------------------------------
#define AHALF_B (64 * TROW * 2)            // 5120
#define STAGE64 (2 * AHALF_B + 2 * TBLK_BYTES)  // 30720
#define GEMM64_SMEM (128 + 2 * STAGE64)    // 61568

__global__ __launch_bounds__(256, 3)
void gemm_out64(const bf16* __restrict__ Ah, const bf16* __restrict__ Al,
                const bf16* __restrict__ Bh, const bf16* __restrict__ Bl,
                const float* __restrict__ bias, float* __restrict__ C, int M)
{
    extern __shared__ char dsm[];
    const uint32_t sbase = smem_u32(dsm);
    const uint32_t mb0 = sbase, mb1 = sbase + 8;
    const uint32_t tiles = sbase + 128;
    const int tid = threadIdx.x;
    const int wid = tid >> 5;
    const int lane = tid & 31;
    const int wm = wid & 3;
    const int wn = wid >> 2;
    const int mblk = blockIdx.y;
    const int nblk = blockIdx.x;
    const int ablk = mblk >> 1, ahalf = mblk & 1;

    float acc[8][4];
#pragma unroll
    for (int j = 0; j < 8; j++)
#pragma unroll
        for (int r = 0; r < 4; r++) acc[j][r] = 0.0f;

    if (tid == 0) { MBAR_INIT(mb0, 1); MBAR_INIT(mb1, 1); }
    __syncthreads();

    const size_t abase_blk = (size_t)ablk * NKB;
    const size_t bbase_blk = (size_t)nblk * NKB;

    auto issue = [&](int kt) {
        const int s = kt & 1;
        const uint32_t dst = tiles + s * STAGE64;
        const uint32_t m = s ? mb1 : mb0;
        MBAR_EXPECT_TX(m, (uint32_t)STAGE64);
        const size_t ao = (abase_blk + kt) * TBLK_ELEMS + (size_t)ahalf * (64 * TROW);
        const size_t bo = (bbase_blk + kt) * TBLK_ELEMS;
        BULK_G2S(dst,                        Ah + ao, (uint32_t)AHALF_B, m);
        BULK_G2S(dst + AHALF_B,              Al + ao, (uint32_t)AHALF_B, m);
        BULK_G2S(dst + 2 * AHALF_B,               Bh + bo, (uint32_t)TBLK_BYTES, m);
        BULK_G2S(dst + 2 * AHALF_B + TBLK_BYTES,  Bl + bo, (uint32_t)TBLK_BYTES, m);
    };
    if (tid == 0) { issue(0); issue(1); }

    const int a_row = (lane & 15);
    const int a_col = (lane >> 4) * 8;
    const int b_row = (lane & 7) + ((lane >> 4) & 1) * 8;
    const int b_col = ((lane >> 3) & 1) * 8;

    int ph0 = 0, ph1 = 0;
    for (int kt = 0; kt < NKT; kt++) {
        const int s = kt & 1;
        if (s == 0) { mbar_wait(mb0, ph0); ph0 ^= 1; }
        else        { mbar_wait(mb1, ph1); ph1 ^= 1; }
        const uint32_t st = tiles + s * STAGE64;

#pragma unroll
        for (int ph = 0; ph < 2; ph++) {
            const int koff = ph * 16;
            uint32_t af[2][4];
#pragma unroll
            for (int prod = 0; prod < 2; prod++) {
                const uint32_t addr = st + prod * AHALF_B +
                    (uint32_t)((wm * 16 + a_row) * (TROW * 2) + (koff + a_col) * 2);
                LDSM_X4(af[prod][0], af[prod][1], af[prod][2], af[prod][3], addr);
            }
#pragma unroll
            for (int np = 0; np < 4; np++) {
                const uint32_t boff =
                    (uint32_t)((wn * 64 + np * 16 + b_row) * (TROW * 2) +
                               (koff + b_col) * 2);
                uint32_t bh[4], bl[4];
                LDSM_X4(bh[0], bh[1], bh[2], bh[3], st + 2 * AHALF_B + boff);
                LDSM_X4(bl[0], bl[1], bl[2], bl[3], st + 2 * AHALF_B + TBLK_BYTES + boff);
                uint32_t bh0[2] = {bh[0], bh[1]}, bh1[2] = {bh[2], bh[3]};
                uint32_t bl0[2] = {bl[0], bl[1]}, bl1[2] = {bl[2], bl[3]};
                MMA16816(acc[np * 2],     af[0], bh0);
                MMA16816(acc[np * 2],     af[0], bl0);
                MMA16816(acc[np * 2],     af[1], bh0);
                MMA16816(acc[np * 2 + 1], af[0], bh1);
                MMA16816(acc[np * 2 + 1], af[0], bl1);
                MMA16816(acc[np * 2 + 1], af[1], bh1);
            }
        }
        __syncthreads();
        if (kt + 2 < NKT && tid == 0) issue(kt + 2);
    }

    const int m0 = mblk * 64, n0 = nblk * 128;
    const int rbase = m0 + wm * 16 + (lane >> 2);
    const int cbase = n0 + wn * 64 + (lane & 3) * 2;
#pragma unroll
    for (int half = 0; half < 2; half++) {
        const int row = rbase + half * 8;
        if (row >= M) continue;
#pragma unroll
        for (int nf = 0; nf < 8; nf++) {
            const int col = cbase + nf * 8;
            float2 o;
            o.x = acc[nf][half * 2 + 0] + bias[col];
            o.y = acc[nf][half * 2 + 1] + bias[col + 1];
            *(float2*)(C + (size_t)row * C_DIM + col) = o;
        }
    }
}

// ---------------------------------------------------------------------------
// Tensorized varlen attention (bf16x3), fixed-shift softmax, bulk-copy K/V,
// 3-stage early-issue pipeline. 256 thr, occ 2, 128 q/block. TILED output.
// ---------------------------------------------------------------------------
#define KSTRIDE_B 144
#define ARR_B (64 * KSTRIDE_B)            // 9216
#define ATT_STAGE (4 * ARR_B)             // 36864
#define ATT_NST 3
#define ATT_SMEM (128 + ATT_NST * ATT_STAGE)

__global__ __launch_bounds__(256, 2) void attn_mma(const int* __restrict__ cu)
{
    const int seq = blockIdx.x;
    const int head = blockIdx.y;
    const int s0 = cu[seq];
    const int L = cu[seq + 1] - s0;
    const int q0 = blockIdx.z * 128;
    if (q0 >= L) return;

    extern __shared__ char sm[];
    const uint32_t sb = smem_u32(sm);
    const uint32_t tiles = sb + 128;
    const int tid = threadIdx.x;
    const int wid = tid >> 5;
    const int lane = tid & 31;
    const int colh = head * HD;

    if (tid == 0) {
        MBAR_INIT(sb + 0, 1);
        MBAR_INIT(sb + 8, 1);
        MBAR_INIT(sb + 16, 1);
    }
    __syncthreads();

    uint32_t aQh[4][4], aQl[4][4];
    {
        int r0 = q0 + wid * 16 + (lane >> 2);
        int r1 = r0 + 8;
        if (r0 >= L) r0 = L - 1;
        if (r1 >= L) r1 = L - 1;
        const size_t b0 = (size_t)(s0 + r0) * C_DIM + colh + (lane & 3) * 2;
        const size_t b1 = (size_t)(s0 + r1) * C_DIM + colh + (lane & 3) * 2;
#pragma unroll
        for (int kc = 0; kc < 4; kc++) {
            aQh[kc][0] = *(const uint32_t*)(g_qh + b0 + kc * 16);
            aQh[kc][1] = *(const uint32_t*)(g_qh + b1 + kc * 16);
            aQh[kc][2] = *(const uint32_t*)(g_qh + b0 + kc * 16 + 8);
            aQh[kc][3] = *(const uint32_t*)(g_qh + b1 + kc * 16 + 8);
            aQl[kc][0] = *(const uint32_t*)(g_ql + b0 + kc * 16);
            aQl[kc][1] = *(const uint32_t*)(g_ql + b1 + kc * 16);
            aQl[kc][2] = *(const uint32_t*)(g_ql + b0 + kc * 16 + 8);
            aQl[kc][3] = *(const uint32_t*)(g_ql + b1 + kc * 16 + 8);
        }
    }

    float o[8][4];
#pragma unroll
    for (int i = 0; i < 8; i++)
#pragma unroll
        for (int j = 0; j < 4; j++) o[i][j] = 0.0f;
    float l0 = 0.0f, l1 = 0.0f;

    const int ntiles = (L + 63) >> 6;
    const size_t hbase = (size_t)(head * NT64 + (s0 >> 6)) * HM_TILE_ELEMS;

    auto issue = [&](int t) {
        const int s = t - (t / ATT_NST) * ATT_NST;
        const uint32_t dst = tiles + s * ATT_STAGE;
        const uint32_t m = sb + s * 8;
        MBAR_EXPECT_TX(m, (uint32_t)ATT_STAGE);
        const size_t off = hbase + (size_t)t * HM_TILE_ELEMS;
        BULK_G2S(dst,               g_khm + off, (uint32_t)ARR_B, m);
        BULK_G2S(dst + ARR_B,       g_klm + off, (uint32_t)ARR_B, m);
        BULK_G2S(dst + 2 * ARR_B,   g_vhm + off, (uint32_t)ARR_B, m);
        BULK_G2S(dst + 3 * ARR_B,   g_vlm + off, (uint32_t)ARR_B, m);
    };
    if (tid == 0) { issue(0); if (ntiles > 1) issue(1); }

    int phase[ATT_NST] = {0, 0, 0};
    for (int t = 0; t < ntiles; t++) {
        const int s = t - (t / ATT_NST) * ATT_NST;
        mbar_wait(sb + s * 8, phase[s]);
        phase[s] ^= 1;
        if (t + 2 < ntiles && tid == 0) issue(t + 2);
        const uint32_t st = tiles + s * ATT_STAGE;
        const int kb = t * 64;

        float sc[8][4];
#pragma unroll
        for (int i = 0; i < 8; i++)
#pragma unroll
            for (int j = 0; j < 4; j++) sc[i][j] = 0.0f;

        const int mat = lane >> 3;
#pragma unroll
        for (int kc = 0; kc < 4; kc++) {
#pragma unroll
            for (int pair = 0; pair < 4; pair++) {
                const int krow = (pair * 2 + (mat >> 1)) * 8 + (lane & 7);
                const uint32_t cb = (uint32_t)(kc * 32 + (mat & 1) * 16);
                uint32_t kh[4], kl[4];
                LDSM_X4(kh[0], kh[1], kh[2], kh[3], st + 0     + krow * KSTRIDE_B + cb);
                LDSM_X4(kl[0], kl[1], kl[2], kl[3], st + ARR_B + krow * KSTRIDE_B + cb);
                uint32_t bh0[2] = {kh[0], kh[1]}, bh1[2] = {kh[2], kh[3]};
                uint32_t bl0[2] = {kl[0], kl[1]}, bl1[2] = {kl[2], kl[3]};
                MMA16816(sc[pair * 2],     aQh[kc], bh0);
                MMA16816(sc[pair * 2],     aQh[kc], bl0);
                MMA16816(sc[pair * 2],     aQl[kc], bh0);
                MMA16816(sc[pair * 2 + 1], aQh[kc], bh1);
                MMA16816(sc[pair * 2 + 1], aQh[kc], bl1);
                MMA16816(sc[pair * 2 + 1], aQl[kc], bh1);
            }
        }

        const int cb0 = (lane & 3) * 2;
#pragma unroll
        for (int nf = 0; nf < 8; nf++) {
            int colk = kb + nf * 8 + cb0;
            if (colk >= L)     { sc[nf][0] = -1e30f; sc[nf][2] = -1e30f; }
            if (colk + 1 >= L) { sc[nf][1] = -1e30f; sc[nf][3] = -1e30f; }
        }
#pragma unroll
        for (int nf = 0; nf < 8; nf++) {
            sc[nf][0] = __expf(sc[nf][0] - 8.0f);
            sc[nf][1] = __expf(sc[nf][1] - 8.0f);
            sc[nf][2] = __expf(sc[nf][2] - 8.0f);
            sc[nf][3] = __expf(sc[nf][3] - 8.0f);
            l0 += sc[nf][0] + sc[nf][1];
            l1 += sc[nf][2] + sc[nf][3];
        }

#pragma unroll
        for (int j = 0; j < 4; j++) {
            uint32_t phh[4], pll[4];
            split2(sc[2 * j][0], sc[2 * j][1], phh[0], pll[0]);
            split2(sc[2 * j][2], sc[2 * j][3], phh[1], pll[1]);
            split2(sc[2 * j + 1][0], sc[2 * j + 1][1], phh[2], pll[2]);
            split2(sc[2 * j + 1][2], sc[2 * j + 1][3], phh[3], pll[3]);
            const uint32_t vrow = (uint32_t)((j * 16 + (lane & 15)) * KSTRIDE_B +
                                             ((lane >> 4) << 3) * 2);
#pragma unroll
            for (int vp = 0; vp < 4; vp++) {
                const uint32_t addr = st + 2 * ARR_B + vrow + (uint32_t)(vp * 32);
                uint32_t vh[4], vl[4];
                LDSM_X4_T(vh[0], vh[1], vh[2], vh[3], addr);
                LDSM_X4_T(vl[0], vl[1], vl[2], vl[3], addr + ARR_B);
                uint32_t bh0[2] = {vh[0], vh[1]}, bh1[2] = {vh[2], vh[3]};
                uint32_t bl0[2] = {vl[0], vl[1]}, bl1[2] = {vl[2], vl[3]};
                MMA16816(o[vp * 2],     phh, bh0);
                MMA16816(o[vp * 2],     pll, bh0);
                MMA16816(o[vp * 2],     phh, bl0);
                MMA16816(o[vp * 2 + 1], phh, bh1);
                MMA16816(o[vp * 2 + 1], pll, bh1);
                MMA16816(o[vp * 2 + 1], phh, bl1);
            }
        }
        __syncthreads();
    }

    l0 += __shfl_xor_sync(0xffffffffu, l0, 1);
    l0 += __shfl_xor_sync(0xffffffffu, l0, 2);
    l1 += __shfl_xor_sync(0xffffffffu, l1, 1);
    l1 += __shfl_xor_sync(0xffffffffu, l1, 2);
    const float inv0 = 1.0f / l0;
    const float inv1 = 1.0f / l1;
    const int r0 = q0 + wid * 16 + (lane >> 2);
    const int r1 = r0 + 8;
#pragma unroll
    for (int nf = 0; nf < 8; nf++) {
        const int col = colh + nf * 8 + (lane & 3) * 2;
        if (r0 < L) {
            uint32_t h, l;
            split2(o[nf][0] * inv0, o[nf][1] * inv0, h, l);
            const size_t off = tiled_off(s0 + r0, col);
            *(uint32_t*)(g_ath + off) = h;
            *(uint32_t*)(g_atl + off) = l;
        }
        if (r1 < L) {
            uint32_t h, l;
            split2(o[nf][2] * inv1, o[nf][3] * inv1, h, l);
            const size_t off = tiled_off(s0 + r1, col);
            *(uint32_t*)(g_ath + off) = h;
            *(uint32_t*)(g_atl + off) = l;
        }
    }
}

// ---------------------------------------------------------------------------
// Launch
// ---------------------------------------------------------------------------
extern "C" void kernel_launch(void* const* d_in, const int* in_sizes, int n_in,
                              void* d_out, int out_size)
{
    const float* x  = (const float*)d_in[0];
    const int* cu   = (const int*)d_in[1];
    const float* Wq = (const float*)d_in[2];
    const float* bq = (const float*)d_in[3];
    const float* Wk = (const float*)d_in[4];
    const float* bk = (const float*)d_in[5];
    const float* Wv = (const float*)d_in[6];
    const float* bv = (const float*)d_in[7];
    const float* qn = (const float*)d_in[8];
    const float* kn = (const float*)d_in[9];
    const float* Wo = (const float*)d_in[10];
    const float* bo = (const float*)d_in[11];
    float* out = (float*)d_out;

    const int T = in_sizes[0] / C_DIM;
    const int nseq = in_sizes[1] - 1;

    bf16 *xh, *xl, *qh, *ql, *kh, *kl, *vh, *vl, *ath, *atl;
    bf16 *wqh, *wql, *wkh, *wkl, *wvh, *wvl, *woh, *wol;
    cudaGetSymbolAddress((void**)&xh, g_xh);
    cudaGetSymbolAddress((void**)&xl, g_xl);
    cudaGetSymbolAddress((void**)&qh, g_qh);
    cudaGetSymbolAddress((void**)&ql, g_ql);
    cudaGetSymbolAddress((void**)&kh, g_khm);
    cudaGetSymbolAddress((void**)&kl, g_klm);
    cudaGetSymbolAddress((void**)&vh, g_vhm);
    cudaGetSymbolAddress((void**)&vl, g_vlm);
    cudaGetSymbolAddress((void**)&ath, g_ath);
    cudaGetSymbolAddress((void**)&atl, g_atl);
    cudaGetSymbolAddress((void**)&wqh, g_wqh);
    cudaGetSymbolAddress((void**)&wql, g_wql);
    cudaGetSymbolAddress((void**)&wkh, g_wkh);
    cudaGetSymbolAddress((void**)&wkl, g_wkl);
    cudaGetSymbolAddress((void**)&wvh, g_wvh);
    cudaGetSymbolAddress((void**)&wvl, g_wvl);
    cudaGetSymbolAddress((void**)&woh, g_woh);
    cudaGetSymbolAddress((void**)&wol, g_wol);

    cudaFuncSetAttribute(gemm_qkv, cudaFuncAttributeMaxDynamicSharedMemorySize, GEMM_SMEM);
    cudaFuncSetAttribute(gemm_out64, cudaFuncAttributeMaxDynamicSharedMemorySize, GEMM64_SMEM);
    cudaFuncSetAttribute(attn_mma, cudaFuncAttributeMaxDynamicSharedMemorySize, ATT_SMEM);

    const int xn8 = T * C_DIM / 8;
    const int wn8 = C_DIM * C_DIM / 8;
    const int total = xn8 + 4 * wn8;
    split_all_tiled<<<(total + 255) / 256, 256>>>(
        (const float4*)x,
        (const float4*)Wq, (const float4*)Wk, (const float4*)Wv, (const float4*)Wo,
        xh, xl, wqh, wql, wkh, wkl, wvh, wvl, woh, wol, xn8, wn8);

    dim3 qkv_grid(C_DIM / 128, (T + 127) / 128, 3);
    gemm_qkv<<<qkv_grid, 256, GEMM_SMEM>>>(xh, xl,
                                           wqh, wql, bq,
                                           wkh, wkl, bk,
                                           wvh, wvl, bv,
                                           qn, kn,
                                           qh, ql, kh, kl, vh, vl, T);

    dim3 attn_grid(nseq, NH, LMAX / 128);
    attn_mma<<<attn_grid, 256, ATT_SMEM>>>(cu);

    dim3 ogrid(C_DIM / 128, (T + 63) / 64);
    gemm_out64<<<ogrid, 256, GEMM64_SMEM>>>(ath, atl, woh, wol, bo, out, T);
}